// round 4
// baseline (speedup 1.0000x reference)
#include <cuda_runtime.h>
#include <cmath>

namespace {
constexpr int D = 192, H = 48, W = 48, PLANE = 2304, VOX = 442368;

// ---- pack buffer layout (float offsets) ----
constexpr int PK_W1 = 0,            SZ_W1 = 19008;   // [cp12][kd6][kh11][kw12][2]
constexpr int PK_W3 = PK_W1 + SZ_W1, SZ_W3 = 663552; // [ic384][t9][dp96][2]
constexpr int PK_WA = PK_W3 + SZ_W3, SZ_WA = 1200;   // [c25][up24][2]
constexpr int PK_BA = PK_WA + SZ_WA, SZ_BA = 48;     // [up24][2]
constexpr int PK_WB = PK_BA + SZ_BA, SZ_WB = 4608;   // [h2][j48][up24][2]
constexpr int PK_BB = PK_WB + SZ_WB, SZ_BB = 96;     // [h2][up24][2]
constexpr int PK_WC = PK_BB + SZ_BB, SZ_WC = 1152;   // [j96][p6][2]
constexpr int PK_BC = PK_WC + SZ_WC, SZ_BC = 12;     // [p6][2]

// K3 smem layout = contiguous copy of [PK_WA .. PK_BC+SZ_BC)
constexpr int SA_WA = 0, SA_BA = 1200, SA_WB = 1248, SA_BB = 5856,
              SA_WC = 5952, SA_BC = 7104, K3_SM = 7116;

// K2 smem: x window 6 slices x 34 rows x pitch 60  + packed W1
constexpr int K2_SX = 6 * 34 * 60;            // 12240 floats
constexpr int K2_SW = SZ_W1;                  // 19008 floats
constexpr int K2_SMEM = (K2_SX + K2_SW) * 4;  // 124992 B
}

__device__ __align__(16) float g_pack[689680];
__device__ float g_h[VOX];
__device__ float g_x1[(size_t)24 * VOX];

// ---- f32x2 helpers ----
__device__ __forceinline__ unsigned long long splat2(float v) {
    unsigned long long r; asm("mov.b64 %0, {%1, %1};" : "=l"(r) : "f"(v)); return r;
}
__device__ __forceinline__ unsigned long long pack2(float a, float b) {
    unsigned long long r; asm("mov.b64 %0, {%1, %2};" : "=l"(r) : "f"(a), "f"(b)); return r;
}
__device__ __forceinline__ float2 unpack2(unsigned long long v) {
    float2 f; asm("mov.b64 {%0, %1}, %2;" : "=f"(f.x), "=f"(f.y) : "l"(v)); return f;
}
__device__ __forceinline__ void fma2(unsigned long long& a, unsigned long long w,
                                     unsigned long long x) {
    asm("fma.rn.f32x2 %0, %1, %2, %0;" : "+l"(a) : "l"(w), "l"(x));
}

// =============== K0: pack weights into pair layouts ===============
__global__ void pack_kernel(const float* __restrict__ W3, const float* __restrict__ W1,
                            const float* __restrict__ Wa, const float* __restrict__ ba,
                            const float* __restrict__ Wb, const float* __restrict__ bb,
                            const float* __restrict__ Wc, const float* __restrict__ bc) {
    int nt = gridDim.x * blockDim.x, tid = blockIdx.x * blockDim.x + threadIdx.x;
    for (int i = tid; i < SZ_W1; i += nt) {
        int par = i & 1, q = i >> 1;
        int kw = q % 12; q /= 12;
        int kh = q % 11; q /= 11;
        int kd = q % 6;  int cp = q / 6;
        int c = cp * 2 + par;
        int flat = kd * 121 + kh * 11 + kw;
        float v = 0.f;
        if (kw < 11 && flat < 665) v = W1[c * 1331 + flat];
        g_pack[PK_W1 + i] = v;
    }
    for (int i = tid; i < SZ_W3; i += nt) {
        int par = i & 1, q = i >> 1;
        int dp = q % 96; q /= 96;
        int t = q % 9;   int ic = q / 9;
        g_pack[PK_W3 + i] = W3[((size_t)(dp * 2 + par) * 384 + ic) * 9 + t];
    }
    for (int i = tid; i < SZ_WA; i += nt) {
        int par = i & 1, q = i >> 1;
        int up = q % 24, c = q / 24;
        g_pack[PK_WA + i] = Wa[(up * 2 + par) * 25 + c];
    }
    for (int i = tid; i < SZ_BA; i += nt) {
        int par = i & 1, up = i >> 1;
        g_pack[PK_BA + i] = ba[up * 2 + par];
    }
    for (int i = tid; i < SZ_WB; i += nt) {
        int par = i & 1, q = i >> 1;
        int up = q % 24; q /= 24;
        int j = q % 48;  int h = q / 48;
        g_pack[PK_WB + i] = Wb[(h * 48 + up * 2 + par) * 48 + j];
    }
    for (int i = tid; i < SZ_BB; i += nt) {
        int par = i & 1, q = i >> 1;
        int up = q % 24, h = q / 24;
        g_pack[PK_BB + i] = bb[h * 48 + up * 2 + par];
    }
    for (int i = tid; i < SZ_WC; i += nt) {
        int par = i & 1, q = i >> 1;
        int p = q % 6, j = q / 6;
        int o = p * 2 + par;
        g_pack[PK_WC + i] = (o < 9) ? Wc[o * 96 + j] : 0.f;
    }
    for (int i = tid; i < SZ_BC; i += nt) {
        int par = i & 1, p = i >> 1;
        int o = p * 2 + par;
        g_pack[PK_BC + i] = (o < 9) ? bc[o] : 0.f;
    }
}

// =============== K1: conv2d (hyper -> g_h), d-pairs packed ===============
__global__ __launch_bounds__(192, 2)
void conv2d_kernel(const float* __restrict__ hyper, const float* __restrict__ b3) {
    __shared__ float s_hyp[16 * 520];  // 16 ic x 10 rows x pitch 52
    int bx = blockIdx.x;
    int dg = bx % 48, rt = bx / 48;
    int r0 = rt * 8;
    int tid = threadIdx.x;
    int dhalf = tid / 96, r8 = (tid % 96) / 12, grp = tid % 12, x0 = grp * 4;
    int dp = dg * 2 + dhalf, d0 = dp * 2;

    unsigned long long acc[4];
    {
        unsigned long long bv = pack2(b3[d0], b3[d0 + 1]);
        acc[0] = bv; acc[1] = bv; acc[2] = bv; acc[3] = bv;
    }
    const unsigned long long* w3u = (const unsigned long long*)g_pack + (PK_W3 / 2);

    for (int icb = 0; icb < 384; icb += 16) {
        for (int i = tid; i < 16 * 520; i += 192) {
            int icl = i / 520, rr = (i % 520) / 52, cc = i % 52;
            int grow = r0 - 1 + rr, gcol = cc - 1;
            float v = 0.f;
            if (grow >= 0 && grow < 48 && gcol >= 0 && gcol < 48)
                v = hyper[(size_t)(icb + icl) * PLANE + grow * 48 + gcol];
            s_hyp[i] = v;
        }
        __syncthreads();
        #pragma unroll 2
        for (int icl = 0; icl < 16; icl++) {
            const float* hw = s_hyp + icl * 520 + r8 * 52 + x0;
            unsigned long long ss[3][6];
            #pragma unroll
            for (int ky = 0; ky < 3; ky++) {
                const float* row = hw + ky * 52;
                float4 a = *(const float4*)row;
                float2 b = *(const float2*)(row + 4);
                ss[ky][0] = splat2(a.x); ss[ky][1] = splat2(a.y); ss[ky][2] = splat2(a.z);
                ss[ky][3] = splat2(a.w); ss[ky][4] = splat2(b.x); ss[ky][5] = splat2(b.y);
            }
            const unsigned long long* wrow = w3u + (size_t)(icb + icl) * 9 * 96 + dp;
            #pragma unroll
            for (int ky = 0; ky < 3; ky++)
                #pragma unroll
                for (int kx = 0; kx < 3; kx++) {
                    unsigned long long wv = wrow[(ky * 3 + kx) * 96];
                    fma2(acc[0], wv, ss[ky][kx + 0]);
                    fma2(acc[1], wv, ss[ky][kx + 1]);
                    fma2(acc[2], wv, ss[ky][kx + 2]);
                    fma2(acc[3], wv, ss[ky][kx + 3]);
                }
        }
        __syncthreads();
    }
    float2 v0 = unpack2(acc[0]), v1 = unpack2(acc[1]);
    float2 v2 = unpack2(acc[2]), v3 = unpack2(acc[3]);
    int gp = (r0 + r8) * 48 + x0;
    *(float4*)(g_h + (size_t)d0 * PLANE + gp)       = make_float4(v0.x, v1.x, v2.x, v3.x);
    *(float4*)(g_h + (size_t)(d0 + 1) * PLANE + gp) = make_float4(v0.y, v1.y, v2.y, v3.y);
}

// =============== K2: masked conv3d, 4 px/thread ===============
__global__ __launch_bounds__(576, 1)
void conv3d_kernel(const float* __restrict__ x, const float* __restrict__ b1) {
    extern __shared__ float sm[];
    float* s_x = sm;
    float* s_w = sm + K2_SX;

    int d = blockIdx.x >> 1, hq = blockIdx.x & 1;
    int r0 = hq * 24;
    int tid = threadIdx.x;
    int chalf = tid / 288, r24 = (tid % 288) / 12, grp = tid % 12, x0 = grp * 4;

    for (int i = tid; i < K2_SX / 4; i += 576)
        ((float4*)s_x)[i] = make_float4(0.f, 0.f, 0.f, 0.f);
    for (int i = tid; i < K2_SW / 4; i += 576)
        ((float4*)s_w)[i] = ((const float4*)(g_pack + PK_W1))[i];
    __syncthreads();
    // rows r0-5 .. r0+28 for depths d-5..d
    for (int i = tid; i < 6 * 34 * 12; i += 576) {
        int s = i / 408, rr = (i % 408) / 12, f4 = i % 12;
        int sd = d - 5 + s, grow = r0 - 5 + rr;
        if (sd >= 0 && grow >= 0 && grow < 48) {
            float4 v = *(const float4*)(x + (size_t)sd * PLANE + grow * 48 + f4 * 4);
            float* dst = s_x + (s * 34 + rr) * 60 + 5 + f4 * 4;
            dst[0] = v.x; dst[1] = v.y; dst[2] = v.z; dst[3] = v.w;
        }
    }
    __syncthreads();

    unsigned long long acc[6][4];
    #pragma unroll
    for (int c = 0; c < 6; c++) {
        int cp = chalf * 6 + c;
        unsigned long long bv = pack2(b1[cp * 2], b1[cp * 2 + 1]);
        acc[c][0] = bv; acc[c][1] = bv; acc[c][2] = bv; acc[c][3] = bv;
    }

    const ulonglong2* wb = (const ulonglong2*)s_w;
    int kd0 = (d >= 5) ? 0 : (5 - d);
    for (int kd = kd0; kd < 6; kd++) {
        int khmax = (kd < 5) ? 11 : 6;
        for (int kh = 0; kh < khmax; kh++) {
            const float* xr = s_x + (kd * 34 + r24 + kh) * 60 + x0;  // 16B aligned
            float4 A = *(const float4*)xr;
            float4 B = *(const float4*)(xr + 4);
            float4 C = *(const float4*)(xr + 8);
            float2 E = *(const float2*)(xr + 12);
            unsigned long long xs[14] = {
                splat2(A.x), splat2(A.y), splat2(A.z), splat2(A.w),
                splat2(B.x), splat2(B.y), splat2(B.z), splat2(B.w),
                splat2(C.x), splat2(C.y), splat2(C.z), splat2(C.w),
                splat2(E.x), splat2(E.y)};
            #pragma unroll
            for (int c = 0; c < 6; c++) {
                int cp = chalf * 6 + c;
                const ulonglong2* wr = wb + ((cp * 6 + kd) * 11 + kh) * 6;
                ulonglong2 wA = wr[0], wB = wr[1], wC = wr[2],
                           wD = wr[3], wE = wr[4], wF = wr[5];
                unsigned long long wv[11] = {wA.x, wA.y, wB.x, wB.y, wC.x, wC.y,
                                             wD.x, wD.y, wE.x, wE.y, wF.x};
                #pragma unroll
                for (int kw = 0; kw < 11; kw++) {
                    fma2(acc[c][0], wv[kw], xs[kw]);
                    fma2(acc[c][1], wv[kw], xs[kw + 1]);
                    fma2(acc[c][2], wv[kw], xs[kw + 2]);
                    fma2(acc[c][3], wv[kw], xs[kw + 3]);
                }
            }
        }
    }

    int gp = (r0 + r24) * 48 + x0;
    #pragma unroll
    for (int c = 0; c < 6; c++) {
        int c0 = (chalf * 6 + c) * 2;
        float2 p0 = unpack2(acc[c][0]), p1 = unpack2(acc[c][1]);
        float2 p2 = unpack2(acc[c][2]), p3 = unpack2(acc[c][3]);
        *(float4*)(g_x1 + ((size_t)d * 24 + c0) * PLANE + gp) =
            make_float4(p0.x, p1.x, p2.x, p3.x);
        *(float4*)(g_x1 + ((size_t)d * 24 + c0 + 1) * PLANE + gp) =
            make_float4(p0.y, p1.y, p2.y, p3.y);
    }
}

// =============== K3: per-voxel MLP + mixture CDF, 2 voxels/thread ===============
__global__ __launch_bounds__(256, 1)
void mlp_kernel(const float* __restrict__ x, float* __restrict__ out) {
    __shared__ float sm[K3_SM + 4];
    int tid = threadIdx.x;
    for (int i = tid; i < K3_SM / 4; i += 256)
        ((float4*)sm)[i] = ((const float4*)(g_pack + PK_WA))[i];
    __syncthreads();
    const unsigned long long* su = (const unsigned long long*)sm;
    const ulonglong2* su2 = (const ulonglong2*)sm;

    int base = (blockIdx.x * 256 + tid) * 2;
    int d = base / PLANE, p = base % PLANE;

    float2 t2[25];
    const float* xb = g_x1 + (size_t)d * 24 * PLANE + p;
    #pragma unroll
    for (int c = 0; c < 24; c++) t2[c] = *(const float2*)(xb + (size_t)c * PLANE);
    t2[24] = *(const float2*)(g_h + base);

    // layer A: 25 -> 48, 2 voxels share weight regs
    unsigned long long accA[2][24];
    #pragma unroll
    for (int u = 0; u < 24; u++) {
        unsigned long long b = su[SA_BA / 2 + u];
        accA[0][u] = b; accA[1][u] = b;
    }
    #pragma unroll 5
    for (int c = 0; c < 25; c++) {
        unsigned long long s0 = splat2(t2[c].x), s1 = splat2(t2[c].y);
        const ulonglong2* wr = su2 + SA_WA / 4 + c * 12;
        #pragma unroll
        for (int u2 = 0; u2 < 12; u2++) {
            ulonglong2 ww = wr[u2];
            fma2(accA[0][2 * u2], ww.x, s0); fma2(accA[0][2 * u2 + 1], ww.y, s0);
            fma2(accA[1][2 * u2], ww.x, s1); fma2(accA[1][2 * u2 + 1], ww.y, s1);
        }
    }
    float a0[48], a1[48];
    #pragma unroll
    for (int u = 0; u < 24; u++) {
        float2 v = unpack2(accA[0][u]);
        a0[2 * u] = fmaxf(v.x, 0.f); a0[2 * u + 1] = fmaxf(v.y, 0.f);
        float2 w = unpack2(accA[1][u]);
        a1[2 * u] = fmaxf(w.x, 0.f); a1[2 * u + 1] = fmaxf(w.y, 0.f);
    }

    unsigned long long oacc[2][5];
    #pragma unroll
    for (int pp = 0; pp < 5; pp++) {
        unsigned long long b = su[SA_BC / 2 + pp];
        oacc[0][pp] = b; oacc[1][pp] = b;
    }

    // layer B in output-quarters (24 units), fused with layer C
    #pragma unroll 1
    for (int q = 0; q < 4; q++) {
        int h = q >> 1, uoff = (q & 1) * 12;
        unsigned long long accB[2][12];
        #pragma unroll
        for (int k = 0; k < 12; k++) {
            unsigned long long b = su[SA_BB / 2 + h * 24 + uoff + k];
            accB[0][k] = b; accB[1][k] = b;
        }
        #pragma unroll 4
        for (int j = 0; j < 48; j++) {
            unsigned long long s0 = splat2(a0[j]), s1 = splat2(a1[j]);
            const ulonglong2* wr = su2 + SA_WB / 4 + (h * 48 + j) * 12 + (q & 1) * 6;
            #pragma unroll
            for (int u2 = 0; u2 < 6; u2++) {
                ulonglong2 ww = wr[u2];
                fma2(accB[0][2 * u2], ww.x, s0); fma2(accB[0][2 * u2 + 1], ww.y, s0);
                fma2(accB[1][2 * u2], ww.x, s1); fma2(accB[1][2 * u2 + 1], ww.y, s1);
            }
        }
        #pragma unroll
        for (int k = 0; k < 12; k++) {
            float2 v0 = unpack2(accB[0][k]);
            float2 v1 = unpack2(accB[1][k]);
            int j96 = h * 48 + (uoff + k) * 2;
            const ulonglong2* w0 = su2 + SA_WC / 4 + j96 * 3;
            ulonglong2 q0 = w0[0], q1 = w0[1], q2 = w0[2];   // unit j96
            ulonglong2 r0 = w0[3], r1 = w0[4], r2 = w0[5];   // unit j96+1
            unsigned long long e00 = splat2(fmaxf(v0.x, 0.f));
            unsigned long long e01 = splat2(fmaxf(v0.y, 0.f));
            unsigned long long e10 = splat2(fmaxf(v1.x, 0.f));
            unsigned long long e11 = splat2(fmaxf(v1.y, 0.f));
            fma2(oacc[0][0], q0.x, e00); fma2(oacc[0][1], q0.y, e00);
            fma2(oacc[0][2], q1.x, e00); fma2(oacc[0][3], q1.y, e00);
            fma2(oacc[0][4], q2.x, e00);
            fma2(oacc[0][0], r0.x, e01); fma2(oacc[0][1], r0.y, e01);
            fma2(oacc[0][2], r1.x, e01); fma2(oacc[0][3], r1.y, e01);
            fma2(oacc[0][4], r2.x, e01);
            fma2(oacc[1][0], q0.x, e10); fma2(oacc[1][1], q0.y, e10);
            fma2(oacc[1][2], q1.x, e10); fma2(oacc[1][3], q1.y, e10);
            fma2(oacc[1][4], q2.x, e10);
            fma2(oacc[1][0], r0.x, e11); fma2(oacc[1][1], r0.y, e11);
            fma2(oacc[1][2], r1.x, e11); fma2(oacc[1][3], r1.y, e11);
            fma2(oacc[1][4], r2.x, e11);
        }
    }

    float p3v[2];
    float o9v[2][9];
    float2 xv2 = *(const float2*)(x + base);
    #pragma unroll
    for (int v = 0; v < 2; v++) {
        float o9[9];
        #pragma unroll
        for (int pp = 0; pp < 4; pp++) {
            float2 w = unpack2(oacc[v][pp]);
            o9[2 * pp] = w.x; o9[2 * pp + 1] = w.y;
        }
        o9[8] = unpack2(oacc[v][4]).x;

        float xv = (v == 0) ? xv2.x : xv2.y;
        float mx = fmaxf(o9[6], fmaxf(o9[7], o9[8]));
        float e0 = expf(o9[6] - mx), e1 = expf(o9[7] - mx), e2 = expf(o9[8] - mx);
        float inv = 1.f / (e0 + e1 + e2);
        float wsm[3] = {e0 * inv, e1 * inv, e2 * inv};

        float p3 = 0.f;
        #pragma unroll
        for (int k = 0; k < 3; k++) {
            float mu = o9[k];
            float scv = o9[3 + k];
            if (scv == 0.f) scv = 1e-9f;
            scv = fabsf(scv);
            float invs = 1.f / scv;
            float l = fabsf(normcdff((xv + 0.5f - mu) * invs)
                          - normcdff((xv - 0.5f - mu) * invs));
            p3 = fmaf(wsm[k], l, p3);
        }
        p3v[v] = p3;
        #pragma unroll
        for (int o = 0; o < 9; o++) o9v[v][o] = o9[o];
    }

    *(float2*)(out + base) = make_float2(p3v[0], p3v[1]);
    #pragma unroll
    for (int o = 0; o < 9; o++)
        *(float2*)(out + (size_t)VOX + (size_t)o * VOX + base) =
            make_float2(o9v[0][o], o9v[1][o]);
}

extern "C" void kernel_launch(void* const* d_in, const int* in_sizes, int n_in,
                              void* d_out, int out_size) {
    const float* x     = (const float*)d_in[0];
    const float* hyper = (const float*)d_in[1];
    const float* W3    = (const float*)d_in[2];
    const float* b3    = (const float*)d_in[3];
    const float* W1    = (const float*)d_in[4];
    const float* b1    = (const float*)d_in[5];
    const float* Wa    = (const float*)d_in[6];
    const float* ba    = (const float*)d_in[7];
    const float* Wb    = (const float*)d_in[8];
    const float* bb    = (const float*)d_in[9];
    const float* Wc    = (const float*)d_in[10];
    const float* bc    = (const float*)d_in[11];
    float* out = (float*)d_out;

    cudaFuncSetAttribute(conv3d_kernel,
                         cudaFuncAttributeMaxDynamicSharedMemorySize, K2_SMEM);

    pack_kernel<<<128, 256>>>(W3, W1, Wa, ba, Wb, bb, Wc, bc);
    conv2d_kernel<<<288, 192>>>(hyper, b3);
    conv3d_kernel<<<384, 576, K2_SMEM>>>(x, b1);
    mlp_kernel<<<VOX / 512, 256>>>(x, out);
}

// round 5
// speedup vs baseline: 1.1357x; 1.1357x over previous
#include <cuda_runtime.h>
#include <cmath>

namespace {
constexpr int D = 192, H = 48, W = 48, PLANE = 2304, VOX = 442368;

// ---- pack buffer layout (float offsets) ----
// W1 packed: [cp12][row61][kw12][2]  where row = kd*11+kh (kd<5: 0..54, kd=5: 55..60)
constexpr int PK_W1 = 0,            SZ_W1 = 12 * 61 * 12 * 2;  // 17568
constexpr int PK_W3 = PK_W1 + SZ_W1, SZ_W3 = 663552; // [ic384][t9][dp96][2]
constexpr int PK_WA = PK_W3 + SZ_W3, SZ_WA = 1200;   // [c25][up24][2]
constexpr int PK_BA = PK_WA + SZ_WA, SZ_BA = 48;
constexpr int PK_WB = PK_BA + SZ_BA, SZ_WB = 4608;   // [h2][j48][up24][2]
constexpr int PK_BB = PK_WB + SZ_WB, SZ_BB = 96;
constexpr int PK_WC = PK_BB + SZ_BB, SZ_WC = 1152;   // [j96][p6][2]
constexpr int PK_BC = PK_WC + SZ_WC, SZ_BC = 12;

// K3 smem layout = contiguous copy of [PK_WA .. PK_BC+SZ_BC)
constexpr int SA_WA = 0, SA_BA = 1200, SA_WB = 1248, SA_BB = 5856,
              SA_WC = 5952, SA_BC = 7104, K3_SM = 7116;

// K2 smem: x window 6 slices x 18 rows x pitch 60 + packed W1
constexpr int K2_SX = 6 * 18 * 60;            // 6480 floats
constexpr int K2_SW = SZ_W1;                  // 17568 floats
constexpr int K2_SMEM = (K2_SX + K2_SW) * 4;  // 96192 B  (2 CTAs/SM)
}

__device__ __align__(16) float g_pack[689680];
__device__ float g_h[VOX];
__device__ float g_x1[(size_t)24 * VOX];

// ---- f32x2 helpers ----
__device__ __forceinline__ unsigned long long splat2(float v) {
    unsigned long long r; asm("mov.b64 %0, {%1, %1};" : "=l"(r) : "f"(v)); return r;
}
__device__ __forceinline__ unsigned long long pack2(float a, float b) {
    unsigned long long r; asm("mov.b64 %0, {%1, %2};" : "=l"(r) : "f"(a), "f"(b)); return r;
}
__device__ __forceinline__ float2 unpack2(unsigned long long v) {
    float2 f; asm("mov.b64 {%0, %1}, %2;" : "=f"(f.x), "=f"(f.y) : "l"(v)); return f;
}
__device__ __forceinline__ void fma2(unsigned long long& a, unsigned long long w,
                                     unsigned long long x) {
    asm("fma.rn.f32x2 %0, %1, %2, %0;" : "+l"(a) : "l"(w), "l"(x));
}

// =============== K0: pack weights into pair layouts ===============
__global__ void pack_kernel(const float* __restrict__ W3, const float* __restrict__ W1,
                            const float* __restrict__ Wa, const float* __restrict__ ba,
                            const float* __restrict__ Wb, const float* __restrict__ bb,
                            const float* __restrict__ Wc, const float* __restrict__ bc) {
    int nt = gridDim.x * blockDim.x, tid = blockIdx.x * blockDim.x + threadIdx.x;
    for (int i = tid; i < SZ_W1; i += nt) {
        int par = i & 1, q = i >> 1;
        int kw = q % 12; q /= 12;
        int row = q % 61; int cp = q / 61;
        int kd = row / 11, kh = row % 11;       // valid for rows 0..60
        int c = cp * 2 + par;
        int flat = kd * 121 + kh * 11 + kw;
        float v = 0.f;
        if (kw < 11 && flat < 665) v = W1[c * 1331 + flat];
        g_pack[PK_W1 + i] = v;
    }
    for (int i = tid; i < SZ_W3; i += nt) {
        int par = i & 1, q = i >> 1;
        int dp = q % 96; q /= 96;
        int t = q % 9;   int ic = q / 9;
        g_pack[PK_W3 + i] = W3[((size_t)(dp * 2 + par) * 384 + ic) * 9 + t];
    }
    for (int i = tid; i < SZ_WA; i += nt) {
        int par = i & 1, q = i >> 1;
        int up = q % 24, c = q / 24;
        g_pack[PK_WA + i] = Wa[(up * 2 + par) * 25 + c];
    }
    for (int i = tid; i < SZ_BA; i += nt) {
        int par = i & 1, up = i >> 1;
        g_pack[PK_BA + i] = ba[up * 2 + par];
    }
    for (int i = tid; i < SZ_WB; i += nt) {
        int par = i & 1, q = i >> 1;
        int up = q % 24; q /= 24;
        int j = q % 48;  int h = q / 48;
        g_pack[PK_WB + i] = Wb[(h * 48 + up * 2 + par) * 48 + j];
    }
    for (int i = tid; i < SZ_BB; i += nt) {
        int par = i & 1, q = i >> 1;
        int up = q % 24, h = q / 24;
        g_pack[PK_BB + i] = bb[h * 48 + up * 2 + par];
    }
    for (int i = tid; i < SZ_WC; i += nt) {
        int par = i & 1, q = i >> 1;
        int p = q % 6, j = q / 6;
        int o = p * 2 + par;
        g_pack[PK_WC + i] = (o < 9) ? Wc[o * 96 + j] : 0.f;
    }
    for (int i = tid; i < SZ_BC; i += nt) {
        int par = i & 1, p = i >> 1;
        int o = p * 2 + par;
        g_pack[PK_BC + i] = (o < 9) ? bc[o] : 0.f;
    }
}

// =============== K1: conv2d (hyper -> g_h), d-pairs packed ===============
__global__ __launch_bounds__(192, 2)
void conv2d_kernel(const float* __restrict__ hyper, const float* __restrict__ b3) {
    __shared__ float s_hyp[16 * 520];  // 16 ic x 10 rows x pitch 52
    int bx = blockIdx.x;
    int dg = bx % 48, rt = bx / 48;
    int r0 = rt * 8;
    int tid = threadIdx.x;
    int dhalf = tid / 96, r8 = (tid % 96) / 12, grp = tid % 12, x0 = grp * 4;
    int dp = dg * 2 + dhalf, d0 = dp * 2;

    unsigned long long acc[4];
    {
        unsigned long long bv = pack2(b3[d0], b3[d0 + 1]);
        acc[0] = bv; acc[1] = bv; acc[2] = bv; acc[3] = bv;
    }
    const unsigned long long* w3u = (const unsigned long long*)g_pack + (PK_W3 / 2);

    for (int icb = 0; icb < 384; icb += 16) {
        for (int i = tid; i < 16 * 520; i += 192) {
            int icl = i / 520, rr = (i % 520) / 52, cc = i % 52;
            int grow = r0 - 1 + rr, gcol = cc - 1;
            float v = 0.f;
            if (grow >= 0 && grow < 48 && gcol >= 0 && gcol < 48)
                v = hyper[(size_t)(icb + icl) * PLANE + grow * 48 + gcol];
            s_hyp[i] = v;
        }
        __syncthreads();
        #pragma unroll 2
        for (int icl = 0; icl < 16; icl++) {
            const float* hw = s_hyp + icl * 520 + r8 * 52 + x0;
            unsigned long long ss[3][6];
            #pragma unroll
            for (int ky = 0; ky < 3; ky++) {
                const float* row = hw + ky * 52;
                float4 a = *(const float4*)row;
                float2 b = *(const float2*)(row + 4);
                ss[ky][0] = splat2(a.x); ss[ky][1] = splat2(a.y); ss[ky][2] = splat2(a.z);
                ss[ky][3] = splat2(a.w); ss[ky][4] = splat2(b.x); ss[ky][5] = splat2(b.y);
            }
            const unsigned long long* wrow = w3u + (size_t)(icb + icl) * 9 * 96 + dp;
            #pragma unroll
            for (int ky = 0; ky < 3; ky++)
                #pragma unroll
                for (int kx = 0; kx < 3; kx++) {
                    unsigned long long wv = wrow[(ky * 3 + kx) * 96];
                    fma2(acc[0], wv, ss[ky][kx + 0]);
                    fma2(acc[1], wv, ss[ky][kx + 1]);
                    fma2(acc[2], wv, ss[ky][kx + 2]);
                    fma2(acc[3], wv, ss[ky][kx + 3]);
                }
        }
        __syncthreads();
    }
    float2 v0 = unpack2(acc[0]), v1 = unpack2(acc[1]);
    float2 v2 = unpack2(acc[2]), v3 = unpack2(acc[3]);
    int gp = (r0 + r8) * 48 + x0;
    *(float4*)(g_h + (size_t)d0 * PLANE + gp)       = make_float4(v0.x, v1.x, v2.x, v3.x);
    *(float4*)(g_h + (size_t)(d0 + 1) * PLANE + gp) = make_float4(v0.y, v1.y, v2.y, v3.y);
}

// =============== K2: masked conv3d: 256 thr, 3 cpairs x 6 px per thread ===============
__global__ __launch_bounds__(256, 2)
void conv3d_kernel(const float* __restrict__ x, const float* __restrict__ b1) {
    extern __shared__ float sm[];
    float* s_x = sm;
    float* s_w = sm + K2_SX;

    int d = blockIdx.x / 6, rb = blockIdx.x % 6;
    int r0 = rb * 8;
    int tid = threadIdx.x;
    int cq = tid >> 6;              // 0..3  -> 3 channel-pairs each
    int t64 = tid & 63;
    int r8 = t64 >> 3;              // 0..7 local output row
    int grp = t64 & 7;              // 0..7 -> 6 px each
    int x0 = grp * 6;

    for (int i = tid; i < K2_SX / 4; i += 256)
        ((float4*)s_x)[i] = make_float4(0.f, 0.f, 0.f, 0.f);
    for (int i = tid; i < K2_SW / 4; i += 256)
        ((float4*)s_w)[i] = ((const float4*)(g_pack + PK_W1))[i];
    __syncthreads();
    // rows r0-5 .. r0+12 for depths d-5..d
    for (int i = tid; i < 6 * 18 * 12; i += 256) {
        int s = i / 216, rr = (i % 216) / 12, f4 = i % 12;
        int sd = d - 5 + s, grow = r0 - 5 + rr;
        if (sd >= 0 && grow >= 0 && grow < 48) {
            float4 v = *(const float4*)(x + (size_t)sd * PLANE + grow * 48 + f4 * 4);
            float* dst = s_x + (s * 18 + rr) * 60 + 5 + f4 * 4;
            dst[0] = v.x; dst[1] = v.y; dst[2] = v.z; dst[3] = v.w;
        }
    }
    __syncthreads();

    unsigned long long acc[3][6];
    #pragma unroll
    for (int c = 0; c < 3; c++) {
        int cp = cq * 3 + c;
        unsigned long long bv = pack2(b1[cp * 2], b1[cp * 2 + 1]);
        #pragma unroll
        for (int p = 0; p < 6; p++) acc[c][p] = bv;
    }

    const ulonglong2* wb = (const ulonglong2*)s_w;
    int kd0 = (d >= 5) ? 0 : (5 - d);
    for (int kd = kd0; kd < 6; kd++) {
        int khmax = (kd < 5) ? 11 : 6;
        for (int kh = 0; kh < khmax; kh++) {
            const float* xr = s_x + (kd * 18 + r8 + kh) * 60 + x0;  // x0 even -> 8B aligned
            unsigned long long xs[16];
            #pragma unroll
            for (int i = 0; i < 16; i += 2) {
                float2 v = *(const float2*)(xr + i);
                xs[i] = splat2(v.x); xs[i + 1] = splat2(v.y);
            }
            int wrow = kd * 11 + kh;  // 0..60, matches packed layout
            #pragma unroll
            for (int c = 0; c < 3; c++) {
                int cp = cq * 3 + c;
                const ulonglong2* wr = wb + (cp * 61 + wrow) * 6;
                ulonglong2 wA = wr[0], wB = wr[1], wC = wr[2],
                           wD = wr[3], wE = wr[4], wF = wr[5];
                unsigned long long wv[11] = {wA.x, wA.y, wB.x, wB.y, wC.x, wC.y,
                                             wD.x, wD.y, wE.x, wE.y, wF.x};
                #pragma unroll
                for (int kw = 0; kw < 11; kw++) {
                    fma2(acc[c][0], wv[kw], xs[kw]);
                    fma2(acc[c][1], wv[kw], xs[kw + 1]);
                    fma2(acc[c][2], wv[kw], xs[kw + 2]);
                    fma2(acc[c][3], wv[kw], xs[kw + 3]);
                    fma2(acc[c][4], wv[kw], xs[kw + 4]);
                    fma2(acc[c][5], wv[kw], xs[kw + 5]);
                }
            }
        }
    }

    int gp = (r0 + r8) * 48 + x0;
    #pragma unroll
    for (int c = 0; c < 3; c++) {
        int c0 = (cq * 3 + c) * 2;
        float2 p0 = unpack2(acc[c][0]), p1 = unpack2(acc[c][1]);
        float2 p2 = unpack2(acc[c][2]), p3 = unpack2(acc[c][3]);
        float2 p4 = unpack2(acc[c][4]), p5 = unpack2(acc[c][5]);
        float* d0p = g_x1 + ((size_t)d * 24 + c0) * PLANE + gp;
        float* d1p = g_x1 + ((size_t)d * 24 + c0 + 1) * PLANE + gp;
        *(float2*)(d0p)     = make_float2(p0.x, p1.x);
        *(float2*)(d0p + 2) = make_float2(p2.x, p3.x);
        *(float2*)(d0p + 4) = make_float2(p4.x, p5.x);
        *(float2*)(d1p)     = make_float2(p0.y, p1.y);
        *(float2*)(d1p + 2) = make_float2(p2.y, p3.y);
        *(float2*)(d1p + 4) = make_float2(p4.y, p5.y);
    }
}

// =============== K3: per-voxel MLP + mixture CDF, 2 voxels/thread, 128-thr CTA ===============
__global__ __launch_bounds__(128)
void mlp_kernel(const float* __restrict__ x, float* __restrict__ out) {
    __shared__ float sm[K3_SM + 4];
    int tid = threadIdx.x;
    for (int i = tid; i < K3_SM / 4; i += 128)
        ((float4*)sm)[i] = ((const float4*)(g_pack + PK_WA))[i];
    __syncthreads();
    const unsigned long long* su = (const unsigned long long*)sm;
    const ulonglong2* su2 = (const ulonglong2*)sm;

    int base = (blockIdx.x * 128 + tid) * 2;
    int d = base / PLANE, p = base % PLANE;

    float2 t2[25];
    const float* xb = g_x1 + (size_t)d * 24 * PLANE + p;
    #pragma unroll
    for (int c = 0; c < 24; c++) t2[c] = *(const float2*)(xb + (size_t)c * PLANE);
    t2[24] = *(const float2*)(g_h + base);

    // layer A: 25 -> 48, 2 voxels share weight regs
    unsigned long long accA[2][24];
    #pragma unroll
    for (int u = 0; u < 24; u++) {
        unsigned long long b = su[SA_BA / 2 + u];
        accA[0][u] = b; accA[1][u] = b;
    }
    #pragma unroll 5
    for (int c = 0; c < 25; c++) {
        unsigned long long s0 = splat2(t2[c].x), s1 = splat2(t2[c].y);
        const ulonglong2* wr = su2 + SA_WA / 4 + c * 12;
        #pragma unroll
        for (int u2 = 0; u2 < 12; u2++) {
            ulonglong2 ww = wr[u2];
            fma2(accA[0][2 * u2], ww.x, s0); fma2(accA[0][2 * u2 + 1], ww.y, s0);
            fma2(accA[1][2 * u2], ww.x, s1); fma2(accA[1][2 * u2 + 1], ww.y, s1);
        }
    }
    float a0[48], a1[48];
    #pragma unroll
    for (int u = 0; u < 24; u++) {
        float2 v = unpack2(accA[0][u]);
        a0[2 * u] = fmaxf(v.x, 0.f); a0[2 * u + 1] = fmaxf(v.y, 0.f);
        float2 w = unpack2(accA[1][u]);
        a1[2 * u] = fmaxf(w.x, 0.f); a1[2 * u + 1] = fmaxf(w.y, 0.f);
    }

    unsigned long long oacc[2][5];
    #pragma unroll
    for (int pp = 0; pp < 5; pp++) {
        unsigned long long b = su[SA_BC / 2 + pp];
        oacc[0][pp] = b; oacc[1][pp] = b;
    }

    // layer B in output-quarters (24 units), fused with layer C
    #pragma unroll 1
    for (int q = 0; q < 4; q++) {
        int h = q >> 1, uoff = (q & 1) * 12;
        unsigned long long accB[2][12];
        #pragma unroll
        for (int k = 0; k < 12; k++) {
            unsigned long long b = su[SA_BB / 2 + h * 24 + uoff + k];
            accB[0][k] = b; accB[1][k] = b;
        }
        #pragma unroll 4
        for (int j = 0; j < 48; j++) {
            unsigned long long s0 = splat2(a0[j]), s1 = splat2(a1[j]);
            const ulonglong2* wr = su2 + SA_WB / 4 + (h * 48 + j) * 12 + (q & 1) * 6;
            #pragma unroll
            for (int u2 = 0; u2 < 6; u2++) {
                ulonglong2 ww = wr[u2];
                fma2(accB[0][2 * u2], ww.x, s0); fma2(accB[0][2 * u2 + 1], ww.y, s0);
                fma2(accB[1][2 * u2], ww.x, s1); fma2(accB[1][2 * u2 + 1], ww.y, s1);
            }
        }
        #pragma unroll
        for (int k = 0; k < 12; k++) {
            float2 v0 = unpack2(accB[0][k]);
            float2 v1 = unpack2(accB[1][k]);
            int j96 = h * 48 + (uoff + k) * 2;
            const ulonglong2* w0 = su2 + SA_WC / 4 + j96 * 3;
            ulonglong2 q0 = w0[0], q1 = w0[1], q2 = w0[2];   // unit j96
            ulonglong2 r0 = w0[3], r1 = w0[4], r2 = w0[5];   // unit j96+1
            unsigned long long e00 = splat2(fmaxf(v0.x, 0.f));
            unsigned long long e01 = splat2(fmaxf(v0.y, 0.f));
            unsigned long long e10 = splat2(fmaxf(v1.x, 0.f));
            unsigned long long e11 = splat2(fmaxf(v1.y, 0.f));
            fma2(oacc[0][0], q0.x, e00); fma2(oacc[0][1], q0.y, e00);
            fma2(oacc[0][2], q1.x, e00); fma2(oacc[0][3], q1.y, e00);
            fma2(oacc[0][4], q2.x, e00);
            fma2(oacc[0][0], r0.x, e01); fma2(oacc[0][1], r0.y, e01);
            fma2(oacc[0][2], r1.x, e01); fma2(oacc[0][3], r1.y, e01);
            fma2(oacc[0][4], r2.x, e01);
            fma2(oacc[1][0], q0.x, e10); fma2(oacc[1][1], q0.y, e10);
            fma2(oacc[1][2], q1.x, e10); fma2(oacc[1][3], q1.y, e10);
            fma2(oacc[1][4], q2.x, e10);
            fma2(oacc[1][0], r0.x, e11); fma2(oacc[1][1], r0.y, e11);
            fma2(oacc[1][2], r1.x, e11); fma2(oacc[1][3], r1.y, e11);
            fma2(oacc[1][4], r2.x, e11);
        }
    }

    float p3v[2];
    float o9v[2][9];
    float2 xv2 = *(const float2*)(x + base);
    #pragma unroll
    for (int v = 0; v < 2; v++) {
        float o9[9];
        #pragma unroll
        for (int pp = 0; pp < 4; pp++) {
            float2 w = unpack2(oacc[v][pp]);
            o9[2 * pp] = w.x; o9[2 * pp + 1] = w.y;
        }
        o9[8] = unpack2(oacc[v][4]).x;

        float xv = (v == 0) ? xv2.x : xv2.y;
        float mx = fmaxf(o9[6], fmaxf(o9[7], o9[8]));
        float e0 = expf(o9[6] - mx), e1 = expf(o9[7] - mx), e2 = expf(o9[8] - mx);
        float inv = 1.f / (e0 + e1 + e2);
        float wsm[3] = {e0 * inv, e1 * inv, e2 * inv};

        float p3 = 0.f;
        #pragma unroll
        for (int k = 0; k < 3; k++) {
            float mu = o9[k];
            float scv = o9[3 + k];
            if (scv == 0.f) scv = 1e-9f;
            scv = fabsf(scv);
            float invs = 1.f / scv;
            float l = fabsf(normcdff((xv + 0.5f - mu) * invs)
                          - normcdff((xv - 0.5f - mu) * invs));
            p3 = fmaf(wsm[k], l, p3);
        }
        p3v[v] = p3;
        #pragma unroll
        for (int o = 0; o < 9; o++) o9v[v][o] = o9[o];
    }

    *(float2*)(out + base) = make_float2(p3v[0], p3v[1]);
    #pragma unroll
    for (int o = 0; o < 9; o++)
        *(float2*)(out + (size_t)VOX + (size_t)o * VOX + base) =
            make_float2(o9v[0][o], o9v[1][o]);
}

extern "C" void kernel_launch(void* const* d_in, const int* in_sizes, int n_in,
                              void* d_out, int out_size) {
    const float* x     = (const float*)d_in[0];
    const float* hyper = (const float*)d_in[1];
    const float* W3    = (const float*)d_in[2];
    const float* b3    = (const float*)d_in[3];
    const float* W1    = (const float*)d_in[4];
    const float* b1    = (const float*)d_in[5];
    const float* Wa    = (const float*)d_in[6];
    const float* ba    = (const float*)d_in[7];
    const float* Wb    = (const float*)d_in[8];
    const float* bb    = (const float*)d_in[9];
    const float* Wc    = (const float*)d_in[10];
    const float* bc    = (const float*)d_in[11];
    float* out = (float*)d_out;

    cudaFuncSetAttribute(conv3d_kernel,
                         cudaFuncAttributeMaxDynamicSharedMemorySize, K2_SMEM);

    pack_kernel<<<128, 256>>>(W3, W1, Wa, ba, Wb, bb, Wc, bc);
    conv2d_kernel<<<288, 192>>>(hyper, b3);
    conv3d_kernel<<<1152, 256, K2_SMEM>>>(x, b1);
    mlp_kernel<<<VOX / 256, 128>>>(x, out);
}

// round 8
// speedup vs baseline: 1.2325x; 1.0852x over previous
#include <cuda_runtime.h>
#include <cuda_bf16.h>
#include <cmath>
#include <cstring>
#include <cstdint>

namespace {
constexpr int D = 192, H = 48, W = 48, PLANE = 2304, VOX = 442368;

// ---- pack buffer layout (float offsets) ----
constexpr int PK_W1 = 0,            SZ_W1 = 12 * 61 * 12 * 2;  // 17568
constexpr int PK_W3 = PK_W1 + SZ_W1, SZ_W3 = 663552;           // [ic384][t9][dp96][2]

// conv3d smem
constexpr int K2_SX = 6 * 18 * 60;
constexpr int K2_SW = SZ_W1;
constexpr int K2_SMEM = (K2_SX + K2_SW) * 4;   // 96192 B

// ---- mlp mma kernel: smem byte offsets ----
constexpr int XP = 208;   // X/activation row pitch (bytes)
constexpr int WP = 112;   // Wa/Wb row pitch
constexpr int CP = 208;   // Wc row pitch
constexpr int MO_XH  = 0;        // 128 x 208
constexpr int MO_XL  = 26624;
constexpr int MO_WAH = 53248;    // 48 x 112
constexpr int MO_WAL = 58624;
constexpr int MO_WBH = 64000;    // 96 x 112
constexpr int MO_WBL = 74752;
constexpr int MO_WCH = 85504;    // 16 x 208
constexpr int MO_WCL = 88832;
constexpr int MO_EX  = 92160;    // 128 x 18 f32 exchange
constexpr int MO_BA  = 101376;
constexpr int MO_BB  = 101568;
constexpr int MO_BC  = 101952;
constexpr int MO_SMEM = 102016;
}

__device__ __align__(16) float g_pack[689680];
__device__ float g_h[VOX];
__device__ float g_x1[(size_t)24 * VOX];

// ---- f32x2 helpers (conv kernels) ----
__device__ __forceinline__ unsigned long long splat2(float v) {
    unsigned long long r; asm("mov.b64 %0, {%1, %1};" : "=l"(r) : "f"(v)); return r;
}
__device__ __forceinline__ unsigned long long pack2(float a, float b) {
    unsigned long long r; asm("mov.b64 %0, {%1, %2};" : "=l"(r) : "f"(a), "f"(b)); return r;
}
__device__ __forceinline__ float2 unpack2(unsigned long long v) {
    float2 f; asm("mov.b64 {%0, %1}, %2;" : "=f"(f.x), "=f"(f.y) : "l"(v)); return f;
}
__device__ __forceinline__ void fma2(unsigned long long& a, unsigned long long w,
                                     unsigned long long x) {
    asm("fma.rn.f32x2 %0, %1, %2, %0;" : "+l"(a) : "l"(w), "l"(x));
}

// ---- mma.sync helpers (baseline PTX, compute_103-safe) ----
__device__ __forceinline__ uint32_t smem_u32(const void* p) {
    uint32_t a;
    asm("{ .reg .u64 t; cvta.to.shared.u64 t, %1; cvt.u32.u64 %0, t; }"
        : "=r"(a) : "l"(p));
    return a;
}
#define LDSM4(r, addr) \
    asm volatile("ldmatrix.sync.aligned.m8n8.x4.shared.b16 {%0,%1,%2,%3}, [%4];" \
        : "=r"((r)[0]), "=r"((r)[1]), "=r"((r)[2]), "=r"((r)[3]) : "r"(addr))
// B stored [N][K] row-major == col-major KxN -> NON-trans x2 (matrix0 = k0-7, matrix1 = k8-15)
#define LDSM2(r, addr) \
    asm volatile("ldmatrix.sync.aligned.m8n8.x2.shared.b16 {%0,%1}, [%2];" \
        : "=r"((r)[0]), "=r"((r)[1]) : "r"(addr))
#define MMA16816(d, a, b) \
    asm volatile("mma.sync.aligned.m16n8k16.row.col.f32.bf16.bf16.f32 " \
        "{%0,%1,%2,%3}, {%4,%5,%6,%7}, {%8,%9}, {%0,%1,%2,%3};" \
        : "+f"((d)[0]), "+f"((d)[1]), "+f"((d)[2]), "+f"((d)[3]) \
        : "r"((a)[0]), "r"((a)[1]), "r"((a)[2]), "r"((a)[3]), \
          "r"((b)[0]), "r"((b)[1]))

__device__ __forceinline__ void split_bf(float v, __nv_bfloat16& h, __nv_bfloat16& l) {
    h = __float2bfloat16(v);
    l = __float2bfloat16(v - __bfloat162float(h));
}
__device__ __forceinline__ uint32_t pack_bf2(__nv_bfloat16 a, __nv_bfloat16 b) {
    __nv_bfloat162 t; t.x = a; t.y = b;
    uint32_t u; memcpy(&u, &t, 4); return u;
}

// =============== K0: pack conv weights ===============
__global__ void pack_kernel(const float* __restrict__ W3, const float* __restrict__ W1) {
    int nt = gridDim.x * blockDim.x, tid = blockIdx.x * blockDim.x + threadIdx.x;
    for (int i = tid; i < SZ_W1; i += nt) {
        int par = i & 1, q = i >> 1;
        int kw = q % 12; q /= 12;
        int row = q % 61; int cp = q / 61;
        int kd = row / 11, kh = row % 11;
        int c = cp * 2 + par;
        int flat = kd * 121 + kh * 11 + kw;
        float v = 0.f;
        if (kw < 11 && flat < 665) v = W1[c * 1331 + flat];
        g_pack[PK_W1 + i] = v;
    }
    for (int i = tid; i < SZ_W3; i += nt) {
        int par = i & 1, q = i >> 1;
        int dp = q % 96; q /= 96;
        int t = q % 9;   int ic = q / 9;
        g_pack[PK_W3 + i] = W3[((size_t)(dp * 2 + par) * 384 + ic) * 9 + t];
    }
}

// =============== K1: conv2d (unchanged R5) ===============
__global__ __launch_bounds__(192, 2)
void conv2d_kernel(const float* __restrict__ hyper, const float* __restrict__ b3) {
    __shared__ float s_hyp[16 * 520];
    int bx = blockIdx.x;
    int dg = bx % 48, rt = bx / 48;
    int r0 = rt * 8;
    int tid = threadIdx.x;
    int dhalf = tid / 96, r8 = (tid % 96) / 12, grp = tid % 12, x0 = grp * 4;
    int dp = dg * 2 + dhalf, d0 = dp * 2;

    unsigned long long acc[4];
    {
        unsigned long long bv = pack2(b3[d0], b3[d0 + 1]);
        acc[0] = bv; acc[1] = bv; acc[2] = bv; acc[3] = bv;
    }
    const unsigned long long* w3u = (const unsigned long long*)g_pack + (PK_W3 / 2);

    for (int icb = 0; icb < 384; icb += 16) {
        for (int i = tid; i < 16 * 520; i += 192) {
            int icl = i / 520, rr = (i % 520) / 52, cc = i % 52;
            int grow = r0 - 1 + rr, gcol = cc - 1;
            float v = 0.f;
            if (grow >= 0 && grow < 48 && gcol >= 0 && gcol < 48)
                v = hyper[(size_t)(icb + icl) * PLANE + grow * 48 + gcol];
            s_hyp[i] = v;
        }
        __syncthreads();
        #pragma unroll 2
        for (int icl = 0; icl < 16; icl++) {
            const float* hw = s_hyp + icl * 520 + r8 * 52 + x0;
            unsigned long long ss[3][6];
            #pragma unroll
            for (int ky = 0; ky < 3; ky++) {
                const float* row = hw + ky * 52;
                float4 a = *(const float4*)row;
                float2 b = *(const float2*)(row + 4);
                ss[ky][0] = splat2(a.x); ss[ky][1] = splat2(a.y); ss[ky][2] = splat2(a.z);
                ss[ky][3] = splat2(a.w); ss[ky][4] = splat2(b.x); ss[ky][5] = splat2(b.y);
            }
            const unsigned long long* wrow = w3u + (size_t)(icb + icl) * 9 * 96 + dp;
            #pragma unroll
            for (int ky = 0; ky < 3; ky++)
                #pragma unroll
                for (int kx = 0; kx < 3; kx++) {
                    unsigned long long wv = wrow[(ky * 3 + kx) * 96];
                    fma2(acc[0], wv, ss[ky][kx + 0]);
                    fma2(acc[1], wv, ss[ky][kx + 1]);
                    fma2(acc[2], wv, ss[ky][kx + 2]);
                    fma2(acc[3], wv, ss[ky][kx + 3]);
                }
        }
        __syncthreads();
    }
    float2 v0 = unpack2(acc[0]), v1 = unpack2(acc[1]);
    float2 v2 = unpack2(acc[2]), v3 = unpack2(acc[3]);
    int gp = (r0 + r8) * 48 + x0;
    *(float4*)(g_h + (size_t)d0 * PLANE + gp)       = make_float4(v0.x, v1.x, v2.x, v3.x);
    *(float4*)(g_h + (size_t)(d0 + 1) * PLANE + gp) = make_float4(v0.y, v1.y, v2.y, v3.y);
}

// =============== K2: masked conv3d (unchanged R5) ===============
__global__ __launch_bounds__(256, 2)
void conv3d_kernel(const float* __restrict__ x, const float* __restrict__ b1) {
    extern __shared__ float sm[];
    float* s_x = sm;
    float* s_w = sm + K2_SX;

    int d = blockIdx.x / 6, rb = blockIdx.x % 6;
    int r0 = rb * 8;
    int tid = threadIdx.x;
    int cq = tid >> 6;
    int t64 = tid & 63;
    int r8 = t64 >> 3;
    int grp = t64 & 7;
    int x0 = grp * 6;

    for (int i = tid; i < K2_SX / 4; i += 256)
        ((float4*)s_x)[i] = make_float4(0.f, 0.f, 0.f, 0.f);
    for (int i = tid; i < K2_SW / 4; i += 256)
        ((float4*)s_w)[i] = ((const float4*)(g_pack + PK_W1))[i];
    __syncthreads();
    for (int i = tid; i < 6 * 18 * 12; i += 256) {
        int s = i / 216, rr = (i % 216) / 12, f4 = i % 12;
        int sd = d - 5 + s, grow = r0 - 5 + rr;
        if (sd >= 0 && grow >= 0 && grow < 48) {
            float4 v = *(const float4*)(x + (size_t)sd * PLANE + grow * 48 + f4 * 4);
            float* dst = s_x + (s * 18 + rr) * 60 + 5 + f4 * 4;
            dst[0] = v.x; dst[1] = v.y; dst[2] = v.z; dst[3] = v.w;
        }
    }
    __syncthreads();

    unsigned long long acc[3][6];
    #pragma unroll
    for (int c = 0; c < 3; c++) {
        int cp = cq * 3 + c;
        unsigned long long bv = pack2(b1[cp * 2], b1[cp * 2 + 1]);
        #pragma unroll
        for (int p = 0; p < 6; p++) acc[c][p] = bv;
    }

    const ulonglong2* wb = (const ulonglong2*)s_w;
    int kd0 = (d >= 5) ? 0 : (5 - d);
    for (int kd = kd0; kd < 6; kd++) {
        int khmax = (kd < 5) ? 11 : 6;
        for (int kh = 0; kh < khmax; kh++) {
            const float* xr = s_x + (kd * 18 + r8 + kh) * 60 + x0;
            unsigned long long xs[16];
            #pragma unroll
            for (int i = 0; i < 16; i += 2) {
                float2 v = *(const float2*)(xr + i);
                xs[i] = splat2(v.x); xs[i + 1] = splat2(v.y);
            }
            int wrow = kd * 11 + kh;
            #pragma unroll
            for (int c = 0; c < 3; c++) {
                int cp = cq * 3 + c;
                const ulonglong2* wr = wb + (cp * 61 + wrow) * 6;
                ulonglong2 wA = wr[0], wB = wr[1], wC = wr[2],
                           wD = wr[3], wE = wr[4], wF = wr[5];
                unsigned long long wv[11] = {wA.x, wA.y, wB.x, wB.y, wC.x, wC.y,
                                             wD.x, wD.y, wE.x, wE.y, wF.x};
                #pragma unroll
                for (int kw = 0; kw < 11; kw++) {
                    fma2(acc[c][0], wv[kw], xs[kw]);
                    fma2(acc[c][1], wv[kw], xs[kw + 1]);
                    fma2(acc[c][2], wv[kw], xs[kw + 2]);
                    fma2(acc[c][3], wv[kw], xs[kw + 3]);
                    fma2(acc[c][4], wv[kw], xs[kw + 4]);
                    fma2(acc[c][5], wv[kw], xs[kw + 5]);
                }
            }
        }
    }

    int gp = (r0 + r8) * 48 + x0;
    #pragma unroll
    for (int c = 0; c < 3; c++) {
        int c0 = (cq * 3 + c) * 2;
        float2 p0 = unpack2(acc[c][0]), p1 = unpack2(acc[c][1]);
        float2 p2 = unpack2(acc[c][2]), p3 = unpack2(acc[c][3]);
        float2 p4 = unpack2(acc[c][4]), p5 = unpack2(acc[c][5]);
        float* d0p = g_x1 + ((size_t)d * 24 + c0) * PLANE + gp;
        float* d1p = g_x1 + ((size_t)d * 24 + c0 + 1) * PLANE + gp;
        *(float2*)(d0p)     = make_float2(p0.x, p1.x);
        *(float2*)(d0p + 2) = make_float2(p2.x, p3.x);
        *(float2*)(d0p + 4) = make_float2(p4.x, p5.x);
        *(float2*)(d1p)     = make_float2(p0.y, p1.y);
        *(float2*)(d1p + 2) = make_float2(p2.y, p3.y);
        *(float2*)(d1p + 4) = make_float2(p4.y, p5.y);
    }
}

// =============== K3: MLP via mma.sync bf16-split + CDF epilogue ===============
__global__ __launch_bounds__(128)
void mlp_mma_kernel(const float* __restrict__ x,
                    const float* __restrict__ Wa, const float* __restrict__ ba,
                    const float* __restrict__ Wb, const float* __restrict__ bb,
                    const float* __restrict__ Wc, const float* __restrict__ bc,
                    float* __restrict__ out)
{
    extern __shared__ char sm_[];
    const uint32_t sb = smem_u32(sm_);
    const int tid = threadIdx.x;
    const int lane = tid & 31, w = tid >> 5;
    const int gid = lane >> 2, tig = lane & 3;

    float* s_ba = (float*)(sm_ + MO_BA);
    float* s_bb = (float*)(sm_ + MO_BB);
    float* s_bc = (float*)(sm_ + MO_BC);
    float* s_ex = (float*)(sm_ + MO_EX);

    for (int i = tid; i < 48; i += 128) s_ba[i] = ba[i];
    for (int i = tid; i < 96; i += 128) s_bb[i] = bb[i];
    for (int i = tid; i < 16; i += 128) s_bc[i] = (i < 9) ? bc[i] : 0.f;

    // Wa [48 units][25 K pad 32]
    for (int u = tid; u < 48; u += 128) {
        #pragma unroll
        for (int i = 0; i < 16; i++) {
            int c0 = 2 * i, c1 = 2 * i + 1;
            float v0 = (c0 < 25) ? Wa[u * 25 + c0] : 0.f;
            float v1 = (c1 < 25) ? Wa[u * 25 + c1] : 0.f;
            __nv_bfloat16 h0, l0, h1, l1;
            split_bf(v0, h0, l0); split_bf(v1, h1, l1);
            *(uint32_t*)(sm_ + MO_WAH + u * WP + 4 * i) = pack_bf2(h0, h1);
            *(uint32_t*)(sm_ + MO_WAL + u * WP + 4 * i) = pack_bf2(l0, l1);
        }
    }
    // Wb [96][48]
    for (int u = tid; u < 96; u += 128) {
        #pragma unroll
        for (int i = 0; i < 24; i++) {
            float v0 = Wb[u * 48 + 2 * i], v1 = Wb[u * 48 + 2 * i + 1];
            __nv_bfloat16 h0, l0, h1, l1;
            split_bf(v0, h0, l0); split_bf(v1, h1, l1);
            *(uint32_t*)(sm_ + MO_WBH + u * WP + 4 * i) = pack_bf2(h0, h1);
            *(uint32_t*)(sm_ + MO_WBL + u * WP + 4 * i) = pack_bf2(l0, l1);
        }
    }
    // Wc [9 pad 16][96]
    for (int u = tid; u < 16; u += 128) {
        #pragma unroll 8
        for (int i = 0; i < 48; i++) {
            float v0 = (u < 9) ? Wc[u * 96 + 2 * i] : 0.f;
            float v1 = (u < 9) ? Wc[u * 96 + 2 * i + 1] : 0.f;
            __nv_bfloat16 h0, l0, h1, l1;
            split_bf(v0, h0, l0); split_bf(v1, h1, l1);
            *(uint32_t*)(sm_ + MO_WCH + u * CP + 4 * i) = pack_bf2(h0, h1);
            *(uint32_t*)(sm_ + MO_WCL + u * CP + 4 * i) = pack_bf2(l0, l1);
        }
    }

    // stage X: voxel = tid, K = 25 pad 32
    const int v = blockIdx.x * 128 + tid;
    const int dd = v / PLANE, p = v % PLANE;
    {
        const float* xb = g_x1 + (size_t)dd * 24 * PLANE + p;
        float t[26];
        #pragma unroll
        for (int c = 0; c < 24; c++) t[c] = xb[(size_t)c * PLANE];
        t[24] = g_h[v];
        t[25] = 0.f;
        #pragma unroll
        for (int i = 0; i < 16; i++) {
            float v0 = (2 * i < 26) ? t[2 * i] : 0.f;
            float v1 = (2 * i + 1 < 26) ? t[2 * i + 1] : 0.f;
            __nv_bfloat16 h0, l0, h1, l1;
            split_bf(v0, h0, l0); split_bf(v1, h1, l1);
            *(uint32_t*)(sm_ + MO_XH + tid * XP + 4 * i) = pack_bf2(h0, h1);
            *(uint32_t*)(sm_ + MO_XL + tid * XP + 4 * i) = pack_bf2(l0, l1);
        }
    }
    __syncthreads();

    // address helpers
    const int amat = lane >> 3, arow = lane & 7;
    const int bl15 = lane & 15, brow = bl15 & 7, bhf = bl15 >> 3;
    #define AADDR(off, row0, kb, P) \
        (sb + (off) + (uint32_t)(((row0) + arow + (amat & 1) * 8) * (P) + (kb) + (amat >> 1) * 16))
    #define BADDR(off, n0, kb, P) \
        (sb + (off) + (uint32_t)(((n0) + brow) * (P) + (kb) + bhf * 16))

    const int row0 = w * 32;

    // -------- layer A: [32 x 48] = X[32 x 32] @ WaT --------
    float dA[2][6][4];
    #pragma unroll
    for (int m = 0; m < 2; m++)
        #pragma unroll
        for (int n = 0; n < 6; n++)
            #pragma unroll
            for (int c = 0; c < 4; c++) dA[m][n][c] = 0.f;
    {
        uint32_t Ahf[2][2][4], Alf[2][2][4];
        #pragma unroll
        for (int m = 0; m < 2; m++)
            #pragma unroll
            for (int k = 0; k < 2; k++) {
                LDSM4(Ahf[m][k], AADDR(MO_XH, row0 + 16 * m, 32 * k, XP));
                LDSM4(Alf[m][k], AADDR(MO_XL, row0 + 16 * m, 32 * k, XP));
            }
        #pragma unroll
        for (int n = 0; n < 6; n++) {
            uint32_t bh[2][2], bl2[2][2];
            #pragma unroll
            for (int k = 0; k < 2; k++) {
                LDSM2(bh[k],  BADDR(MO_WAH, n * 8, 32 * k, WP));
                LDSM2(bl2[k], BADDR(MO_WAL, n * 8, 32 * k, WP));
            }
            #pragma unroll
            for (int m = 0; m < 2; m++)
                #pragma unroll
                for (int k = 0; k < 2; k++) {
                    MMA16816(dA[m][n], Ahf[m][k], bh[k]);
                    MMA16816(dA[m][n], Ahf[m][k], bl2[k]);
                    MMA16816(dA[m][n], Alf[m][k], bh[k]);
                }
        }
    }
    // bias + relu + split, bounce to X buffer (cols 0..47)
    #pragma unroll
    for (int m = 0; m < 2; m++)
        #pragma unroll
        for (int n = 0; n < 6; n++) {
            float2 bias = *(float2*)(s_ba + n * 8 + 2 * tig);
            float v0 = fmaxf(dA[m][n][0] + bias.x, 0.f);
            float v1 = fmaxf(dA[m][n][1] + bias.y, 0.f);
            float v2 = fmaxf(dA[m][n][2] + bias.x, 0.f);
            float v3 = fmaxf(dA[m][n][3] + bias.y, 0.f);
            int r1 = row0 + 16 * m + gid, r2 = r1 + 8;
            int cb = (n * 8 + 2 * tig) * 2;
            __nv_bfloat16 h0, l0, h1, l1;
            split_bf(v0, h0, l0); split_bf(v1, h1, l1);
            *(uint32_t*)(sm_ + MO_XH + r1 * XP + cb) = pack_bf2(h0, h1);
            *(uint32_t*)(sm_ + MO_XL + r1 * XP + cb) = pack_bf2(l0, l1);
            split_bf(v2, h0, l0); split_bf(v3, h1, l1);
            *(uint32_t*)(sm_ + MO_XH + r2 * XP + cb) = pack_bf2(h0, h1);
            *(uint32_t*)(sm_ + MO_XL + r2 * XP + cb) = pack_bf2(l0, l1);
        }
    __syncwarp();

    // -------- layer B: [32 x 96] = A[32 x 48] @ WbT --------
    float dB[2][12][4];
    #pragma unroll
    for (int m = 0; m < 2; m++)
        #pragma unroll
        for (int n = 0; n < 12; n++)
            #pragma unroll
            for (int c = 0; c < 4; c++) dB[m][n][c] = 0.f;
    {
        uint32_t Ahf[2][3][4], Alf[2][3][4];
        #pragma unroll
        for (int m = 0; m < 2; m++)
            #pragma unroll
            for (int k = 0; k < 3; k++) {
                LDSM4(Ahf[m][k], AADDR(MO_XH, row0 + 16 * m, 32 * k, XP));
                LDSM4(Alf[m][k], AADDR(MO_XL, row0 + 16 * m, 32 * k, XP));
            }
        #pragma unroll
        for (int n = 0; n < 12; n++) {
            uint32_t bh[3][2], bl2[3][2];
            #pragma unroll
            for (int k = 0; k < 3; k++) {
                LDSM2(bh[k],  BADDR(MO_WBH, n * 8, 32 * k, WP));
                LDSM2(bl2[k], BADDR(MO_WBL, n * 8, 32 * k, WP));
            }
            #pragma unroll
            for (int m = 0; m < 2; m++)
                #pragma unroll
                for (int k = 0; k < 3; k++) {
                    MMA16816(dB[m][n], Ahf[m][k], bh[k]);
                    MMA16816(dB[m][n], Ahf[m][k], bl2[k]);
                    MMA16816(dB[m][n], Alf[m][k], bh[k]);
                }
        }
    }
    #pragma unroll
    for (int m = 0; m < 2; m++)
        #pragma unroll
        for (int n = 0; n < 12; n++) {
            float2 bias = *(float2*)(s_bb + n * 8 + 2 * tig);
            float v0 = fmaxf(dB[m][n][0] + bias.x, 0.f);
            float v1 = fmaxf(dB[m][n][1] + bias.y, 0.f);
            float v2 = fmaxf(dB[m][n][2] + bias.x, 0.f);
            float v3 = fmaxf(dB[m][n][3] + bias.y, 0.f);
            int r1 = row0 + 16 * m + gid, r2 = r1 + 8;
            int cb = (n * 8 + 2 * tig) * 2;
            __nv_bfloat16 h0, l0, h1, l1;
            split_bf(v0, h0, l0); split_bf(v1, h1, l1);
            *(uint32_t*)(sm_ + MO_XH + r1 * XP + cb) = pack_bf2(h0, h1);
            *(uint32_t*)(sm_ + MO_XL + r1 * XP + cb) = pack_bf2(l0, l1);
            split_bf(v2, h0, l0); split_bf(v3, h1, l1);
            *(uint32_t*)(sm_ + MO_XH + r2 * XP + cb) = pack_bf2(h0, h1);
            *(uint32_t*)(sm_ + MO_XL + r2 * XP + cb) = pack_bf2(l0, l1);
        }
    __syncwarp();

    // -------- layer C: [32 x 16] = B[32 x 96] @ WcT --------
    float dC[2][2][4];
    #pragma unroll
    for (int m = 0; m < 2; m++)
        #pragma unroll
        for (int n = 0; n < 2; n++)
            #pragma unroll
            for (int c = 0; c < 4; c++) dC[m][n][c] = 0.f;
    {
        uint32_t Ahf[2][6][4], Alf[2][6][4];
        #pragma unroll
        for (int m = 0; m < 2; m++)
            #pragma unroll
            for (int k = 0; k < 6; k++) {
                LDSM4(Ahf[m][k], AADDR(MO_XH, row0 + 16 * m, 32 * k, XP));
                LDSM4(Alf[m][k], AADDR(MO_XL, row0 + 16 * m, 32 * k, XP));
            }
        #pragma unroll
        for (int n = 0; n < 2; n++) {
            #pragma unroll
            for (int k = 0; k < 6; k++) {
                uint32_t bh[2], bl2[2];
                LDSM2(bh,  BADDR(MO_WCH, n * 8, 32 * k, CP));
                LDSM2(bl2, BADDR(MO_WCL, n * 8, 32 * k, CP));
                #pragma unroll
                for (int m = 0; m < 2; m++) {
                    MMA16816(dC[m][n], Ahf[m][k], bh);
                    MMA16816(dC[m][n], Ahf[m][k], bl2);
                    MMA16816(dC[m][n], Alf[m][k], bh);
                }
            }
        }
    }

    // exchange (warp-private rows)
    #pragma unroll
    for (int m = 0; m < 2; m++)
        #pragma unroll
        for (int n = 0; n < 2; n++) {
            int r1 = row0 + 16 * m + gid, r2 = r1 + 8;
            int cc = n * 8 + 2 * tig;
            s_ex[r1 * 18 + cc]     = dC[m][n][0];
            s_ex[r1 * 18 + cc + 1] = dC[m][n][1];
            s_ex[r2 * 18 + cc]     = dC[m][n][2];
            s_ex[r2 * 18 + cc + 1] = dC[m][n][3];
        }
    __syncwarp();

    float o9[9];
    #pragma unroll
    for (int o = 0; o < 9; o++) o9[o] = s_ex[tid * 18 + o] + s_bc[o];

    float xv = x[v];
    float mx = fmaxf(o9[6], fmaxf(o9[7], o9[8]));
    float e0 = expf(o9[6] - mx), e1 = expf(o9[7] - mx), e2 = expf(o9[8] - mx);
    float inv = 1.f / (e0 + e1 + e2);
    float wsm[3] = {e0 * inv, e1 * inv, e2 * inv};

    float p3 = 0.f;
    #pragma unroll
    for (int k = 0; k < 3; k++) {
        float mu = o9[k];
        float scv = o9[3 + k];
        if (scv == 0.f) scv = 1e-9f;
        scv = fabsf(scv);
        float invs = 1.f / scv;
        float l = fabsf(normcdff((xv + 0.5f - mu) * invs)
                      - normcdff((xv - 0.5f - mu) * invs));
        p3 = fmaf(wsm[k], l, p3);
    }

    out[v] = p3;
    #pragma unroll
    for (int o = 0; o < 9; o++)
        out[(size_t)VOX + (size_t)o * VOX + v] = o9[o];
    #undef AADDR
    #undef BADDR
}

extern "C" void kernel_launch(void* const* d_in, const int* in_sizes, int n_in,
                              void* d_out, int out_size) {
    const float* x     = (const float*)d_in[0];
    const float* hyper = (const float*)d_in[1];
    const float* W3    = (const float*)d_in[2];
    const float* b3    = (const float*)d_in[3];
    const float* W1    = (const float*)d_in[4];
    const float* b1    = (const float*)d_in[5];
    const float* Wa    = (const float*)d_in[6];
    const float* ba    = (const float*)d_in[7];
    const float* Wb    = (const float*)d_in[8];
    const float* bb    = (const float*)d_in[9];
    const float* Wc    = (const float*)d_in[10];
    const float* bc    = (const float*)d_in[11];
    float* out = (float*)d_out;

    cudaFuncSetAttribute(conv3d_kernel,
                         cudaFuncAttributeMaxDynamicSharedMemorySize, K2_SMEM);
    cudaFuncSetAttribute(mlp_mma_kernel,
                         cudaFuncAttributeMaxDynamicSharedMemorySize, MO_SMEM);

    pack_kernel<<<128, 256>>>(W3, W1);
    conv2d_kernel<<<288, 192>>>(hyper, b3);
    conv3d_kernel<<<1152, 256, K2_SMEM>>>(x, b1);
    mlp_mma_kernel<<<VOX / 128, 128, MO_SMEM>>>(x, Wa, ba, Wb, bb, Wc, bc, out);
}

// round 9
// speedup vs baseline: 1.3278x; 1.0774x over previous
#include <cuda_runtime.h>
#include <cuda_bf16.h>
#include <cmath>
#include <cstring>
#include <cstdint>

namespace {
constexpr int D = 192, H = 48, W = 48, PLANE = 2304, VOX = 442368;

// ---- pack buffer layout (float offsets) ----
constexpr int PK_W3 = 0,  SZ_W3 = 663552;     // conv2d weights [ic384][t9][dp96][2]
constexpr int PK_WT = 663552;                  // conv3d bf16 weight image (hi, then lo)
constexpr int WT_U32_HALF = 9504;              // 264 rows x 36 u32 (pitch 144B)

// ---- conv3d mma kernel smem (bytes) ----
constexpr int C_XW = 0;            // 6 x 16 x 64 f32           = 24576
constexpr int C_AH = 24576;        // 384 rows x 144B           = 55296
constexpr int C_AL = 79872;        // 55296
constexpr int C_WH = 135168;       // 264 rows x 144B           = 38016
constexpr int C_WL = 173184;       // 38016
constexpr int C_SMEM = 211200;

// ---- mlp mma kernel: smem byte offsets (R8-validated) ----
constexpr int XP = 208;
constexpr int WP = 112;
constexpr int CP = 208;
constexpr int MO_XH  = 0;
constexpr int MO_XL  = 26624;
constexpr int MO_WAH = 53248;
constexpr int MO_WAL = 58624;
constexpr int MO_WBH = 64000;
constexpr int MO_WBL = 74752;
constexpr int MO_WCH = 85504;
constexpr int MO_WCL = 88832;
constexpr int MO_EX  = 92160;
constexpr int MO_BA  = 101376;
constexpr int MO_BB  = 101568;
constexpr int MO_BC  = 101952;
constexpr int MO_SMEM = 102016;
}

__device__ __align__(16) float g_pack[689680];
__device__ float g_h[VOX];
__device__ float g_x1[(size_t)24 * VOX];

// ---- f32x2 helpers (conv2d kernel) ----
__device__ __forceinline__ unsigned long long splat2(float v) {
    unsigned long long r; asm("mov.b64 %0, {%1, %1};" : "=l"(r) : "f"(v)); return r;
}
__device__ __forceinline__ unsigned long long pack2(float a, float b) {
    unsigned long long r; asm("mov.b64 %0, {%1, %2};" : "=l"(r) : "f"(a), "f"(b)); return r;
}
__device__ __forceinline__ float2 unpack2(unsigned long long v) {
    float2 f; asm("mov.b64 {%0, %1}, %2;" : "=f"(f.x), "=f"(f.y) : "l"(v)); return f;
}
__device__ __forceinline__ void fma2(unsigned long long& a, unsigned long long w,
                                     unsigned long long x) {
    asm("fma.rn.f32x2 %0, %1, %2, %0;" : "+l"(a) : "l"(w), "l"(x));
}

// ---- mma.sync helpers (validated R8) ----
__device__ __forceinline__ uint32_t smem_u32(const void* p) {
    uint32_t a;
    asm("{ .reg .u64 t; cvta.to.shared.u64 t, %1; cvt.u32.u64 %0, t; }"
        : "=r"(a) : "l"(p));
    return a;
}
#define LDSM4(r, addr) \
    asm volatile("ldmatrix.sync.aligned.m8n8.x4.shared.b16 {%0,%1,%2,%3}, [%4];" \
        : "=r"((r)[0]), "=r"((r)[1]), "=r"((r)[2]), "=r"((r)[3]) : "r"(addr))
#define LDSM2(r, addr) \
    asm volatile("ldmatrix.sync.aligned.m8n8.x2.shared.b16 {%0,%1}, [%2];" \
        : "=r"((r)[0]), "=r"((r)[1]) : "r"(addr))
#define MMA16816(d, a, b) \
    asm volatile("mma.sync.aligned.m16n8k16.row.col.f32.bf16.bf16.f32 " \
        "{%0,%1,%2,%3}, {%4,%5,%6,%7}, {%8,%9}, {%0,%1,%2,%3};" \
        : "+f"((d)[0]), "+f"((d)[1]), "+f"((d)[2]), "+f"((d)[3]) \
        : "r"((a)[0]), "r"((a)[1]), "r"((a)[2]), "r"((a)[3]), \
          "r"((b)[0]), "r"((b)[1]))

__device__ __forceinline__ void split_bf(float v, __nv_bfloat16& h, __nv_bfloat16& l) {
    h = __float2bfloat16(v);
    l = __float2bfloat16(v - __bfloat162float(h));
}
__device__ __forceinline__ uint32_t pack_bf2(__nv_bfloat16 a, __nv_bfloat16 b) {
    __nv_bfloat162 t; t.x = a; t.y = b;
    uint32_t u; memcpy(&u, &t, 4); return u;
}

// =============== K0: pack weights ===============
__global__ void pack_kernel(const float* __restrict__ W3, const float* __restrict__ W1) {
    int nt = gridDim.x * blockDim.x, tid = blockIdx.x * blockDim.x + threadIdx.x;
    // conv2d W3 d-pair pack
    for (int i = tid; i < SZ_W3; i += nt) {
        int par = i & 1, q = i >> 1;
        int dp = q % 96; q /= 96;
        int t = q % 9;   int ic = q / 9;
        g_pack[PK_W3 + i] = W3[((size_t)(dp * 2 + par) * 384 + ic) * 9 + t];
    }
    // conv3d bf16 weight image: rows (kw*24 + c), 36 u32 cols (k pairs), hi then lo
    uint32_t* wt = (uint32_t*)(g_pack + PK_WT);
    for (int j = tid; j < 2 * WT_U32_HALF; j += nt) {
        int half = j / WT_U32_HALF, jj = j % WT_U32_HALF;
        int row = jj / 36, col = jj % 36;
        int kw = row / 24, c = row % 24;
        float v[2];
        #pragma unroll
        for (int s = 0; s < 2; s++) {
            int k = col * 2 + s;
            float val = 0.f;
            if (k <= 60) {
                int kd = k / 11, kh = k % 11;
                int flat = kd * 121 + kh * 11 + kw;
                if (flat < 665) val = W1[c * 1331 + flat];
            }
            v[s] = val;
        }
        __nv_bfloat16 h0, l0, h1, l1;
        split_bf(v[0], h0, l0); split_bf(v[1], h1, l1);
        wt[j] = half ? pack_bf2(l0, l1) : pack_bf2(h0, h1);
    }
}

// =============== K1: conv2d (unchanged) ===============
__global__ __launch_bounds__(192, 2)
void conv2d_kernel(const float* __restrict__ hyper, const float* __restrict__ b3) {
    __shared__ float s_hyp[16 * 520];
    int bx = blockIdx.x;
    int dg = bx % 48, rt = bx / 48;
    int r0 = rt * 8;
    int tid = threadIdx.x;
    int dhalf = tid / 96, r8 = (tid % 96) / 12, grp = tid % 12, x0 = grp * 4;
    int dp = dg * 2 + dhalf, d0 = dp * 2;

    unsigned long long acc[4];
    {
        unsigned long long bv = pack2(b3[d0], b3[d0 + 1]);
        acc[0] = bv; acc[1] = bv; acc[2] = bv; acc[3] = bv;
    }
    const unsigned long long* w3u = (const unsigned long long*)g_pack + (PK_W3 / 2);

    for (int icb = 0; icb < 384; icb += 16) {
        for (int i = tid; i < 16 * 520; i += 192) {
            int icl = i / 520, rr = (i % 520) / 52, cc = i % 52;
            int grow = r0 - 1 + rr, gcol = cc - 1;
            float v = 0.f;
            if (grow >= 0 && grow < 48 && gcol >= 0 && gcol < 48)
                v = hyper[(size_t)(icb + icl) * PLANE + grow * 48 + gcol];
            s_hyp[i] = v;
        }
        __syncthreads();
        #pragma unroll 2
        for (int icl = 0; icl < 16; icl++) {
            const float* hw = s_hyp + icl * 520 + r8 * 52 + x0;
            unsigned long long ss[3][6];
            #pragma unroll
            for (int ky = 0; ky < 3; ky++) {
                const float* row = hw + ky * 52;
                float4 a = *(const float4*)row;
                float2 b = *(const float2*)(row + 4);
                ss[ky][0] = splat2(a.x); ss[ky][1] = splat2(a.y); ss[ky][2] = splat2(a.z);
                ss[ky][3] = splat2(a.w); ss[ky][4] = splat2(b.x); ss[ky][5] = splat2(b.y);
            }
            const unsigned long long* wrow = w3u + (size_t)(icb + icl) * 9 * 96 + dp;
            #pragma unroll
            for (int ky = 0; ky < 3; ky++)
                #pragma unroll
                for (int kx = 0; kx < 3; kx++) {
                    unsigned long long wv = wrow[(ky * 3 + kx) * 96];
                    fma2(acc[0], wv, ss[ky][kx + 0]);
                    fma2(acc[1], wv, ss[ky][kx + 1]);
                    fma2(acc[2], wv, ss[ky][kx + 2]);
                    fma2(acc[3], wv, ss[ky][kx + 3]);
                }
        }
        __syncthreads();
    }
    float2 v0 = unpack2(acc[0]), v1 = unpack2(acc[1]);
    float2 v2 = unpack2(acc[2]), v3 = unpack2(acc[3]);
    int gp = (r0 + r8) * 48 + x0;
    *(float4*)(g_h + (size_t)d0 * PLANE + gp)       = make_float4(v0.x, v1.x, v2.x, v3.x);
    *(float4*)(g_h + (size_t)(d0 + 1) * PLANE + gp) = make_float4(v0.y, v1.y, v2.y, v3.y);
}

// =============== K2: masked conv3d via mma.sync implicit GEMM ===============
// CTA = (d, 6-row block). A[(hr,wx)][k=(kd*11+kh)] = x[d-5+kd][h0+hr-5+kh][wx-5].
// For each kw: GEMM rows at m_ext = hr*64 + w + kw; acc accumulates over (kw,k16).
__global__ __launch_bounds__(192)
void conv3d_mma_kernel(const float* __restrict__ x, const float* __restrict__ b1) {
    extern __shared__ char cs[];
    const uint32_t sb = smem_u32(cs);
    const int tid = threadIdx.x;
    const int lane = tid & 31, wrp = tid >> 5;          // 6 warps; warp = h-row
    const int gid = lane >> 2, tig = lane & 3;
    const int amat = lane >> 3, arow = lane & 7;
    const int bl15 = lane & 15, brow = bl15 & 7, bhf = bl15 >> 3;

    const int d = blockIdx.x >> 3, hb = blockIdx.x & 7;
    const int h0 = hb * 6;

    // stage x window: 6 slices x 16 rows x 64 wx (zero-padded)
    float* s_xw = (float*)(cs + C_XW);
    for (int i = tid; i < 6 * 16 * 64; i += 192) {
        int s = i >> 10, rem = i & 1023;
        int r = rem >> 6, wxx = rem & 63;
        int sd = d - 5 + s, gh = h0 - 5 + r, gw = wxx - 5;
        float v = 0.f;
        if (sd >= 0 && gh >= 0 && gh < 48 && gw >= 0 && gw < 48)
            v = x[(size_t)sd * PLANE + gh * 48 + gw];
        s_xw[i] = v;
    }
    // copy pre-split weight image (WH then WL contiguous)
    {
        float4* wdst = (float4*)(cs + C_WH);
        const float4* wsrc = (const float4*)(g_pack + PK_WT);
        for (int i = tid; i < (2 * WT_U32_HALF) / 4; i += 192) wdst[i] = wsrc[i];
    }
    __syncthreads();

    // build A hi/lo: 384 rows x 32 k-pairs, pitch 144B
    #pragma unroll
    for (int i = 0; i < 32; i++) {
        const int k0 = 2 * i, k1 = 2 * i + 1;
        #pragma unroll
        for (int rr = 0; rr < 2; rr++) {
            int r = tid + rr * 192;
            int hr = r >> 6, wx = r & 63;
            float v0 = 0.f, v1 = 0.f;
            if (k0 <= 60) v0 = s_xw[((k0 / 11) * 16 + hr + (k0 % 11)) * 64 + wx];
            if (k1 <= 60) v1 = s_xw[((k1 / 11) * 16 + hr + (k1 % 11)) * 64 + wx];
            __nv_bfloat16 h0b, l0b, h1b, l1b;
            split_bf(v0, h0b, l0b); split_bf(v1, h1b, l1b);
            *(uint32_t*)(cs + C_AH + r * 144 + i * 4) = pack_bf2(h0b, h1b);
            *(uint32_t*)(cs + C_AL + r * 144 + i * 4) = pack_bf2(l0b, l1b);
        }
    }
    __syncthreads();

    // bias values for this thread's columns
    float bb1[3][2];
    #pragma unroll
    for (int n = 0; n < 3; n++) {
        int c0 = n * 8 + 2 * tig;
        bb1[n][0] = b1[c0]; bb1[n][1] = b1[c0 + 1];
    }

    float acc[3][3][4];   // [m-tile][n-tile][frag]
    #pragma unroll
    for (int mt = 0; mt < 3; mt++)
        #pragma unroll
        for (int n = 0; n < 3; n++)
            #pragma unroll
            for (int c = 0; c < 4; c++) acc[mt][n][c] = 0.f;

    #pragma unroll 1
    for (int kw = 0; kw < 11; kw++) {
        #pragma unroll
        for (int k16 = 0; k16 < 4; k16++) {
            uint32_t bh[3][2], bl[3][2];
            #pragma unroll
            for (int n = 0; n < 3; n++) {
                uint32_t boff = (uint32_t)((kw * 24 + n * 8 + brow) * 144 + k16 * 32 + bhf * 16);
                LDSM2(bh[n], sb + C_WH + boff);
                LDSM2(bl[n], sb + C_WL + boff);
            }
            #pragma unroll
            for (int mt = 0; mt < 3; mt++) {
                int rowbase = wrp * 64 + mt * 16 + kw;
                uint32_t aoff = (uint32_t)((rowbase + arow + (amat & 1) * 8) * 144
                                           + k16 * 32 + (amat >> 1) * 16);
                uint32_t Ah[4], Al[4];
                LDSM4(Ah, sb + C_AH + aoff);
                LDSM4(Al, sb + C_AL + aoff);
                #pragma unroll
                for (int n = 0; n < 3; n++) {
                    MMA16816(acc[mt][n], Ah, bh[n]);
                    MMA16816(acc[mt][n], Ah, bl[n]);
                    MMA16816(acc[mt][n], Al, bh[n]);
                }
            }
        }
    }

    // epilogue: bias + store to g_x1 (h row = h0 + wrp)
    const int h_glob = h0 + wrp;
    #pragma unroll
    for (int mt = 0; mt < 3; mt++) {
        int px0 = mt * 16 + gid, px1 = px0 + 8;
        #pragma unroll
        for (int n = 0; n < 3; n++) {
            int c0 = n * 8 + 2 * tig;
            float* o0 = g_x1 + ((size_t)d * 24 + c0) * PLANE + h_glob * 48;
            float* o1 = g_x1 + ((size_t)d * 24 + c0 + 1) * PLANE + h_glob * 48;
            o0[px0] = acc[mt][n][0] + bb1[n][0];
            o1[px0] = acc[mt][n][1] + bb1[n][1];
            o0[px1] = acc[mt][n][2] + bb1[n][0];
            o1[px1] = acc[mt][n][3] + bb1[n][1];
        }
    }
}

// =============== K3: MLP via mma.sync (unchanged R8, validated) ===============
__global__ __launch_bounds__(128)
void mlp_mma_kernel(const float* __restrict__ x,
                    const float* __restrict__ Wa, const float* __restrict__ ba,
                    const float* __restrict__ Wb, const float* __restrict__ bb,
                    const float* __restrict__ Wc, const float* __restrict__ bc,
                    float* __restrict__ out)
{
    extern __shared__ char sm_[];
    const uint32_t sb = smem_u32(sm_);
    const int tid = threadIdx.x;
    const int lane = tid & 31, w = tid >> 5;
    const int gid = lane >> 2, tig = lane & 3;

    float* s_ba = (float*)(sm_ + MO_BA);
    float* s_bb = (float*)(sm_ + MO_BB);
    float* s_bc = (float*)(sm_ + MO_BC);
    float* s_ex = (float*)(sm_ + MO_EX);

    for (int i = tid; i < 48; i += 128) s_ba[i] = ba[i];
    for (int i = tid; i < 96; i += 128) s_bb[i] = bb[i];
    for (int i = tid; i < 16; i += 128) s_bc[i] = (i < 9) ? bc[i] : 0.f;

    for (int u = tid; u < 48; u += 128) {
        #pragma unroll
        for (int i = 0; i < 16; i++) {
            int c0 = 2 * i, c1 = 2 * i + 1;
            float v0 = (c0 < 25) ? Wa[u * 25 + c0] : 0.f;
            float v1 = (c1 < 25) ? Wa[u * 25 + c1] : 0.f;
            __nv_bfloat16 h0, l0, h1, l1;
            split_bf(v0, h0, l0); split_bf(v1, h1, l1);
            *(uint32_t*)(sm_ + MO_WAH + u * WP + 4 * i) = pack_bf2(h0, h1);
            *(uint32_t*)(sm_ + MO_WAL + u * WP + 4 * i) = pack_bf2(l0, l1);
        }
    }
    for (int u = tid; u < 96; u += 128) {
        #pragma unroll
        for (int i = 0; i < 24; i++) {
            float v0 = Wb[u * 48 + 2 * i], v1 = Wb[u * 48 + 2 * i + 1];
            __nv_bfloat16 h0, l0, h1, l1;
            split_bf(v0, h0, l0); split_bf(v1, h1, l1);
            *(uint32_t*)(sm_ + MO_WBH + u * WP + 4 * i) = pack_bf2(h0, h1);
            *(uint32_t*)(sm_ + MO_WBL + u * WP + 4 * i) = pack_bf2(l0, l1);
        }
    }
    for (int u = tid; u < 16; u += 128) {
        #pragma unroll 8
        for (int i = 0; i < 48; i++) {
            float v0 = (u < 9) ? Wc[u * 96 + 2 * i] : 0.f;
            float v1 = (u < 9) ? Wc[u * 96 + 2 * i + 1] : 0.f;
            __nv_bfloat16 h0, l0, h1, l1;
            split_bf(v0, h0, l0); split_bf(v1, h1, l1);
            *(uint32_t*)(sm_ + MO_WCH + u * CP + 4 * i) = pack_bf2(h0, h1);
            *(uint32_t*)(sm_ + MO_WCL + u * CP + 4 * i) = pack_bf2(l0, l1);
        }
    }

    const int v = blockIdx.x * 128 + tid;
    const int dd = v / PLANE, p = v % PLANE;
    {
        const float* xb = g_x1 + (size_t)dd * 24 * PLANE + p;
        float t[26];
        #pragma unroll
        for (int c = 0; c < 24; c++) t[c] = xb[(size_t)c * PLANE];
        t[24] = g_h[v];
        t[25] = 0.f;
        #pragma unroll
        for (int i = 0; i < 16; i++) {
            float v0 = (2 * i < 26) ? t[2 * i] : 0.f;
            float v1 = (2 * i + 1 < 26) ? t[2 * i + 1] : 0.f;
            __nv_bfloat16 h0, l0, h1, l1;
            split_bf(v0, h0, l0); split_bf(v1, h1, l1);
            *(uint32_t*)(sm_ + MO_XH + tid * XP + 4 * i) = pack_bf2(h0, h1);
            *(uint32_t*)(sm_ + MO_XL + tid * XP + 4 * i) = pack_bf2(l0, l1);
        }
    }
    __syncthreads();

    const int amat = lane >> 3, arow = lane & 7;
    const int bl15 = lane & 15, brow = bl15 & 7, bhf = bl15 >> 3;
    #define AADDR(off, row0, kb, P) \
        (sb + (off) + (uint32_t)(((row0) + arow + (amat & 1) * 8) * (P) + (kb) + (amat >> 1) * 16))
    #define BADDR(off, n0, kb, P) \
        (sb + (off) + (uint32_t)(((n0) + brow) * (P) + (kb) + bhf * 16))

    const int row0 = w * 32;

    float dA[2][6][4];
    #pragma unroll
    for (int m = 0; m < 2; m++)
        #pragma unroll
        for (int n = 0; n < 6; n++)
            #pragma unroll
            for (int c = 0; c < 4; c++) dA[m][n][c] = 0.f;
    {
        uint32_t Ahf[2][2][4], Alf[2][2][4];
        #pragma unroll
        for (int m = 0; m < 2; m++)
            #pragma unroll
            for (int k = 0; k < 2; k++) {
                LDSM4(Ahf[m][k], AADDR(MO_XH, row0 + 16 * m, 32 * k, XP));
                LDSM4(Alf[m][k], AADDR(MO_XL, row0 + 16 * m, 32 * k, XP));
            }
        #pragma unroll
        for (int n = 0; n < 6; n++) {
            uint32_t bh[2][2], bl2[2][2];
            #pragma unroll
            for (int k = 0; k < 2; k++) {
                LDSM2(bh[k],  BADDR(MO_WAH, n * 8, 32 * k, WP));
                LDSM2(bl2[k], BADDR(MO_WAL, n * 8, 32 * k, WP));
            }
            #pragma unroll
            for (int m = 0; m < 2; m++)
                #pragma unroll
                for (int k = 0; k < 2; k++) {
                    MMA16816(dA[m][n], Ahf[m][k], bh[k]);
                    MMA16816(dA[m][n], Ahf[m][k], bl2[k]);
                    MMA16816(dA[m][n], Alf[m][k], bh[k]);
                }
        }
    }
    #pragma unroll
    for (int m = 0; m < 2; m++)
        #pragma unroll
        for (int n = 0; n < 6; n++) {
            float2 bias = *(float2*)(s_ba + n * 8 + 2 * tig);
            float v0 = fmaxf(dA[m][n][0] + bias.x, 0.f);
            float v1 = fmaxf(dA[m][n][1] + bias.y, 0.f);
            float v2 = fmaxf(dA[m][n][2] + bias.x, 0.f);
            float v3 = fmaxf(dA[m][n][3] + bias.y, 0.f);
            int r1 = row0 + 16 * m + gid, r2 = r1 + 8;
            int cb = (n * 8 + 2 * tig) * 2;
            __nv_bfloat16 h0, l0, h1, l1;
            split_bf(v0, h0, l0); split_bf(v1, h1, l1);
            *(uint32_t*)(sm_ + MO_XH + r1 * XP + cb) = pack_bf2(h0, h1);
            *(uint32_t*)(sm_ + MO_XL + r1 * XP + cb) = pack_bf2(l0, l1);
            split_bf(v2, h0, l0); split_bf(v3, h1, l1);
            *(uint32_t*)(sm_ + MO_XH + r2 * XP + cb) = pack_bf2(h0, h1);
            *(uint32_t*)(sm_ + MO_XL + r2 * XP + cb) = pack_bf2(l0, l1);
        }
    __syncwarp();

    float dB[2][12][4];
    #pragma unroll
    for (int m = 0; m < 2; m++)
        #pragma unroll
        for (int n = 0; n < 12; n++)
            #pragma unroll
            for (int c = 0; c < 4; c++) dB[m][n][c] = 0.f;
    {
        uint32_t Ahf[2][3][4], Alf[2][3][4];
        #pragma unroll
        for (int m = 0; m < 2; m++)
            #pragma unroll
            for (int k = 0; k < 3; k++) {
                LDSM4(Ahf[m][k], AADDR(MO_XH, row0 + 16 * m, 32 * k, XP));
                LDSM4(Alf[m][k], AADDR(MO_XL, row0 + 16 * m, 32 * k, XP));
            }
        #pragma unroll
        for (int n = 0; n < 12; n++) {
            uint32_t bh[3][2], bl2[3][2];
            #pragma unroll
            for (int k = 0; k < 3; k++) {
                LDSM2(bh[k],  BADDR(MO_WBH, n * 8, 32 * k, WP));
                LDSM2(bl2[k], BADDR(MO_WBL, n * 8, 32 * k, WP));
            }
            #pragma unroll
            for (int m = 0; m < 2; m++)
                #pragma unroll
                for (int k = 0; k < 3; k++) {
                    MMA16816(dB[m][n], Ahf[m][k], bh[k]);
                    MMA16816(dB[m][n], Ahf[m][k], bl2[k]);
                    MMA16816(dB[m][n], Alf[m][k], bh[k]);
                }
        }
    }
    #pragma unroll
    for (int m = 0; m < 2; m++)
        #pragma unroll
        for (int n = 0; n < 12; n++) {
            float2 bias = *(float2*)(s_bb + n * 8 + 2 * tig);
            float v0 = fmaxf(dB[m][n][0] + bias.x, 0.f);
            float v1 = fmaxf(dB[m][n][1] + bias.y, 0.f);
            float v2 = fmaxf(dB[m][n][2] + bias.x, 0.f);
            float v3 = fmaxf(dB[m][n][3] + bias.y, 0.f);
            int r1 = row0 + 16 * m + gid, r2 = r1 + 8;
            int cb = (n * 8 + 2 * tig) * 2;
            __nv_bfloat16 h0, l0, h1, l1;
            split_bf(v0, h0, l0); split_bf(v1, h1, l1);
            *(uint32_t*)(sm_ + MO_XH + r1 * XP + cb) = pack_bf2(h0, h1);
            *(uint32_t*)(sm_ + MO_XL + r1 * XP + cb) = pack_bf2(l0, l1);
            split_bf(v2, h0, l0); split_bf(v3, h1, l1);
            *(uint32_t*)(sm_ + MO_XH + r2 * XP + cb) = pack_bf2(h0, h1);
            *(uint32_t*)(sm_ + MO_XL + r2 * XP + cb) = pack_bf2(l0, l1);
        }
    __syncwarp();

    float dC[2][2][4];
    #pragma unroll
    for (int m = 0; m < 2; m++)
        #pragma unroll
        for (int n = 0; n < 2; n++)
            #pragma unroll
            for (int c = 0; c < 4; c++) dC[m][n][c] = 0.f;
    {
        uint32_t Ahf[2][6][4], Alf[2][6][4];
        #pragma unroll
        for (int m = 0; m < 2; m++)
            #pragma unroll
            for (int k = 0; k < 6; k++) {
                LDSM4(Ahf[m][k], AADDR(MO_XH, row0 + 16 * m, 32 * k, XP));
                LDSM4(Alf[m][k], AADDR(MO_XL, row0 + 16 * m, 32 * k, XP));
            }
        #pragma unroll
        for (int n = 0; n < 2; n++) {
            #pragma unroll
            for (int k = 0; k < 6; k++) {
                uint32_t bh[2], bl2[2];
                LDSM2(bh,  BADDR(MO_WCH, n * 8, 32 * k, CP));
                LDSM2(bl2, BADDR(MO_WCL, n * 8, 32 * k, CP));
                #pragma unroll
                for (int m = 0; m < 2; m++) {
                    MMA16816(dC[m][n], Ahf[m][k], bh);
                    MMA16816(dC[m][n], Ahf[m][k], bl2);
                    MMA16816(dC[m][n], Alf[m][k], bh);
                }
            }
        }
    }

    #pragma unroll
    for (int m = 0; m < 2; m++)
        #pragma unroll
        for (int n = 0; n < 2; n++) {
            int r1 = row0 + 16 * m + gid, r2 = r1 + 8;
            int cc = n * 8 + 2 * tig;
            s_ex[r1 * 18 + cc]     = dC[m][n][0];
            s_ex[r1 * 18 + cc + 1] = dC[m][n][1];
            s_ex[r2 * 18 + cc]     = dC[m][n][2];
            s_ex[r2 * 18 + cc + 1] = dC[m][n][3];
        }
    __syncwarp();

    float o9[9];
    #pragma unroll
    for (int o = 0; o < 9; o++) o9[o] = s_ex[tid * 18 + o] + s_bc[o];

    float xv = x[v];
    float mx = fmaxf(o9[6], fmaxf(o9[7], o9[8]));
    float e0 = expf(o9[6] - mx), e1 = expf(o9[7] - mx), e2 = expf(o9[8] - mx);
    float inv = 1.f / (e0 + e1 + e2);
    float wsm[3] = {e0 * inv, e1 * inv, e2 * inv};

    float p3 = 0.f;
    #pragma unroll
    for (int k = 0; k < 3; k++) {
        float mu = o9[k];
        float scv = o9[3 + k];
        if (scv == 0.f) scv = 1e-9f;
        scv = fabsf(scv);
        float invs = 1.f / scv;
        float l = fabsf(normcdff((xv + 0.5f - mu) * invs)
                      - normcdff((xv - 0.5f - mu) * invs));
        p3 = fmaf(wsm[k], l, p3);
    }

    out[v] = p3;
    #pragma unroll
    for (int o = 0; o < 9; o++)
        out[(size_t)VOX + (size_t)o * VOX + v] = o9[o];
    #undef AADDR
    #undef BADDR
}

extern "C" void kernel_launch(void* const* d_in, const int* in_sizes, int n_in,
                              void* d_out, int out_size) {
    const float* x     = (const float*)d_in[0];
    const float* hyper = (const float*)d_in[1];
    const float* W3    = (const float*)d_in[2];
    const float* b3    = (const float*)d_in[3];
    const float* W1    = (const float*)d_in[4];
    const float* b1    = (const float*)d_in[5];
    const float* Wa    = (const float*)d_in[6];
    const float* ba    = (const float*)d_in[7];
    const float* Wb    = (const float*)d_in[8];
    const float* bb    = (const float*)d_in[9];
    const float* Wc    = (const float*)d_in[10];
    const float* bc    = (const float*)d_in[11];
    float* out = (float*)d_out;

    cudaFuncSetAttribute(conv3d_mma_kernel,
                         cudaFuncAttributeMaxDynamicSharedMemorySize, C_SMEM);
    cudaFuncSetAttribute(mlp_mma_kernel,
                         cudaFuncAttributeMaxDynamicSharedMemorySize, MO_SMEM);

    pack_kernel<<<128, 256>>>(W3, W1);
    conv2d_kernel<<<288, 192>>>(hyper, b3);
    conv3d_mma_kernel<<<192 * 8, 192, C_SMEM>>>(x, b1);
    mlp_mma_kernel<<<VOX / 128, 128, MO_SMEM>>>(x, Wa, ba, Wb, bb, Wc, bc, out);
}

// round 10
// speedup vs baseline: 2.0254x; 1.5254x over previous
#include <cuda_runtime.h>
#include <cuda_bf16.h>
#include <cmath>
#include <cstring>
#include <cstdint>

namespace {
constexpr int D = 192, H = 48, W = 48, PLANE = 2304, VOX = 442368;
constexpr int KK = 3456;              // conv2d GEMM K = 384 ic * 9 taps
constexpr int KSPLIT = 4, KSEG = 864; // per-split K

// ---- pack buffer (float offsets) : conv3d weight image only ----
constexpr int PK_WT = 663552;
constexpr int WT_U32_HALF = 9504;     // 264 rows x 36 u32 (pitch 144B)

// ---- conv3d mma smem (bytes) ----
constexpr int C_XW = 0;
constexpr int C_AH = 24576;
constexpr int C_AL = 79872;
constexpr int C_WH = 135168;
constexpr int C_WL = 173184;
constexpr int C_SMEM = 211200;

// ---- conv2d mma smem (bytes): pitch 112B (96B data + 16 pad) ----
constexpr int G_AH = 0;                // 64 x 112
constexpr int G_AL = 7168;
constexpr int G_BH = 14336;            // 192 x 112
constexpr int G_BL = 35840;
constexpr int G_SMEM = 57344;

// ---- mlp mma smem byte offsets (R8-validated) ----
constexpr int XP = 208;
constexpr int WP = 112;
constexpr int CP = 208;
constexpr int MO_XH  = 0;
constexpr int MO_XL  = 26624;
constexpr int MO_WAH = 53248;
constexpr int MO_WAL = 58624;
constexpr int MO_WBH = 64000;
constexpr int MO_WBL = 74752;
constexpr int MO_WCH = 85504;
constexpr int MO_WCL = 88832;
constexpr int MO_EX  = 92160;
constexpr int MO_BA  = 101376;
constexpr int MO_BB  = 101568;
constexpr int MO_BC  = 101952;
constexpr int MO_SMEM = 102016;
}

__device__ __align__(16) float g_pack[689680];
__device__ float g_x1[(size_t)24 * VOX];
__device__ __align__(16) __nv_bfloat16 g_imH[(size_t)PLANE * KK];
__device__ __align__(16) __nv_bfloat16 g_imL[(size_t)PLANE * KK];
__device__ __align__(16) __nv_bfloat16 g_w3H[(size_t)D * KK];
__device__ __align__(16) __nv_bfloat16 g_w3L[(size_t)D * KK];
__device__ float g_part[(size_t)KSPLIT * VOX];

// ---- mma.sync helpers (validated) ----
__device__ __forceinline__ uint32_t smem_u32(const void* p) {
    uint32_t a;
    asm("{ .reg .u64 t; cvta.to.shared.u64 t, %1; cvt.u32.u64 %0, t; }"
        : "=r"(a) : "l"(p));
    return a;
}
#define LDSM4(r, addr) \
    asm volatile("ldmatrix.sync.aligned.m8n8.x4.shared.b16 {%0,%1,%2,%3}, [%4];" \
        : "=r"((r)[0]), "=r"((r)[1]), "=r"((r)[2]), "=r"((r)[3]) : "r"(addr))
#define LDSM2(r, addr) \
    asm volatile("ldmatrix.sync.aligned.m8n8.x2.shared.b16 {%0,%1}, [%2];" \
        : "=r"((r)[0]), "=r"((r)[1]) : "r"(addr))
#define MMA16816(d, a, b) \
    asm volatile("mma.sync.aligned.m16n8k16.row.col.f32.bf16.bf16.f32 " \
        "{%0,%1,%2,%3}, {%4,%5,%6,%7}, {%8,%9}, {%0,%1,%2,%3};" \
        : "+f"((d)[0]), "+f"((d)[1]), "+f"((d)[2]), "+f"((d)[3]) \
        : "r"((a)[0]), "r"((a)[1]), "r"((a)[2]), "r"((a)[3]), \
          "r"((b)[0]), "r"((b)[1]))

__device__ __forceinline__ void split_bf(float v, __nv_bfloat16& h, __nv_bfloat16& l) {
    h = __float2bfloat16(v);
    l = __float2bfloat16(v - __bfloat162float(h));
}
__device__ __forceinline__ uint32_t pack_bf2(__nv_bfloat16 a, __nv_bfloat16 b) {
    __nv_bfloat162 t; t.x = a; t.y = b;
    uint32_t u; memcpy(&u, &t, 4); return u;
}

// =============== K0a: pack conv3d weight image + conv2d weight split ===============
__global__ void pack_kernel(const float* __restrict__ W3, const float* __restrict__ W1) {
    int nt = gridDim.x * blockDim.x, tid = blockIdx.x * blockDim.x + threadIdx.x;
    // conv3d bf16 weight image
    uint32_t* wt = (uint32_t*)(g_pack + PK_WT);
    for (int j = tid; j < 2 * WT_U32_HALF; j += nt) {
        int half = j / WT_U32_HALF, jj = j % WT_U32_HALF;
        int row = jj / 36, col = jj % 36;
        int kw = row / 24, c = row % 24;
        float v[2];
        #pragma unroll
        for (int s = 0; s < 2; s++) {
            int k = col * 2 + s;
            float val = 0.f;
            if (k <= 60) {
                int kd = k / 11, kh = k % 11;
                int flat = kd * 121 + kh * 11 + kw;
                if (flat < 665) val = W1[c * 1331 + flat];
            }
            v[s] = val;
        }
        __nv_bfloat16 h0, l0, h1, l1;
        split_bf(v[0], h0, l0); split_bf(v[1], h1, l1);
        wt[j] = half ? pack_bf2(l0, l1) : pack_bf2(h0, h1);
    }
    // conv2d weights: g_w3[d][kk], kk = ic*9 + t
    for (int i = tid; i < D * KK; i += nt) {
        int kk = i % KK, d = i / KK;
        int ic = kk / 9, t = kk % 9;
        float v = W3[((size_t)d * 384 + ic) * 9 + t];
        __nv_bfloat16 hv, lv; split_bf(v, hv, lv);
        g_w3H[i] = hv; g_w3L[i] = lv;
    }
}

// =============== K0b: im2col of hyper, split bf16 ===============
__global__ void im2col_kernel(const float* __restrict__ hyper) {
    size_t N = (size_t)PLANE * KK;
    for (size_t i = (size_t)blockIdx.x * blockDim.x + threadIdx.x; i < N;
         i += (size_t)gridDim.x * blockDim.x) {
        int kk = (int)(i % KK);
        int px = (int)(i / KK);
        int ic = kk / 9, t = kk % 9;
        int ky = t / 3, kx = t % 3;
        int h = px / 48, w = px % 48;
        int gh = h + ky - 1, gw = w + kx - 1;
        float v = 0.f;
        if (gh >= 0 && gh < 48 && gw >= 0 && gw < 48)
            v = hyper[(size_t)ic * PLANE + gh * 48 + gw];
        __nv_bfloat16 hv, lv; split_bf(v, hv, lv);
        g_imH[i] = hv; g_imL[i] = lv;
    }
}

// =============== K1: conv2d GEMM via mma.sync (K-split partials) ===============
// CTA = (m-block of 64 px, k-split of 864). 256 thr = 2(wm) x 4(wn) warps.
// Warp tile: M 32 (2 m16) x N 48 (6 n8). Chunks of kc=48 staged to smem.
__global__ __launch_bounds__(256)
void conv2d_mma_kernel() {
    extern __shared__ char s[];
    const uint32_t sb = smem_u32(s);
    const int tid = threadIdx.x;
    const int lane = tid & 31, warp = tid >> 5;
    const int wm = warp >> 2, wn = warp & 3;
    const int gid = lane >> 2, tig = lane & 3;
    const int amat = lane >> 3, arow = lane & 7;
    const int brow = lane & 7, bk = (lane >> 3) & 1, bn8 = (lane >> 4) & 1;

    const int mblk = blockIdx.x % 36, ksp = blockIdx.x / 36;
    const int px0 = mblk * 64;
    const int k0 = ksp * KSEG;

    float acc[2][6][4];
    #pragma unroll
    for (int mt = 0; mt < 2; mt++)
        #pragma unroll
        for (int n = 0; n < 6; n++)
            #pragma unroll
            for (int c = 0; c < 4; c++) acc[mt][n][c] = 0.f;

    #pragma unroll 1
    for (int ch = 0; ch < 18; ch++) {
        const int koff = k0 + ch * 48;
        // stage: 256 rows (64 A + 192 B) x 2 halves x 6 uint4
        for (int id = tid; id < 3072; id += 256) {
            int row = id / 12, r2 = id % 12;
            int half = r2 / 6, q = r2 % 6;
            const uint4* src;
            uint4* dst;
            if (row < 64) {
                size_t base = ((size_t)(px0 + row) * KK + koff);
                src = (const uint4*)((half ? g_imL : g_imH) + base) + q;
                dst = (uint4*)(s + (half ? G_AL : G_AH) + row * 112) + q;
            } else {
                int dch = row - 64;
                size_t base = ((size_t)dch * KK + koff);
                src = (const uint4*)((half ? g_w3L : g_w3H) + base) + q;
                dst = (uint4*)(s + (half ? G_BL : G_BH) + dch * 112) + q;
            }
            *dst = *src;
        }
        __syncthreads();
        #pragma unroll
        for (int j = 0; j < 3; j++) {
            uint32_t Ah[2][4], Al[2][4];
            #pragma unroll
            for (int mt = 0; mt < 2; mt++) {
                uint32_t aoff = (uint32_t)((wm * 32 + mt * 16 + arow + (amat & 1) * 8) * 112
                                           + j * 32 + (amat >> 1) * 16);
                LDSM4(Ah[mt], sb + G_AH + aoff);
                LDSM4(Al[mt], sb + G_AL + aoff);
            }
            uint32_t Bh[3][4], Bl[3][4];
            #pragma unroll
            for (int nb = 0; nb < 3; nb++) {
                uint32_t boff = (uint32_t)((wn * 48 + nb * 16 + brow + bn8 * 8) * 112
                                           + j * 32 + bk * 16);
                LDSM4(Bh[nb], sb + G_BH + boff);
                LDSM4(Bl[nb], sb + G_BL + boff);
            }
            #pragma unroll
            for (int mt = 0; mt < 2; mt++)
                #pragma unroll
                for (int nb = 0; nb < 3; nb++) {
                    MMA16816(acc[mt][nb * 2],     Ah[mt], Bh[nb]);
                    MMA16816(acc[mt][nb * 2],     Ah[mt], Bl[nb]);
                    MMA16816(acc[mt][nb * 2],     Al[mt], Bh[nb]);
                    MMA16816(acc[mt][nb * 2 + 1], Ah[mt], Bh[nb] + 2);
                    MMA16816(acc[mt][nb * 2 + 1], Ah[mt], Bl[nb] + 2);
                    MMA16816(acc[mt][nb * 2 + 1], Al[mt], Bh[nb] + 2);
                }
        }
        __syncthreads();
    }

    float* op = g_part + (size_t)ksp * VOX;
    #pragma unroll
    for (int mt = 0; mt < 2; mt++) {
        int px = px0 + wm * 32 + mt * 16 + gid;
        #pragma unroll
        for (int n = 0; n < 6; n++) {
            int d0 = wn * 48 + n * 8 + 2 * tig;
            op[(size_t)d0 * PLANE + px]           = acc[mt][n][0];
            op[(size_t)(d0 + 1) * PLANE + px]     = acc[mt][n][1];
            op[(size_t)d0 * PLANE + px + 8]       = acc[mt][n][2];
            op[(size_t)(d0 + 1) * PLANE + px + 8] = acc[mt][n][3];
        }
    }
}

// =============== K2: masked conv3d via mma.sync implicit GEMM (R9-validated) ===============
__global__ __launch_bounds__(192)
void conv3d_mma_kernel(const float* __restrict__ x, const float* __restrict__ b1) {
    extern __shared__ char cs[];
    const uint32_t sb = smem_u32(cs);
    const int tid = threadIdx.x;
    const int lane = tid & 31, wrp = tid >> 5;
    const int gid = lane >> 2, tig = lane & 3;
    const int amat = lane >> 3, arow = lane & 7;
    const int brow = (lane & 15) & 7, bhf = (lane & 15) >> 3;

    const int d = blockIdx.x >> 3, hb = blockIdx.x & 7;
    const int h0 = hb * 6;

    float* s_xw = (float*)(cs + C_XW);
    for (int i = tid; i < 6 * 16 * 64; i += 192) {
        int s = i >> 10, rem = i & 1023;
        int r = rem >> 6, wxx = rem & 63;
        int sd = d - 5 + s, gh = h0 - 5 + r, gw = wxx - 5;
        float v = 0.f;
        if (sd >= 0 && gh >= 0 && gh < 48 && gw >= 0 && gw < 48)
            v = x[(size_t)sd * PLANE + gh * 48 + gw];
        s_xw[i] = v;
    }
    {
        float4* wdst = (float4*)(cs + C_WH);
        const float4* wsrc = (const float4*)(g_pack + PK_WT);
        for (int i = tid; i < (2 * WT_U32_HALF) / 4; i += 192) wdst[i] = wsrc[i];
    }
    __syncthreads();

    #pragma unroll
    for (int i = 0; i < 32; i++) {
        const int k0 = 2 * i, k1 = 2 * i + 1;
        #pragma unroll
        for (int rr = 0; rr < 2; rr++) {
            int r = tid + rr * 192;
            int hr = r >> 6, wx = r & 63;
            float v0 = 0.f, v1 = 0.f;
            if (k0 <= 60) v0 = s_xw[((k0 / 11) * 16 + hr + (k0 % 11)) * 64 + wx];
            if (k1 <= 60) v1 = s_xw[((k1 / 11) * 16 + hr + (k1 % 11)) * 64 + wx];
            __nv_bfloat16 h0b, l0b, h1b, l1b;
            split_bf(v0, h0b, l0b); split_bf(v1, h1b, l1b);
            *(uint32_t*)(cs + C_AH + r * 144 + i * 4) = pack_bf2(h0b, h1b);
            *(uint32_t*)(cs + C_AL + r * 144 + i * 4) = pack_bf2(l0b, l1b);
        }
    }
    __syncthreads();

    float bb1[3][2];
    #pragma unroll
    for (int n = 0; n < 3; n++) {
        int c0 = n * 8 + 2 * tig;
        bb1[n][0] = b1[c0]; bb1[n][1] = b1[c0 + 1];
    }

    float acc[3][3][4];
    #pragma unroll
    for (int mt = 0; mt < 3; mt++)
        #pragma unroll
        for (int n = 0; n < 3; n++)
            #pragma unroll
            for (int c = 0; c < 4; c++) acc[mt][n][c] = 0.f;

    #pragma unroll 1
    for (int kw = 0; kw < 11; kw++) {
        #pragma unroll
        for (int k16 = 0; k16 < 4; k16++) {
            uint32_t bh[3][2], bl[3][2];
            #pragma unroll
            for (int n = 0; n < 3; n++) {
                uint32_t boff = (uint32_t)((kw * 24 + n * 8 + brow) * 144 + k16 * 32 + bhf * 16);
                LDSM2(bh[n], sb + C_WH + boff);
                LDSM2(bl[n], sb + C_WL + boff);
            }
            #pragma unroll
            for (int mt = 0; mt < 3; mt++) {
                int rowbase = wrp * 64 + mt * 16 + kw;
                uint32_t aoff = (uint32_t)((rowbase + arow + (amat & 1) * 8) * 144
                                           + k16 * 32 + (amat >> 1) * 16);
                uint32_t Ah[4], Al[4];
                LDSM4(Ah, sb + C_AH + aoff);
                LDSM4(Al, sb + C_AL + aoff);
                #pragma unroll
                for (int n = 0; n < 3; n++) {
                    MMA16816(acc[mt][n], Ah, bh[n]);
                    MMA16816(acc[mt][n], Ah, bl[n]);
                    MMA16816(acc[mt][n], Al, bh[n]);
                }
            }
        }
    }

    const int h_glob = h0 + wrp;
    #pragma unroll
    for (int mt = 0; mt < 3; mt++) {
        int px0 = mt * 16 + gid, px1 = px0 + 8;
        #pragma unroll
        for (int n = 0; n < 3; n++) {
            int c0 = n * 8 + 2 * tig;
            float* o0 = g_x1 + ((size_t)d * 24 + c0) * PLANE + h_glob * 48;
            float* o1 = g_x1 + ((size_t)d * 24 + c0 + 1) * PLANE + h_glob * 48;
            o0[px0] = acc[mt][n][0] + bb1[n][0];
            o1[px0] = acc[mt][n][1] + bb1[n][1];
            o0[px1] = acc[mt][n][2] + bb1[n][0];
            o1[px1] = acc[mt][n][3] + bb1[n][1];
        }
    }
}

// =============== K3: MLP via mma.sync (R8-validated; reads conv2d partials) ===============
__global__ __launch_bounds__(128)
void mlp_mma_kernel(const float* __restrict__ x, const float* __restrict__ b3,
                    const float* __restrict__ Wa, const float* __restrict__ ba,
                    const float* __restrict__ Wb, const float* __restrict__ bb,
                    const float* __restrict__ Wc, const float* __restrict__ bc,
                    float* __restrict__ out)
{
    extern __shared__ char sm_[];
    const uint32_t sb = smem_u32(sm_);
    const int tid = threadIdx.x;
    const int lane = tid & 31, w = tid >> 5;
    const int gid = lane >> 2, tig = lane & 3;

    float* s_ba = (float*)(sm_ + MO_BA);
    float* s_bb = (float*)(sm_ + MO_BB);
    float* s_bc = (float*)(sm_ + MO_BC);
    float* s_ex = (float*)(sm_ + MO_EX);

    for (int i = tid; i < 48; i += 128) s_ba[i] = ba[i];
    for (int i = tid; i < 96; i += 128) s_bb[i] = bb[i];
    for (int i = tid; i < 16; i += 128) s_bc[i] = (i < 9) ? bc[i] : 0.f;

    for (int u = tid; u < 48; u += 128) {
        #pragma unroll
        for (int i = 0; i < 16; i++) {
            int c0 = 2 * i, c1 = 2 * i + 1;
            float v0 = (c0 < 25) ? Wa[u * 25 + c0] : 0.f;
            float v1 = (c1 < 25) ? Wa[u * 25 + c1] : 0.f;
            __nv_bfloat16 h0, l0, h1, l1;
            split_bf(v0, h0, l0); split_bf(v1, h1, l1);
            *(uint32_t*)(sm_ + MO_WAH + u * WP + 4 * i) = pack_bf2(h0, h1);
            *(uint32_t*)(sm_ + MO_WAL + u * WP + 4 * i) = pack_bf2(l0, l1);
        }
    }
    for (int u = tid; u < 96; u += 128) {
        #pragma unroll
        for (int i = 0; i < 24; i++) {
            float v0 = Wb[u * 48 + 2 * i], v1 = Wb[u * 48 + 2 * i + 1];
            __nv_bfloat16 h0, l0, h1, l1;
            split_bf(v0, h0, l0); split_bf(v1, h1, l1);
            *(uint32_t*)(sm_ + MO_WBH + u * WP + 4 * i) = pack_bf2(h0, h1);
            *(uint32_t*)(sm_ + MO_WBL + u * WP + 4 * i) = pack_bf2(l0, l1);
        }
    }
    for (int u = tid; u < 16; u += 128) {
        #pragma unroll 8
        for (int i = 0; i < 48; i++) {
            float v0 = (u < 9) ? Wc[u * 96 + 2 * i] : 0.f;
            float v1 = (u < 9) ? Wc[u * 96 + 2 * i + 1] : 0.f;
            __nv_bfloat16 h0, l0, h1, l1;
            split_bf(v0, h0, l0); split_bf(v1, h1, l1);
            *(uint32_t*)(sm_ + MO_WCH + u * CP + 4 * i) = pack_bf2(h0, h1);
            *(uint32_t*)(sm_ + MO_WCL + u * CP + 4 * i) = pack_bf2(l0, l1);
        }
    }

    const int v = blockIdx.x * 128 + tid;
    const int dd = v / PLANE, p = v % PLANE;
    {
        const float* xb = g_x1 + (size_t)dd * 24 * PLANE + p;
        float t[26];
        #pragma unroll
        for (int c = 0; c < 24; c++) t[c] = xb[(size_t)c * PLANE];
        t[24] = g_part[v] + g_part[VOX + v] + g_part[2 * (size_t)VOX + v]
              + g_part[3 * (size_t)VOX + v] + b3[dd];
        t[25] = 0.f;
        #pragma unroll
        for (int i = 0; i < 16; i++) {
            float v0 = (2 * i < 26) ? t[2 * i] : 0.f;
            float v1 = (2 * i + 1 < 26) ? t[2 * i + 1] : 0.f;
            __nv_bfloat16 h0, l0, h1, l1;
            split_bf(v0, h0, l0); split_bf(v1, h1, l1);
            *(uint32_t*)(sm_ + MO_XH + tid * XP + 4 * i) = pack_bf2(h0, h1);
            *(uint32_t*)(sm_ + MO_XL + tid * XP + 4 * i) = pack_bf2(l0, l1);
        }
    }
    __syncthreads();

    const int amat = lane >> 3, arow = lane & 7;
    const int bl15 = lane & 15, brow = bl15 & 7, bhf = bl15 >> 3;
    #define AADDR(off, row0, kb, P) \
        (sb + (off) + (uint32_t)(((row0) + arow + (amat & 1) * 8) * (P) + (kb) + (amat >> 1) * 16))
    #define BADDR(off, n0, kb, P) \
        (sb + (off) + (uint32_t)(((n0) + brow) * (P) + (kb) + bhf * 16))

    const int row0 = w * 32;

    float dA[2][6][4];
    #pragma unroll
    for (int m = 0; m < 2; m++)
        #pragma unroll
        for (int n = 0; n < 6; n++)
            #pragma unroll
            for (int c = 0; c < 4; c++) dA[m][n][c] = 0.f;
    {
        uint32_t Ahf[2][2][4], Alf[2][2][4];
        #pragma unroll
        for (int m = 0; m < 2; m++)
            #pragma unroll
            for (int k = 0; k < 2; k++) {
                LDSM4(Ahf[m][k], AADDR(MO_XH, row0 + 16 * m, 32 * k, XP));
                LDSM4(Alf[m][k], AADDR(MO_XL, row0 + 16 * m, 32 * k, XP));
            }
        #pragma unroll
        for (int n = 0; n < 6; n++) {
            uint32_t bh[2][2], bl2[2][2];
            #pragma unroll
            for (int k = 0; k < 2; k++) {
                LDSM2(bh[k],  BADDR(MO_WAH, n * 8, 32 * k, WP));
                LDSM2(bl2[k], BADDR(MO_WAL, n * 8, 32 * k, WP));
            }
            #pragma unroll
            for (int m = 0; m < 2; m++)
                #pragma unroll
                for (int k = 0; k < 2; k++) {
                    MMA16816(dA[m][n], Ahf[m][k], bh[k]);
                    MMA16816(dA[m][n], Ahf[m][k], bl2[k]);
                    MMA16816(dA[m][n], Alf[m][k], bh[k]);
                }
        }
    }
    #pragma unroll
    for (int m = 0; m < 2; m++)
        #pragma unroll
        for (int n = 0; n < 6; n++) {
            float2 bias = *(float2*)(s_ba + n * 8 + 2 * tig);
            float v0 = fmaxf(dA[m][n][0] + bias.x, 0.f);
            float v1 = fmaxf(dA[m][n][1] + bias.y, 0.f);
            float v2 = fmaxf(dA[m][n][2] + bias.x, 0.f);
            float v3 = fmaxf(dA[m][n][3] + bias.y, 0.f);
            int r1 = row0 + 16 * m + gid, r2 = r1 + 8;
            int cb = (n * 8 + 2 * tig) * 2;
            __nv_bfloat16 h0, l0, h1, l1;
            split_bf(v0, h0, l0); split_bf(v1, h1, l1);
            *(uint32_t*)(sm_ + MO_XH + r1 * XP + cb) = pack_bf2(h0, h1);
            *(uint32_t*)(sm_ + MO_XL + r1 * XP + cb) = pack_bf2(l0, l1);
            split_bf(v2, h0, l0); split_bf(v3, h1, l1);
            *(uint32_t*)(sm_ + MO_XH + r2 * XP + cb) = pack_bf2(h0, h1);
            *(uint32_t*)(sm_ + MO_XL + r2 * XP + cb) = pack_bf2(l0, l1);
        }
    __syncwarp();

    float dB[2][12][4];
    #pragma unroll
    for (int m = 0; m < 2; m++)
        #pragma unroll
        for (int n = 0; n < 12; n++)
            #pragma unroll
            for (int c = 0; c < 4; c++) dB[m][n][c] = 0.f;
    {
        uint32_t Ahf[2][3][4], Alf[2][3][4];
        #pragma unroll
        for (int m = 0; m < 2; m++)
            #pragma unroll
            for (int k = 0; k < 3; k++) {
                LDSM4(Ahf[m][k], AADDR(MO_XH, row0 + 16 * m, 32 * k, XP));
                LDSM4(Alf[m][k], AADDR(MO_XL, row0 + 16 * m, 32 * k, XP));
            }
        #pragma unroll
        for (int n = 0; n < 12; n++) {
            uint32_t bh[3][2], bl2[3][2];
            #pragma unroll
            for (int k = 0; k < 3; k++) {
                LDSM2(bh[k],  BADDR(MO_WBH, n * 8, 32 * k, WP));
                LDSM2(bl2[k], BADDR(MO_WBL, n * 8, 32 * k, WP));
            }
            #pragma unroll
            for (int m = 0; m < 2; m++)
                #pragma unroll
                for (int k = 0; k < 3; k++) {
                    MMA16816(dB[m][n], Ahf[m][k], bh[k]);
                    MMA16816(dB[m][n], Ahf[m][k], bl2[k]);
                    MMA16816(dB[m][n], Alf[m][k], bh[k]);
                }
        }
    }
    #pragma unroll
    for (int m = 0; m < 2; m++)
        #pragma unroll
        for (int n = 0; n < 12; n++) {
            float2 bias = *(float2*)(s_bb + n * 8 + 2 * tig);
            float v0 = fmaxf(dB[m][n][0] + bias.x, 0.f);
            float v1 = fmaxf(dB[m][n][1] + bias.y, 0.f);
            float v2 = fmaxf(dB[m][n][2] + bias.x, 0.f);
            float v3 = fmaxf(dB[m][n][3] + bias.y, 0.f);
            int r1 = row0 + 16 * m + gid, r2 = r1 + 8;
            int cb = (n * 8 + 2 * tig) * 2;
            __nv_bfloat16 h0, l0, h1, l1;
            split_bf(v0, h0, l0); split_bf(v1, h1, l1);
            *(uint32_t*)(sm_ + MO_XH + r1 * XP + cb) = pack_bf2(h0, h1);
            *(uint32_t*)(sm_ + MO_XL + r1 * XP + cb) = pack_bf2(l0, l1);
            split_bf(v2, h0, l0); split_bf(v3, h1, l1);
            *(uint32_t*)(sm_ + MO_XH + r2 * XP + cb) = pack_bf2(h0, h1);
            *(uint32_t*)(sm_ + MO_XL + r2 * XP + cb) = pack_bf2(l0, l1);
        }
    __syncwarp();

    float dC[2][2][4];
    #pragma unroll
    for (int m = 0; m < 2; m++)
        #pragma unroll
        for (int n = 0; n < 2; n++)
            #pragma unroll
            for (int c = 0; c < 4; c++) dC[m][n][c] = 0.f;
    {
        uint32_t Ahf[2][6][4], Alf[2][6][4];
        #pragma unroll
        for (int m = 0; m < 2; m++)
            #pragma unroll
            for (int k = 0; k < 6; k++) {
                LDSM4(Ahf[m][k], AADDR(MO_XH, row0 + 16 * m, 32 * k, XP));
                LDSM4(Alf[m][k], AADDR(MO_XL, row0 + 16 * m, 32 * k, XP));
            }
        #pragma unroll
        for (int n = 0; n < 2; n++) {
            #pragma unroll
            for (int k = 0; k < 6; k++) {
                uint32_t bh[2], bl2[2];
                LDSM2(bh,  BADDR(MO_WCH, n * 8, 32 * k, CP));
                LDSM2(bl2, BADDR(MO_WCL, n * 8, 32 * k, CP));
                #pragma unroll
                for (int m = 0; m < 2; m++) {
                    MMA16816(dC[m][n], Ahf[m][k], bh);
                    MMA16816(dC[m][n], Ahf[m][k], bl2);
                    MMA16816(dC[m][n], Alf[m][k], bh);
                }
            }
        }
    }

    #pragma unroll
    for (int m = 0; m < 2; m++)
        #pragma unroll
        for (int n = 0; n < 2; n++) {
            int r1 = row0 + 16 * m + gid, r2 = r1 + 8;
            int cc = n * 8 + 2 * tig;
            s_ex[r1 * 18 + cc]     = dC[m][n][0];
            s_ex[r1 * 18 + cc + 1] = dC[m][n][1];
            s_ex[r2 * 18 + cc]     = dC[m][n][2];
            s_ex[r2 * 18 + cc + 1] = dC[m][n][3];
        }
    __syncwarp();

    float o9[9];
    #pragma unroll
    for (int o = 0; o < 9; o++) o9[o] = s_ex[tid * 18 + o] + s_bc[o];

    float xv = x[v];
    float mx = fmaxf(o9[6], fmaxf(o9[7], o9[8]));
    float e0 = expf(o9[6] - mx), e1 = expf(o9[7] - mx), e2 = expf(o9[8] - mx);
    float inv = 1.f / (e0 + e1 + e2);
    float wsm[3] = {e0 * inv, e1 * inv, e2 * inv};

    float p3 = 0.f;
    #pragma unroll
    for (int k = 0; k < 3; k++) {
        float mu = o9[k];
        float scv = o9[3 + k];
        if (scv == 0.f) scv = 1e-9f;
        scv = fabsf(scv);
        float invs = 1.f / scv;
        float l = fabsf(normcdff((xv + 0.5f - mu) * invs)
                      - normcdff((xv - 0.5f - mu) * invs));
        p3 = fmaf(wsm[k], l, p3);
    }

    out[v] = p3;
    #pragma unroll
    for (int o = 0; o < 9; o++)
        out[(size_t)VOX + (size_t)o * VOX + v] = o9[o];
    #undef AADDR
    #undef BADDR
}

extern "C" void kernel_launch(void* const* d_in, const int* in_sizes, int n_in,
                              void* d_out, int out_size) {
    const float* x     = (const float*)d_in[0];
    const float* hyper = (const float*)d_in[1];
    const float* W3    = (const float*)d_in[2];
    const float* b3    = (const float*)d_in[3];
    const float* W1    = (const float*)d_in[4];
    const float* b1    = (const float*)d_in[5];
    const float* Wa    = (const float*)d_in[6];
    const float* ba    = (const float*)d_in[7];
    const float* Wb    = (const float*)d_in[8];
    const float* bb    = (const float*)d_in[9];
    const float* Wc    = (const float*)d_in[10];
    const float* bc    = (const float*)d_in[11];
    float* out = (float*)d_out;

    cudaFuncSetAttribute(conv3d_mma_kernel,
                         cudaFuncAttributeMaxDynamicSharedMemorySize, C_SMEM);
    cudaFuncSetAttribute(conv2d_mma_kernel,
                         cudaFuncAttributeMaxDynamicSharedMemorySize, G_SMEM);
    cudaFuncSetAttribute(mlp_mma_kernel,
                         cudaFuncAttributeMaxDynamicSharedMemorySize, MO_SMEM);

    pack_kernel<<<256, 256>>>(W3, W1);
    im2col_kernel<<<4096, 256>>>(hyper);
    conv2d_mma_kernel<<<36 * KSPLIT, 256, G_SMEM>>>();
    conv3d_mma_kernel<<<192 * 8, 192, C_SMEM>>>(x, b1);
    mlp_mma_kernel<<<VOX / 128, 128, MO_SMEM>>>(x, b3, Wa, ba, Wb, bb, Wc, bc, out);
}

// round 11
// speedup vs baseline: 2.0538x; 1.0140x over previous
#include <cuda_runtime.h>
#include <cuda_bf16.h>
#include <cmath>
#include <cstring>
#include <cstdint>

namespace {
constexpr int D = 192, H = 48, W = 48, PLANE = 2304, VOX = 442368;
constexpr int KK = 3456;              // conv2d GEMM K = 384 ic * 9 taps
constexpr int KSPLIT = 4, KSEG = 864; // per-split K

// ---- pack buffer (float offsets) : conv3d weight image only ----
constexpr int PK_WT = 663552;
constexpr int WT_U32_HALF = 9504;     // 264 rows x 36 u32 (pitch 144B)

// ---- conv3d mma smem (bytes) ----
constexpr int C_XW = 0;
constexpr int C_AH = 24576;
constexpr int C_AL = 79872;           // reused as reduction exchange post-mainloop
constexpr int C_WH = 135168;
constexpr int C_WL = 173184;
constexpr int C_SMEM = 211200;

// ---- conv2d mma smem (bytes): pitch 112B ----
constexpr int G_AH = 0;
constexpr int G_AL = 7168;
constexpr int G_BH = 14336;
constexpr int G_BL = 35840;
constexpr int G_SMEM = 57344;

// ---- mlp mma smem byte offsets (R8-validated) ----
constexpr int XP = 208;
constexpr int WP = 112;
constexpr int CP = 208;
constexpr int MO_XH  = 0;
constexpr int MO_XL  = 26624;
constexpr int MO_WAH = 53248;
constexpr int MO_WAL = 58624;
constexpr int MO_WBH = 64000;
constexpr int MO_WBL = 74752;
constexpr int MO_WCH = 85504;
constexpr int MO_WCL = 88832;
constexpr int MO_EX  = 92160;
constexpr int MO_BA  = 101376;
constexpr int MO_BB  = 101568;
constexpr int MO_BC  = 101952;
constexpr int MO_SMEM = 102016;
}

__device__ __align__(16) float g_pack[689680];
__device__ float g_x1[(size_t)24 * VOX];
__device__ __align__(16) __nv_bfloat16 g_imH[(size_t)PLANE * KK];
__device__ __align__(16) __nv_bfloat16 g_imL[(size_t)PLANE * KK];
__device__ __align__(16) __nv_bfloat16 g_w3H[(size_t)D * KK];
__device__ __align__(16) __nv_bfloat16 g_w3L[(size_t)D * KK];
__device__ float g_part[(size_t)KSPLIT * VOX];

// ---- mma.sync helpers (validated) ----
__device__ __forceinline__ uint32_t smem_u32(const void* p) {
    uint32_t a;
    asm("{ .reg .u64 t; cvta.to.shared.u64 t, %1; cvt.u32.u64 %0, t; }"
        : "=r"(a) : "l"(p));
    return a;
}
#define LDSM4(r, addr) \
    asm volatile("ldmatrix.sync.aligned.m8n8.x4.shared.b16 {%0,%1,%2,%3}, [%4];" \
        : "=r"((r)[0]), "=r"((r)[1]), "=r"((r)[2]), "=r"((r)[3]) : "r"(addr))
#define LDSM2(r, addr) \
    asm volatile("ldmatrix.sync.aligned.m8n8.x2.shared.b16 {%0,%1}, [%2];" \
        : "=r"((r)[0]), "=r"((r)[1]) : "r"(addr))
#define MMA16816(d, a, b) \
    asm volatile("mma.sync.aligned.m16n8k16.row.col.f32.bf16.bf16.f32 " \
        "{%0,%1,%2,%3}, {%4,%5,%6,%7}, {%8,%9}, {%0,%1,%2,%3};" \
        : "+f"((d)[0]), "+f"((d)[1]), "+f"((d)[2]), "+f"((d)[3]) \
        : "r"((a)[0]), "r"((a)[1]), "r"((a)[2]), "r"((a)[3]), \
          "r"((b)[0]), "r"((b)[1]))

__device__ __forceinline__ void split_bf(float v, __nv_bfloat16& h, __nv_bfloat16& l) {
    h = __float2bfloat16(v);
    l = __float2bfloat16(v - __bfloat162float(h));
}
__device__ __forceinline__ uint32_t pack_bf2(__nv_bfloat16 a, __nv_bfloat16 b) {
    __nv_bfloat162 t; t.x = a; t.y = b;
    uint32_t u; memcpy(&u, &t, 4); return u;
}

// =============== K0a: pack conv3d weight image + conv2d weight split ===============
__global__ void pack_kernel(const float* __restrict__ W3, const float* __restrict__ W1) {
    int nt = gridDim.x * blockDim.x, tid = blockIdx.x * blockDim.x + threadIdx.x;
    uint32_t* wt = (uint32_t*)(g_pack + PK_WT);
    for (int j = tid; j < 2 * WT_U32_HALF; j += nt) {
        int half = j / WT_U32_HALF, jj = j % WT_U32_HALF;
        int row = jj / 36, col = jj % 36;
        int kw = row / 24, c = row % 24;
        float v[2];
        #pragma unroll
        for (int s = 0; s < 2; s++) {
            int k = col * 2 + s;
            float val = 0.f;
            if (k <= 60) {
                int kd = k / 11, kh = k % 11;
                int flat = kd * 121 + kh * 11 + kw;
                if (flat < 665) val = W1[c * 1331 + flat];
            }
            v[s] = val;
        }
        __nv_bfloat16 h0, l0, h1, l1;
        split_bf(v[0], h0, l0); split_bf(v[1], h1, l1);
        wt[j] = half ? pack_bf2(l0, l1) : pack_bf2(h0, h1);
    }
    for (int i = tid; i < D * KK; i += nt) {
        int kk = i % KK, d = i / KK;
        int ic = kk / 9, t = kk % 9;
        float v = W3[((size_t)d * 384 + ic) * 9 + t];
        __nv_bfloat16 hv, lv; split_bf(v, hv, lv);
        g_w3H[i] = hv; g_w3L[i] = lv;
    }
}

// =============== K0b: im2col of hyper, split bf16 ===============
__global__ void im2col_kernel(const float* __restrict__ hyper) {
    size_t N = (size_t)PLANE * KK;
    for (size_t i = (size_t)blockIdx.x * blockDim.x + threadIdx.x; i < N;
         i += (size_t)gridDim.x * blockDim.x) {
        int kk = (int)(i % KK);
        int px = (int)(i / KK);
        int ic = kk / 9, t = kk % 9;
        int ky = t / 3, kx = t % 3;
        int h = px / 48, w = px % 48;
        int gh = h + ky - 1, gw = w + kx - 1;
        float v = 0.f;
        if (gh >= 0 && gh < 48 && gw >= 0 && gw < 48)
            v = hyper[(size_t)ic * PLANE + gh * 48 + gw];
        __nv_bfloat16 hv, lv; split_bf(v, hv, lv);
        g_imH[i] = hv; g_imL[i] = lv;
    }
}

// =============== K1: conv2d GEMM via mma.sync (R10-validated) ===============
__global__ __launch_bounds__(256)
void conv2d_mma_kernel() {
    extern __shared__ char s[];
    const uint32_t sb = smem_u32(s);
    const int tid = threadIdx.x;
    const int lane = tid & 31, warp = tid >> 5;
    const int wm = warp >> 2, wn = warp & 3;
    const int gid = lane >> 2, tig = lane & 3;
    const int amat = lane >> 3, arow = lane & 7;
    const int brow = lane & 7, bk = (lane >> 3) & 1, bn8 = (lane >> 4) & 1;

    const int mblk = blockIdx.x % 36, ksp = blockIdx.x / 36;
    const int px0 = mblk * 64;
    const int k0 = ksp * KSEG;

    float acc[2][6][4];
    #pragma unroll
    for (int mt = 0; mt < 2; mt++)
        #pragma unroll
        for (int n = 0; n < 6; n++)
            #pragma unroll
            for (int c = 0; c < 4; c++) acc[mt][n][c] = 0.f;

    #pragma unroll 1
    for (int ch = 0; ch < 18; ch++) {
        const int koff = k0 + ch * 48;
        for (int id = tid; id < 3072; id += 256) {
            int row = id / 12, r2 = id % 12;
            int half = r2 / 6, q = r2 % 6;
            const uint4* src;
            uint4* dst;
            if (row < 64) {
                size_t base = ((size_t)(px0 + row) * KK + koff);
                src = (const uint4*)((half ? g_imL : g_imH) + base) + q;
                dst = (uint4*)(s + (half ? G_AL : G_AH) + row * 112) + q;
            } else {
                int dch = row - 64;
                size_t base = ((size_t)dch * KK + koff);
                src = (const uint4*)((half ? g_w3L : g_w3H) + base) + q;
                dst = (uint4*)(s + (half ? G_BL : G_BH) + dch * 112) + q;
            }
            *dst = *src;
        }
        __syncthreads();
        #pragma unroll
        for (int j = 0; j < 3; j++) {
            uint32_t Ah[2][4], Al[2][4];
            #pragma unroll
            for (int mt = 0; mt < 2; mt++) {
                uint32_t aoff = (uint32_t)((wm * 32 + mt * 16 + arow + (amat & 1) * 8) * 112
                                           + j * 32 + (amat >> 1) * 16);
                LDSM4(Ah[mt], sb + G_AH + aoff);
                LDSM4(Al[mt], sb + G_AL + aoff);
            }
            uint32_t Bh[3][4], Bl[3][4];
            #pragma unroll
            for (int nb = 0; nb < 3; nb++) {
                uint32_t boff = (uint32_t)((wn * 48 + nb * 16 + brow + bn8 * 8) * 112
                                           + j * 32 + bk * 16);
                LDSM4(Bh[nb], sb + G_BH + boff);
                LDSM4(Bl[nb], sb + G_BL + boff);
            }
            #pragma unroll
            for (int mt = 0; mt < 2; mt++)
                #pragma unroll
                for (int nb = 0; nb < 3; nb++) {
                    MMA16816(acc[mt][nb * 2],     Ah[mt], Bh[nb]);
                    MMA16816(acc[mt][nb * 2],     Ah[mt], Bl[nb]);
                    MMA16816(acc[mt][nb * 2],     Al[mt], Bh[nb]);
                    MMA16816(acc[mt][nb * 2 + 1], Ah[mt], Bh[nb] + 2);
                    MMA16816(acc[mt][nb * 2 + 1], Ah[mt], Bl[nb] + 2);
                    MMA16816(acc[mt][nb * 2 + 1], Al[mt], Bh[nb] + 2);
                }
        }
        __syncthreads();
    }

    float* op = g_part + (size_t)ksp * VOX;
    #pragma unroll
    for (int mt = 0; mt < 2; mt++) {
        int px = px0 + wm * 32 + mt * 16 + gid;
        #pragma unroll
        for (int n = 0; n < 6; n++) {
            int d0 = wn * 48 + n * 8 + 2 * tig;
            op[(size_t)d0 * PLANE + px]           = acc[mt][n][0];
            op[(size_t)(d0 + 1) * PLANE + px]     = acc[mt][n][1];
            op[(size_t)d0 * PLANE + px + 8]       = acc[mt][n][2];
            op[(size_t)(d0 + 1) * PLANE + px + 8] = acc[mt][n][3];
        }
    }
}

// =============== K2: masked conv3d, kw-split across 12 warps ===============
// Warps 0-5: h-rows 0-5, kw 0-5.  Warps 6-11: same h-rows, kw 6-10.
// Partial accumulators reduced through smem (reusing the A-lo region).
__global__ __launch_bounds__(384)
void conv3d_mma_kernel(const float* __restrict__ x, const float* __restrict__ b1) {
    extern __shared__ char cs[];
    const uint32_t sb = smem_u32(cs);
    const int tid = threadIdx.x;
    const int lane = tid & 31, wrp = tid >> 5;          // 0..11
    const int hrow = (wrp < 6) ? wrp : wrp - 6;
    const int khalf = (wrp < 6) ? 0 : 1;
    const int gid = lane >> 2, tig = lane & 3;
    const int amat = lane >> 3, arow = lane & 7;
    const int brow = (lane & 15) & 7, bhf = (lane & 15) >> 3;

    const int d = blockIdx.x >> 3, hb = blockIdx.x & 7;
    const int h0 = hb * 6;

    float* s_xw = (float*)(cs + C_XW);
    for (int i = tid; i < 6 * 16 * 64; i += 384) {
        int s = i >> 10, rem = i & 1023;
        int r = rem >> 6, wxx = rem & 63;
        int sd = d - 5 + s, gh = h0 - 5 + r, gw = wxx - 5;
        float v = 0.f;
        if (sd >= 0 && gh >= 0 && gh < 48 && gw >= 0 && gw < 48)
            v = x[(size_t)sd * PLANE + gh * 48 + gw];
        s_xw[i] = v;
    }
    {
        float4* wdst = (float4*)(cs + C_WH);
        const float4* wsrc = (const float4*)(g_pack + PK_WT);
        for (int i = tid; i < (2 * WT_U32_HALF) / 4; i += 384) wdst[i] = wsrc[i];
    }
    __syncthreads();

    // build A hi/lo: 384 rows, one row per thread
    {
        int r = tid;
        int hr = r >> 6, wx = r & 63;
        #pragma unroll
        for (int i = 0; i < 32; i++) {
            const int k0 = 2 * i, k1 = 2 * i + 1;
            float v0 = 0.f, v1 = 0.f;
            if (k0 <= 60) v0 = s_xw[((k0 / 11) * 16 + hr + (k0 % 11)) * 64 + wx];
            if (k1 <= 60) v1 = s_xw[((k1 / 11) * 16 + hr + (k1 % 11)) * 64 + wx];
            __nv_bfloat16 h0b, l0b, h1b, l1b;
            split_bf(v0, h0b, l0b); split_bf(v1, h1b, l1b);
            *(uint32_t*)(cs + C_AH + r * 144 + i * 4) = pack_bf2(h0b, h1b);
            *(uint32_t*)(cs + C_AL + r * 144 + i * 4) = pack_bf2(l0b, l1b);
        }
    }
    __syncthreads();

    float acc[3][3][4];
    #pragma unroll
    for (int mt = 0; mt < 3; mt++)
        #pragma unroll
        for (int n = 0; n < 3; n++)
            #pragma unroll
            for (int c = 0; c < 4; c++) acc[mt][n][c] = 0.f;

    const int kw_lo = khalf * 6, kw_hi = khalf ? 11 : 6;
    #pragma unroll 1
    for (int kw = kw_lo; kw < kw_hi; kw++) {
        #pragma unroll
        for (int k16 = 0; k16 < 4; k16++) {
            uint32_t bh[3][2], bl[3][2];
            #pragma unroll
            for (int n = 0; n < 3; n++) {
                uint32_t boff = (uint32_t)((kw * 24 + n * 8 + brow) * 144 + k16 * 32 + bhf * 16);
                LDSM2(bh[n], sb + C_WH + boff);
                LDSM2(bl[n], sb + C_WL + boff);
            }
            #pragma unroll
            for (int mt = 0; mt < 3; mt++) {
                int rowbase = hrow * 64 + mt * 16 + kw;
                uint32_t aoff = (uint32_t)((rowbase + arow + (amat & 1) * 8) * 144
                                           + k16 * 32 + (amat >> 1) * 16);
                uint32_t Ah[4], Al[4];
                LDSM4(Ah, sb + C_AH + aoff);
                LDSM4(Al, sb + C_AL + aoff);
                #pragma unroll
                for (int n = 0; n < 3; n++) {
                    MMA16816(acc[mt][n], Ah, bh[n]);
                    MMA16816(acc[mt][n], Ah, bl[n]);
                    MMA16816(acc[mt][n], Al, bh[n]);
                }
            }
        }
    }

    // ---- reduce kw-halves: upper warps dump to smem (reuse A-lo region) ----
    __syncthreads();                       // everyone done reading A/W
    float* exch = (float*)(cs + C_AL);     // 6 warps x 32 lanes x 37 floats = 28416B
    if (khalf == 1) {
        float* e = exch + ((wrp - 6) * 32 + lane) * 37;
        #pragma unroll
        for (int mt = 0; mt < 3; mt++)
            #pragma unroll
            for (int n = 0; n < 3; n++)
                #pragma unroll
                for (int c = 0; c < 4; c++)
                    e[(mt * 3 + n) * 4 + c] = acc[mt][n][c];
    }
    __syncthreads();
    if (khalf == 0) {
        const float* e = exch + (wrp * 32 + lane) * 37;
        float bb1[3][2];
        #pragma unroll
        for (int n = 0; n < 3; n++) {
            int c0 = n * 8 + 2 * tig;
            bb1[n][0] = b1[c0]; bb1[n][1] = b1[c0 + 1];
        }
        const int h_glob = h0 + hrow;
        #pragma unroll
        for (int mt = 0; mt < 3; mt++) {
            int px0 = mt * 16 + gid, px1 = px0 + 8;
            #pragma unroll
            for (int n = 0; n < 3; n++) {
                int c0 = n * 8 + 2 * tig;
                const float* ep = e + (mt * 3 + n) * 4;
                float* o0 = g_x1 + ((size_t)d * 24 + c0) * PLANE + h_glob * 48;
                float* o1 = g_x1 + ((size_t)d * 24 + c0 + 1) * PLANE + h_glob * 48;
                o0[px0] = acc[mt][n][0] + ep[0] + bb1[n][0];
                o1[px0] = acc[mt][n][1] + ep[1] + bb1[n][1];
                o0[px1] = acc[mt][n][2] + ep[2] + bb1[n][0];
                o1[px1] = acc[mt][n][3] + ep[3] + bb1[n][1];
            }
        }
    }
}

// =============== K3: MLP via mma.sync (R8-validated; reads conv2d partials) ===============
__global__ __launch_bounds__(128)
void mlp_mma_kernel(const float* __restrict__ x, const float* __restrict__ b3,
                    const float* __restrict__ Wa, const float* __restrict__ ba,
                    const float* __restrict__ Wb, const float* __restrict__ bb,
                    const float* __restrict__ Wc, const float* __restrict__ bc,
                    float* __restrict__ out)
{
    extern __shared__ char sm_[];
    const uint32_t sb = smem_u32(sm_);
    const int tid = threadIdx.x;
    const int lane = tid & 31, w = tid >> 5;
    const int gid = lane >> 2, tig = lane & 3;

    float* s_ba = (float*)(sm_ + MO_BA);
    float* s_bb = (float*)(sm_ + MO_BB);
    float* s_bc = (float*)(sm_ + MO_BC);
    float* s_ex = (float*)(sm_ + MO_EX);

    for (int i = tid; i < 48; i += 128) s_ba[i] = ba[i];
    for (int i = tid; i < 96; i += 128) s_bb[i] = bb[i];
    for (int i = tid; i < 16; i += 128) s_bc[i] = (i < 9) ? bc[i] : 0.f;

    for (int u = tid; u < 48; u += 128) {
        #pragma unroll
        for (int i = 0; i < 16; i++) {
            int c0 = 2 * i, c1 = 2 * i + 1;
            float v0 = (c0 < 25) ? Wa[u * 25 + c0] : 0.f;
            float v1 = (c1 < 25) ? Wa[u * 25 + c1] : 0.f;
            __nv_bfloat16 h0, l0, h1, l1;
            split_bf(v0, h0, l0); split_bf(v1, h1, l1);
            *(uint32_t*)(sm_ + MO_WAH + u * WP + 4 * i) = pack_bf2(h0, h1);
            *(uint32_t*)(sm_ + MO_WAL + u * WP + 4 * i) = pack_bf2(l0, l1);
        }
    }
    for (int u = tid; u < 96; u += 128) {
        #pragma unroll
        for (int i = 0; i < 24; i++) {
            float v0 = Wb[u * 48 + 2 * i], v1 = Wb[u * 48 + 2 * i + 1];
            __nv_bfloat16 h0, l0, h1, l1;
            split_bf(v0, h0, l0); split_bf(v1, h1, l1);
            *(uint32_t*)(sm_ + MO_WBH + u * WP + 4 * i) = pack_bf2(h0, h1);
            *(uint32_t*)(sm_ + MO_WBL + u * WP + 4 * i) = pack_bf2(l0, l1);
        }
    }
    for (int u = tid; u < 16; u += 128) {
        #pragma unroll 8
        for (int i = 0; i < 48; i++) {
            float v0 = (u < 9) ? Wc[u * 96 + 2 * i] : 0.f;
            float v1 = (u < 9) ? Wc[u * 96 + 2 * i + 1] : 0.f;
            __nv_bfloat16 h0, l0, h1, l1;
            split_bf(v0, h0, l0); split_bf(v1, h1, l1);
            *(uint32_t*)(sm_ + MO_WCH + u * CP + 4 * i) = pack_bf2(h0, h1);
            *(uint32_t*)(sm_ + MO_WCL + u * CP + 4 * i) = pack_bf2(l0, l1);
        }
    }

    const int v = blockIdx.x * 128 + tid;
    const int dd = v / PLANE, p = v % PLANE;
    {
        const float* xb = g_x1 + (size_t)dd * 24 * PLANE + p;
        float t[26];
        #pragma unroll
        for (int c = 0; c < 24; c++) t[c] = xb[(size_t)c * PLANE];
        t[24] = g_part[v] + g_part[VOX + v] + g_part[2 * (size_t)VOX + v]
              + g_part[3 * (size_t)VOX + v] + b3[dd];
        t[25] = 0.f;
        #pragma unroll
        for (int i = 0; i < 16; i++) {
            float v0 = (2 * i < 26) ? t[2 * i] : 0.f;
            float v1 = (2 * i + 1 < 26) ? t[2 * i + 1] : 0.f;
            __nv_bfloat16 h0, l0, h1, l1;
            split_bf(v0, h0, l0); split_bf(v1, h1, l1);
            *(uint32_t*)(sm_ + MO_XH + tid * XP + 4 * i) = pack_bf2(h0, h1);
            *(uint32_t*)(sm_ + MO_XL + tid * XP + 4 * i) = pack_bf2(l0, l1);
        }
    }
    __syncthreads();

    const int amat = lane >> 3, arow = lane & 7;
    const int bl15 = lane & 15, brow = bl15 & 7, bhf = bl15 >> 3;
    #define AADDR(off, row0, kb, P) \
        (sb + (off) + (uint32_t)(((row0) + arow + (amat & 1) * 8) * (P) + (kb) + (amat >> 1) * 16))
    #define BADDR(off, n0, kb, P) \
        (sb + (off) + (uint32_t)(((n0) + brow) * (P) + (kb) + bhf * 16))

    const int row0 = w * 32;

    float dA[2][6][4];
    #pragma unroll
    for (int m = 0; m < 2; m++)
        #pragma unroll
        for (int n = 0; n < 6; n++)
            #pragma unroll
            for (int c = 0; c < 4; c++) dA[m][n][c] = 0.f;
    {
        uint32_t Ahf[2][2][4], Alf[2][2][4];
        #pragma unroll
        for (int m = 0; m < 2; m++)
            #pragma unroll
            for (int k = 0; k < 2; k++) {
                LDSM4(Ahf[m][k], AADDR(MO_XH, row0 + 16 * m, 32 * k, XP));
                LDSM4(Alf[m][k], AADDR(MO_XL, row0 + 16 * m, 32 * k, XP));
            }
        #pragma unroll
        for (int n = 0; n < 6; n++) {
            uint32_t bh[2][2], bl2[2][2];
            #pragma unroll
            for (int k = 0; k < 2; k++) {
                LDSM2(bh[k],  BADDR(MO_WAH, n * 8, 32 * k, WP));
                LDSM2(bl2[k], BADDR(MO_WAL, n * 8, 32 * k, WP));
            }
            #pragma unroll
            for (int m = 0; m < 2; m++)
                #pragma unroll
                for (int k = 0; k < 2; k++) {
                    MMA16816(dA[m][n], Ahf[m][k], bh[k]);
                    MMA16816(dA[m][n], Ahf[m][k], bl2[k]);
                    MMA16816(dA[m][n], Alf[m][k], bh[k]);
                }
        }
    }
    #pragma unroll
    for (int m = 0; m < 2; m++)
        #pragma unroll
        for (int n = 0; n < 6; n++) {
            float2 bias = *(float2*)(s_ba + n * 8 + 2 * tig);
            float v0 = fmaxf(dA[m][n][0] + bias.x, 0.f);
            float v1 = fmaxf(dA[m][n][1] + bias.y, 0.f);
            float v2 = fmaxf(dA[m][n][2] + bias.x, 0.f);
            float v3 = fmaxf(dA[m][n][3] + bias.y, 0.f);
            int r1 = row0 + 16 * m + gid, r2 = r1 + 8;
            int cb = (n * 8 + 2 * tig) * 2;
            __nv_bfloat16 h0, l0, h1, l1;
            split_bf(v0, h0, l0); split_bf(v1, h1, l1);
            *(uint32_t*)(sm_ + MO_XH + r1 * XP + cb) = pack_bf2(h0, h1);
            *(uint32_t*)(sm_ + MO_XL + r1 * XP + cb) = pack_bf2(l0, l1);
            split_bf(v2, h0, l0); split_bf(v3, h1, l1);
            *(uint32_t*)(sm_ + MO_XH + r2 * XP + cb) = pack_bf2(h0, h1);
            *(uint32_t*)(sm_ + MO_XL + r2 * XP + cb) = pack_bf2(l0, l1);
        }
    __syncwarp();

    float dB[2][12][4];
    #pragma unroll
    for (int m = 0; m < 2; m++)
        #pragma unroll
        for (int n = 0; n < 12; n++)
            #pragma unroll
            for (int c = 0; c < 4; c++) dB[m][n][c] = 0.f;
    {
        uint32_t Ahf[2][3][4], Alf[2][3][4];
        #pragma unroll
        for (int m = 0; m < 2; m++)
            #pragma unroll
            for (int k = 0; k < 3; k++) {
                LDSM4(Ahf[m][k], AADDR(MO_XH, row0 + 16 * m, 32 * k, XP));
                LDSM4(Alf[m][k], AADDR(MO_XL, row0 + 16 * m, 32 * k, XP));
            }
        #pragma unroll
        for (int n = 0; n < 12; n++) {
            uint32_t bh[3][2], bl2[3][2];
            #pragma unroll
            for (int k = 0; k < 3; k++) {
                LDSM2(bh[k],  BADDR(MO_WBH, n * 8, 32 * k, WP));
                LDSM2(bl2[k], BADDR(MO_WBL, n * 8, 32 * k, WP));
            }
            #pragma unroll
            for (int m = 0; m < 2; m++)
                #pragma unroll
                for (int k = 0; k < 3; k++) {
                    MMA16816(dB[m][n], Ahf[m][k], bh[k]);
                    MMA16816(dB[m][n], Ahf[m][k], bl2[k]);
                    MMA16816(dB[m][n], Alf[m][k], bh[k]);
                }
        }
    }
    #pragma unroll
    for (int m = 0; m < 2; m++)
        #pragma unroll
        for (int n = 0; n < 12; n++) {
            float2 bias = *(float2*)(s_bb + n * 8 + 2 * tig);
            float v0 = fmaxf(dB[m][n][0] + bias.x, 0.f);
            float v1 = fmaxf(dB[m][n][1] + bias.y, 0.f);
            float v2 = fmaxf(dB[m][n][2] + bias.x, 0.f);
            float v3 = fmaxf(dB[m][n][3] + bias.y, 0.f);
            int r1 = row0 + 16 * m + gid, r2 = r1 + 8;
            int cb = (n * 8 + 2 * tig) * 2;
            __nv_bfloat16 h0, l0, h1, l1;
            split_bf(v0, h0, l0); split_bf(v1, h1, l1);
            *(uint32_t*)(sm_ + MO_XH + r1 * XP + cb) = pack_bf2(h0, h1);
            *(uint32_t*)(sm_ + MO_XL + r1 * XP + cb) = pack_bf2(l0, l1);
            split_bf(v2, h0, l0); split_bf(v3, h1, l1);
            *(uint32_t*)(sm_ + MO_XH + r2 * XP + cb) = pack_bf2(h0, h1);
            *(uint32_t*)(sm_ + MO_XL + r2 * XP + cb) = pack_bf2(l0, l1);
        }
    __syncwarp();

    float dC[2][2][4];
    #pragma unroll
    for (int m = 0; m < 2; m++)
        #pragma unroll
        for (int n = 0; n < 2; n++)
            #pragma unroll
            for (int c = 0; c < 4; c++) dC[m][n][c] = 0.f;
    {
        uint32_t Ahf[2][6][4], Alf[2][6][4];
        #pragma unroll
        for (int m = 0; m < 2; m++)
            #pragma unroll
            for (int k = 0; k < 6; k++) {
                LDSM4(Ahf[m][k], AADDR(MO_XH, row0 + 16 * m, 32 * k, XP));
                LDSM4(Alf[m][k], AADDR(MO_XL, row0 + 16 * m, 32 * k, XP));
            }
        #pragma unroll
        for (int n = 0; n < 2; n++) {
            #pragma unroll
            for (int k = 0; k < 6; k++) {
                uint32_t bh[2], bl2[2];
                LDSM2(bh,  BADDR(MO_WCH, n * 8, 32 * k, CP));
                LDSM2(bl2, BADDR(MO_WCL, n * 8, 32 * k, CP));
                #pragma unroll
                for (int m = 0; m < 2; m++) {
                    MMA16816(dC[m][n], Ahf[m][k], bh);
                    MMA16816(dC[m][n], Ahf[m][k], bl2);
                    MMA16816(dC[m][n], Alf[m][k], bh);
                }
            }
        }
    }

    #pragma unroll
    for (int m = 0; m < 2; m++)
        #pragma unroll
        for (int n = 0; n < 2; n++) {
            int r1 = row0 + 16 * m + gid, r2 = r1 + 8;
            int cc = n * 8 + 2 * tig;
            s_ex[r1 * 18 + cc]     = dC[m][n][0];
            s_ex[r1 * 18 + cc + 1] = dC[m][n][1];
            s_ex[r2 * 18 + cc]     = dC[m][n][2];
            s_ex[r2 * 18 + cc + 1] = dC[m][n][3];
        }
    __syncwarp();

    float o9[9];
    #pragma unroll
    for (int o = 0; o < 9; o++) o9[o] = s_ex[tid * 18 + o] + s_bc[o];

    float xv = x[v];
    float mx = fmaxf(o9[6], fmaxf(o9[7], o9[8]));
    float e0 = expf(o9[6] - mx), e1 = expf(o9[7] - mx), e2 = expf(o9[8] - mx);
    float inv = 1.f / (e0 + e1 + e2);
    float wsm[3] = {e0 * inv, e1 * inv, e2 * inv};

    float p3 = 0.f;
    #pragma unroll
    for (int k = 0; k < 3; k++) {
        float mu = o9[k];
        float scv = o9[3 + k];
        if (scv == 0.f) scv = 1e-9f;
        scv = fabsf(scv);
        float invs = 1.f / scv;
        float l = fabsf(normcdff((xv + 0.5f - mu) * invs)
                      - normcdff((xv - 0.5f - mu) * invs));
        p3 = fmaf(wsm[k], l, p3);
    }

    out[v] = p3;
    #pragma unroll
    for (int o = 0; o < 9; o++)
        out[(size_t)VOX + (size_t)o * VOX + v] = o9[o];
    #undef AADDR
    #undef BADDR
}

extern "C" void kernel_launch(void* const* d_in, const int* in_sizes, int n_in,
                              void* d_out, int out_size) {
    const float* x     = (const float*)d_in[0];
    const float* hyper = (const float*)d_in[1];
    const float* W3    = (const float*)d_in[2];
    const float* b3    = (const float*)d_in[3];
    const float* W1    = (const float*)d_in[4];
    const float* b1    = (const float*)d_in[5];
    const float* Wa    = (const float*)d_in[6];
    const float* ba    = (const float*)d_in[7];
    const float* Wb    = (const float*)d_in[8];
    const float* bb    = (const float*)d_in[9];
    const float* Wc    = (const float*)d_in[10];
    const float* bc    = (const float*)d_in[11];
    float* out = (float*)d_out;

    cudaFuncSetAttribute(conv3d_mma_kernel,
                         cudaFuncAttributeMaxDynamicSharedMemorySize, C_SMEM);
    cudaFuncSetAttribute(conv2d_mma_kernel,
                         cudaFuncAttributeMaxDynamicSharedMemorySize, G_SMEM);
    cudaFuncSetAttribute(mlp_mma_kernel,
                         cudaFuncAttributeMaxDynamicSharedMemorySize, MO_SMEM);

    pack_kernel<<<256, 256>>>(W3, W1);
    im2col_kernel<<<4096, 256>>>(hyper);
    conv2d_mma_kernel<<<36 * KSPLIT, 256, G_SMEM>>>();
    conv3d_mma_kernel<<<192 * 8, 384, C_SMEM>>>(x, b1);
    mlp_mma_kernel<<<VOX / 128, 128, MO_SMEM>>>(x, b3, Wa, ba, Wb, bb, Wc, bc, out);
}

// round 12
// speedup vs baseline: 2.2678x; 1.1042x over previous
#include <cuda_runtime.h>
#include <cuda_bf16.h>
#include <cmath>
#include <cstring>
#include <cstdint>

namespace {
constexpr int D = 192, H = 48, W = 48, PLANE = 2304, VOX = 442368;
constexpr int KK = 3456;
constexpr int KSPLIT = 4, KSEG = 864;

// ---- pack buffer (float offsets) : conv3d weight image ----
constexpr int PK_WT = 663552;
constexpr int WT_U32_HALF = 9504;

// ---- conv3d mma smem (bytes) ----
constexpr int C_XW = 0;
constexpr int C_AH = 24576;
constexpr int C_AL = 79872;
constexpr int C_WH = 135168;
constexpr int C_WL = 173184;
constexpr int C_SMEM = 211200;

// ---- conv2d mma smem (bytes) ----
constexpr int G_AH = 0;
constexpr int G_AL = 7168;
constexpr int G_BH = 14336;
constexpr int G_BL = 35840;
constexpr int G_SMEM = 57344;

// ---- mlp: pre-packed weight image (byte offsets, gmem AND smem-identical) ----
constexpr int PW_AH = 0;        // 48 x 112
constexpr int PW_AL = 5376;
constexpr int PW_BH = 10752;    // 96 x 112
constexpr int PW_BL = 21504;
constexpr int PW_CH = 32256;    // 16 x 208
constexpr int PW_CL = 35584;
constexpr int PW_BA = 38912;    // 48 f32
constexpr int PW_BB = 39104;    // 96 f32
constexpr int PW_BC = 39488;    // 16 f32
constexpr int PW_BYTES = 39552;

// ---- mlp smem (bytes): weights image + X tiles for 256 voxels + exchange ----
constexpr int XP = 208;
constexpr int WP = 112;
constexpr int CP = 208;
constexpr int MO_XH = 39552;    // 256 x 208
constexpr int MO_XL = 92800;
constexpr int MO_EX = 146048;   // 256 x 18 f32
constexpr int MO_SMEM = 164480;
}

__device__ __align__(16) float g_pack[689680];
__device__ float g_x1[(size_t)24 * VOX];
__device__ __align__(16) __nv_bfloat16 g_imH[(size_t)PLANE * KK];
__device__ __align__(16) __nv_bfloat16 g_imL[(size_t)PLANE * KK];
__device__ __align__(16) __nv_bfloat16 g_w3H[(size_t)D * KK];
__device__ __align__(16) __nv_bfloat16 g_w3L[(size_t)D * KK];
__device__ float g_part[(size_t)KSPLIT * VOX];
__device__ __align__(16) uint32_t g_mlpw[PW_BYTES / 4];

// ---- mma.sync helpers (validated) ----
__device__ __forceinline__ uint32_t smem_u32(const void* p) {
    uint32_t a;
    asm("{ .reg .u64 t; cvta.to.shared.u64 t, %1; cvt.u32.u64 %0, t; }"
        : "=r"(a) : "l"(p));
    return a;
}
#define LDSM4(r, addr) \
    asm volatile("ldmatrix.sync.aligned.m8n8.x4.shared.b16 {%0,%1,%2,%3}, [%4];" \
        : "=r"((r)[0]), "=r"((r)[1]), "=r"((r)[2]), "=r"((r)[3]) : "r"(addr))
#define LDSM2(r, addr) \
    asm volatile("ldmatrix.sync.aligned.m8n8.x2.shared.b16 {%0,%1}, [%2];" \
        : "=r"((r)[0]), "=r"((r)[1]) : "r"(addr))
#define MMA16816(d, a, b) \
    asm volatile("mma.sync.aligned.m16n8k16.row.col.f32.bf16.bf16.f32 " \
        "{%0,%1,%2,%3}, {%4,%5,%6,%7}, {%8,%9}, {%0,%1,%2,%3};" \
        : "+f"((d)[0]), "+f"((d)[1]), "+f"((d)[2]), "+f"((d)[3]) \
        : "r"((a)[0]), "r"((a)[1]), "r"((a)[2]), "r"((a)[3]), \
          "r"((b)[0]), "r"((b)[1]))

__device__ __forceinline__ void split_bf(float v, __nv_bfloat16& h, __nv_bfloat16& l) {
    h = __float2bfloat16(v);
    l = __float2bfloat16(v - __bfloat162float(h));
}
__device__ __forceinline__ uint32_t pack_bf2(__nv_bfloat16 a, __nv_bfloat16 b) {
    __nv_bfloat162 t; t.x = a; t.y = b;
    uint32_t u; memcpy(&u, &t, 4); return u;
}

// =============== K0a: pack conv weights + MLP weight image ===============
__global__ void pack_kernel(const float* __restrict__ W3, const float* __restrict__ W1,
                            const float* __restrict__ Wa, const float* __restrict__ ba,
                            const float* __restrict__ Wb, const float* __restrict__ bb,
                            const float* __restrict__ Wc, const float* __restrict__ bc) {
    int nt = gridDim.x * blockDim.x, tid = blockIdx.x * blockDim.x + threadIdx.x;
    // conv3d bf16 weight image
    uint32_t* wt = (uint32_t*)(g_pack + PK_WT);
    for (int j = tid; j < 2 * WT_U32_HALF; j += nt) {
        int half = j / WT_U32_HALF, jj = j % WT_U32_HALF;
        int row = jj / 36, col = jj % 36;
        int kw = row / 24, c = row % 24;
        float v[2];
        #pragma unroll
        for (int s = 0; s < 2; s++) {
            int k = col * 2 + s;
            float val = 0.f;
            if (k <= 60) {
                int kd = k / 11, kh = k % 11;
                int flat = kd * 121 + kh * 11 + kw;
                if (flat < 665) val = W1[c * 1331 + flat];
            }
            v[s] = val;
        }
        __nv_bfloat16 h0, l0, h1, l1;
        split_bf(v[0], h0, l0); split_bf(v[1], h1, l1);
        wt[j] = half ? pack_bf2(l0, l1) : pack_bf2(h0, h1);
    }
    // conv2d weights
    for (int i = tid; i < D * KK; i += nt) {
        int kk = i % KK, d = i / KK;
        int ic = kk / 9, t = kk % 9;
        float v = W3[((size_t)d * 384 + ic) * 9 + t];
        __nv_bfloat16 hv, lv; split_bf(v, hv, lv);
        g_w3H[i] = hv; g_w3L[i] = lv;
    }
    // MLP weight image (smem-identical layout)
    for (int i = tid; i < 48 * 16; i += nt) {
        int u = i / 16, k2 = i % 16;
        int c0 = 2 * k2, c1 = c0 + 1;
        float v0 = (c0 < 25) ? Wa[u * 25 + c0] : 0.f;
        float v1 = (c1 < 25) ? Wa[u * 25 + c1] : 0.f;
        __nv_bfloat16 h0, l0, h1, l1;
        split_bf(v0, h0, l0); split_bf(v1, h1, l1);
        g_mlpw[PW_AH / 4 + u * 28 + k2] = pack_bf2(h0, h1);
        g_mlpw[PW_AL / 4 + u * 28 + k2] = pack_bf2(l0, l1);
    }
    for (int i = tid; i < 96 * 24; i += nt) {
        int u = i / 24, k2 = i % 24;
        float v0 = Wb[u * 48 + 2 * k2], v1 = Wb[u * 48 + 2 * k2 + 1];
        __nv_bfloat16 h0, l0, h1, l1;
        split_bf(v0, h0, l0); split_bf(v1, h1, l1);
        g_mlpw[PW_BH / 4 + u * 28 + k2] = pack_bf2(h0, h1);
        g_mlpw[PW_BL / 4 + u * 28 + k2] = pack_bf2(l0, l1);
    }
    for (int i = tid; i < 16 * 48; i += nt) {
        int u = i / 48, k2 = i % 48;
        float v0 = (u < 9) ? Wc[u * 96 + 2 * k2] : 0.f;
        float v1 = (u < 9) ? Wc[u * 96 + 2 * k2 + 1] : 0.f;
        __nv_bfloat16 h0, l0, h1, l1;
        split_bf(v0, h0, l0); split_bf(v1, h1, l1);
        g_mlpw[PW_CH / 4 + u * 52 + k2] = pack_bf2(h0, h1);
        g_mlpw[PW_CL / 4 + u * 52 + k2] = pack_bf2(l0, l1);
    }
    float* fw = (float*)g_mlpw;
    for (int i = tid; i < 48; i += nt) fw[PW_BA / 4 + i] = ba[i];
    for (int i = tid; i < 96; i += nt) fw[PW_BB / 4 + i] = bb[i];
    for (int i = tid; i < 16; i += nt) fw[PW_BC / 4 + i] = (i < 9) ? bc[i] : 0.f;
    // zero unused tail of Wa (cols 16..27) and Wb (24..27), Wc (48..51) pads
    for (int i = tid; i < 48 * 12; i += nt) {
        int u = i / 12, k2 = 16 + i % 12;
        g_mlpw[PW_AH / 4 + u * 28 + k2] = 0;
        g_mlpw[PW_AL / 4 + u * 28 + k2] = 0;
    }
    for (int i = tid; i < 96 * 4; i += nt) {
        int u = i / 4, k2 = 24 + i % 4;
        g_mlpw[PW_BH / 4 + u * 28 + k2] = 0;
        g_mlpw[PW_BL / 4 + u * 28 + k2] = 0;
    }
    for (int i = tid; i < 16 * 4; i += nt) {
        int u = i / 4, k2 = 48 + i % 4;
        g_mlpw[PW_CH / 4 + u * 52 + k2] = 0;
        g_mlpw[PW_CL / 4 + u * 52 + k2] = 0;
    }
}

// =============== K0b: im2col of hyper, split bf16 ===============
__global__ void im2col_kernel(const float* __restrict__ hyper) {
    size_t N = (size_t)PLANE * KK;
    for (size_t i = (size_t)blockIdx.x * blockDim.x + threadIdx.x; i < N;
         i += (size_t)gridDim.x * blockDim.x) {
        int kk = (int)(i % KK);
        int px = (int)(i / KK);
        int ic = kk / 9, t = kk % 9;
        int ky = t / 3, kx = t % 3;
        int h = px / 48, w = px % 48;
        int gh = h + ky - 1, gw = w + kx - 1;
        float v = 0.f;
        if (gh >= 0 && gh < 48 && gw >= 0 && gw < 48)
            v = hyper[(size_t)ic * PLANE + gh * 48 + gw];
        __nv_bfloat16 hv, lv; split_bf(v, hv, lv);
        g_imH[i] = hv; g_imL[i] = lv;
    }
}

// =============== K1: conv2d GEMM via mma.sync (R10-validated) ===============
__global__ __launch_bounds__(256)
void conv2d_mma_kernel() {
    extern __shared__ char s[];
    const uint32_t sb = smem_u32(s);
    const int tid = threadIdx.x;
    const int lane = tid & 31, warp = tid >> 5;
    const int wm = warp >> 2, wn = warp & 3;
    const int gid = lane >> 2, tig = lane & 3;
    const int amat = lane >> 3, arow = lane & 7;
    const int brow = lane & 7, bk = (lane >> 3) & 1, bn8 = (lane >> 4) & 1;

    const int mblk = blockIdx.x % 36, ksp = blockIdx.x / 36;
    const int px0 = mblk * 64;
    const int k0 = ksp * KSEG;

    float acc[2][6][4];
    #pragma unroll
    for (int mt = 0; mt < 2; mt++)
        #pragma unroll
        for (int n = 0; n < 6; n++)
            #pragma unroll
            for (int c = 0; c < 4; c++) acc[mt][n][c] = 0.f;

    #pragma unroll 1
    for (int ch = 0; ch < 18; ch++) {
        const int koff = k0 + ch * 48;
        for (int id = tid; id < 3072; id += 256) {
            int row = id / 12, r2 = id % 12;
            int half = r2 / 6, q = r2 % 6;
            const uint4* src;
            uint4* dst;
            if (row < 64) {
                size_t base = ((size_t)(px0 + row) * KK + koff);
                src = (const uint4*)((half ? g_imL : g_imH) + base) + q;
                dst = (uint4*)(s + (half ? G_AL : G_AH) + row * 112) + q;
            } else {
                int dch = row - 64;
                size_t base = ((size_t)dch * KK + koff);
                src = (const uint4*)((half ? g_w3L : g_w3H) + base) + q;
                dst = (uint4*)(s + (half ? G_BL : G_BH) + dch * 112) + q;
            }
            *dst = *src;
        }
        __syncthreads();
        #pragma unroll
        for (int j = 0; j < 3; j++) {
            uint32_t Ah[2][4], Al[2][4];
            #pragma unroll
            for (int mt = 0; mt < 2; mt++) {
                uint32_t aoff = (uint32_t)((wm * 32 + mt * 16 + arow + (amat & 1) * 8) * 112
                                           + j * 32 + (amat >> 1) * 16);
                LDSM4(Ah[mt], sb + G_AH + aoff);
                LDSM4(Al[mt], sb + G_AL + aoff);
            }
            uint32_t Bh[3][4], Bl[3][4];
            #pragma unroll
            for (int nb = 0; nb < 3; nb++) {
                uint32_t boff = (uint32_t)((wn * 48 + nb * 16 + brow + bn8 * 8) * 112
                                           + j * 32 + bk * 16);
                LDSM4(Bh[nb], sb + G_BH + boff);
                LDSM4(Bl[nb], sb + G_BL + boff);
            }
            #pragma unroll
            for (int mt = 0; mt < 2; mt++)
                #pragma unroll
                for (int nb = 0; nb < 3; nb++) {
                    MMA16816(acc[mt][nb * 2],     Ah[mt], Bh[nb]);
                    MMA16816(acc[mt][nb * 2],     Ah[mt], Bl[nb]);
                    MMA16816(acc[mt][nb * 2],     Al[mt], Bh[nb]);
                    MMA16816(acc[mt][nb * 2 + 1], Ah[mt], Bh[nb] + 2);
                    MMA16816(acc[mt][nb * 2 + 1], Ah[mt], Bl[nb] + 2);
                    MMA16816(acc[mt][nb * 2 + 1], Al[mt], Bh[nb] + 2);
                }
        }
        __syncthreads();
    }

    float* op = g_part + (size_t)ksp * VOX;
    #pragma unroll
    for (int mt = 0; mt < 2; mt++) {
        int px = px0 + wm * 32 + mt * 16 + gid;
        #pragma unroll
        for (int n = 0; n < 6; n++) {
            int d0 = wn * 48 + n * 8 + 2 * tig;
            op[(size_t)d0 * PLANE + px]           = acc[mt][n][0];
            op[(size_t)(d0 + 1) * PLANE + px]     = acc[mt][n][1];
            op[(size_t)d0 * PLANE + px + 8]       = acc[mt][n][2];
            op[(size_t)(d0 + 1) * PLANE + px + 8] = acc[mt][n][3];
        }
    }
}

// =============== K2: masked conv3d, kw-split across 12 warps (R11-validated) ===============
__global__ __launch_bounds__(384)
void conv3d_mma_kernel(const float* __restrict__ x, const float* __restrict__ b1) {
    extern __shared__ char cs[];
    const uint32_t sb = smem_u32(cs);
    const int tid = threadIdx.x;
    const int lane = tid & 31, wrp = tid >> 5;
    const int hrow = (wrp < 6) ? wrp : wrp - 6;
    const int khalf = (wrp < 6) ? 0 : 1;
    const int gid = lane >> 2, tig = lane & 3;
    const int amat = lane >> 3, arow = lane & 7;
    const int brow = (lane & 15) & 7, bhf = (lane & 15) >> 3;

    const int d = blockIdx.x >> 3, hb = blockIdx.x & 7;
    const int h0 = hb * 6;

    float* s_xw = (float*)(cs + C_XW);
    for (int i = tid; i < 6 * 16 * 64; i += 384) {
        int s = i >> 10, rem = i & 1023;
        int r = rem >> 6, wxx = rem & 63;
        int sd = d - 5 + s, gh = h0 - 5 + r, gw = wxx - 5;
        float v = 0.f;
        if (sd >= 0 && gh >= 0 && gh < 48 && gw >= 0 && gw < 48)
            v = x[(size_t)sd * PLANE + gh * 48 + gw];
        s_xw[i] = v;
    }
    {
        float4* wdst = (float4*)(cs + C_WH);
        const float4* wsrc = (const float4*)(g_pack + PK_WT);
        for (int i = tid; i < (2 * WT_U32_HALF) / 4; i += 384) wdst[i] = wsrc[i];
    }
    __syncthreads();

    {
        int r = tid;
        int hr = r >> 6, wx = r & 63;
        #pragma unroll
        for (int i = 0; i < 32; i++) {
            const int k0 = 2 * i, k1 = 2 * i + 1;
            float v0 = 0.f, v1 = 0.f;
            if (k0 <= 60) v0 = s_xw[((k0 / 11) * 16 + hr + (k0 % 11)) * 64 + wx];
            if (k1 <= 60) v1 = s_xw[((k1 / 11) * 16 + hr + (k1 % 11)) * 64 + wx];
            __nv_bfloat16 h0b, l0b, h1b, l1b;
            split_bf(v0, h0b, l0b); split_bf(v1, h1b, l1b);
            *(uint32_t*)(cs + C_AH + r * 144 + i * 4) = pack_bf2(h0b, h1b);
            *(uint32_t*)(cs + C_AL + r * 144 + i * 4) = pack_bf2(l0b, l1b);
        }
    }
    __syncthreads();

    float acc[3][3][4];
    #pragma unroll
    for (int mt = 0; mt < 3; mt++)
        #pragma unroll
        for (int n = 0; n < 3; n++)
            #pragma unroll
            for (int c = 0; c < 4; c++) acc[mt][n][c] = 0.f;

    const int kw_lo = khalf * 6, kw_hi = khalf ? 11 : 6;
    #pragma unroll 1
    for (int kw = kw_lo; kw < kw_hi; kw++) {
        #pragma unroll
        for (int k16 = 0; k16 < 4; k16++) {
            uint32_t bh[3][2], bl[3][2];
            #pragma unroll
            for (int n = 0; n < 3; n++) {
                uint32_t boff = (uint32_t)((kw * 24 + n * 8 + brow) * 144 + k16 * 32 + bhf * 16);
                LDSM2(bh[n], sb + C_WH + boff);
                LDSM2(bl[n], sb + C_WL + boff);
            }
            #pragma unroll
            for (int mt = 0; mt < 3; mt++) {
                int rowbase = hrow * 64 + mt * 16 + kw;
                uint32_t aoff = (uint32_t)((rowbase + arow + (amat & 1) * 8) * 144
                                           + k16 * 32 + (amat >> 1) * 16);
                uint32_t Ah[4], Al[4];
                LDSM4(Ah, sb + C_AH + aoff);
                LDSM4(Al, sb + C_AL + aoff);
                #pragma unroll
                for (int n = 0; n < 3; n++) {
                    MMA16816(acc[mt][n], Ah, bh[n]);
                    MMA16816(acc[mt][n], Ah, bl[n]);
                    MMA16816(acc[mt][n], Al, bh[n]);
                }
            }
        }
    }

    __syncthreads();
    float* exch = (float*)(cs + C_AL);
    if (khalf == 1) {
        float* e = exch + ((wrp - 6) * 32 + lane) * 37;
        #pragma unroll
        for (int mt = 0; mt < 3; mt++)
            #pragma unroll
            for (int n = 0; n < 3; n++)
                #pragma unroll
                for (int c = 0; c < 4; c++)
                    e[(mt * 3 + n) * 4 + c] = acc[mt][n][c];
    }
    __syncthreads();
    if (khalf == 0) {
        const float* e = exch + (wrp * 32 + lane) * 37;
        float bb1[3][2];
        #pragma unroll
        for (int n = 0; n < 3; n++) {
            int c0 = n * 8 + 2 * tig;
            bb1[n][0] = b1[c0]; bb1[n][1] = b1[c0 + 1];
        }
        const int h_glob = h0 + hrow;
        #pragma unroll
        for (int mt = 0; mt < 3; mt++) {
            int px0 = mt * 16 + gid, px1 = px0 + 8;
            #pragma unroll
            for (int n = 0; n < 3; n++) {
                int c0 = n * 8 + 2 * tig;
                const float* ep = e + (mt * 3 + n) * 4;
                float* o0 = g_x1 + ((size_t)d * 24 + c0) * PLANE + h_glob * 48;
                float* o1 = g_x1 + ((size_t)d * 24 + c0 + 1) * PLANE + h_glob * 48;
                o0[px0] = acc[mt][n][0] + ep[0] + bb1[n][0];
                o1[px0] = acc[mt][n][1] + ep[1] + bb1[n][1];
                o0[px1] = acc[mt][n][2] + ep[2] + bb1[n][0];
                o1[px1] = acc[mt][n][3] + ep[3] + bb1[n][1];
            }
        }
    }
}

// =============== K3: MLP, 256 voxels/CTA, weight image copied verbatim ===============
__global__ __launch_bounds__(256)
void mlp_mma_kernel(const float* __restrict__ x, const float* __restrict__ b3,
                    float* __restrict__ out)
{
    extern __shared__ char sm_[];
    const uint32_t sb = smem_u32(sm_);
    const int tid = threadIdx.x;
    const int lane = tid & 31, w = tid >> 5;
    const int gid = lane >> 2, tig = lane & 3;

    // copy pre-packed weight image (uint4 verbatim)
    for (int i = tid; i < PW_BYTES / 16; i += 256)
        ((uint4*)sm_)[i] = ((const uint4*)g_mlpw)[i];

    float* s_ba = (float*)(sm_ + PW_BA);
    float* s_bb = (float*)(sm_ + PW_BB);
    float* s_bc = (float*)(sm_ + PW_BC);
    float* s_ex = (float*)(sm_ + MO_EX);

    const int v = blockIdx.x * 256 + tid;
    const int dd = v / PLANE, p = v % PLANE;
    {
        const float* xb = g_x1 + (size_t)dd * 24 * PLANE + p;
        float t[26];
        #pragma unroll
        for (int c = 0; c < 24; c++) t[c] = xb[(size_t)c * PLANE];
        t[24] = g_part[v] + g_part[VOX + v] + g_part[2 * (size_t)VOX + v]
              + g_part[3 * (size_t)VOX + v] + b3[dd];
        t[25] = 0.f;
        #pragma unroll
        for (int i = 0; i < 16; i++) {
            float v0 = (2 * i < 26) ? t[2 * i] : 0.f;
            float v1 = (2 * i + 1 < 26) ? t[2 * i + 1] : 0.f;
            __nv_bfloat16 h0, l0, h1, l1;
            split_bf(v0, h0, l0); split_bf(v1, h1, l1);
            *(uint32_t*)(sm_ + MO_XH + tid * XP + 4 * i) = pack_bf2(h0, h1);
            *(uint32_t*)(sm_ + MO_XL + tid * XP + 4 * i) = pack_bf2(l0, l1);
        }
    }
    __syncthreads();

    const int amat = lane >> 3, arow = lane & 7;
    const int bl15 = lane & 15, brow = bl15 & 7, bhf = bl15 >> 3;
    #define AADDR(off, row0, kb, P) \
        (sb + (off) + (uint32_t)(((row0) + arow + (amat & 1) * 8) * (P) + (kb) + (amat >> 1) * 16))
    #define BADDR(off, n0, kb, P) \
        (sb + (off) + (uint32_t)(((n0) + brow) * (P) + (kb) + bhf * 16))

    const int row0 = w * 32;

    float dA[2][6][4];
    #pragma unroll
    for (int m = 0; m < 2; m++)
        #pragma unroll
        for (int n = 0; n < 6; n++)
            #pragma unroll
            for (int c = 0; c < 4; c++) dA[m][n][c] = 0.f;
    {
        uint32_t Ahf[2][2][4], Alf[2][2][4];
        #pragma unroll
        for (int m = 0; m < 2; m++)
            #pragma unroll
            for (int k = 0; k < 2; k++) {
                LDSM4(Ahf[m][k], AADDR(MO_XH, row0 + 16 * m, 32 * k, XP));
                LDSM4(Alf[m][k], AADDR(MO_XL, row0 + 16 * m, 32 * k, XP));
            }
        #pragma unroll
        for (int n = 0; n < 6; n++) {
            uint32_t bh[2][2], bl2[2][2];
            #pragma unroll
            for (int k = 0; k < 2; k++) {
                LDSM2(bh[k],  BADDR(PW_AH, n * 8, 32 * k, WP));
                LDSM2(bl2[k], BADDR(PW_AL, n * 8, 32 * k, WP));
            }
            #pragma unroll
            for (int m = 0; m < 2; m++)
                #pragma unroll
                for (int k = 0; k < 2; k++) {
                    MMA16816(dA[m][n], Ahf[m][k], bh[k]);
                    MMA16816(dA[m][n], Ahf[m][k], bl2[k]);
                    MMA16816(dA[m][n], Alf[m][k], bh[k]);
                }
        }
    }
    #pragma unroll
    for (int m = 0; m < 2; m++)
        #pragma unroll
        for (int n = 0; n < 6; n++) {
            float2 bias = *(float2*)(s_ba + n * 8 + 2 * tig);
            float v0 = fmaxf(dA[m][n][0] + bias.x, 0.f);
            float v1 = fmaxf(dA[m][n][1] + bias.y, 0.f);
            float v2 = fmaxf(dA[m][n][2] + bias.x, 0.f);
            float v3 = fmaxf(dA[m][n][3] + bias.y, 0.f);
            int r1 = row0 + 16 * m + gid, r2 = r1 + 8;
            int cb = (n * 8 + 2 * tig) * 2;
            __nv_bfloat16 h0, l0, h1, l1;
            split_bf(v0, h0, l0); split_bf(v1, h1, l1);
            *(uint32_t*)(sm_ + MO_XH + r1 * XP + cb) = pack_bf2(h0, h1);
            *(uint32_t*)(sm_ + MO_XL + r1 * XP + cb) = pack_bf2(l0, l1);
            split_bf(v2, h0, l0); split_bf(v3, h1, l1);
            *(uint32_t*)(sm_ + MO_XH + r2 * XP + cb) = pack_bf2(h0, h1);
            *(uint32_t*)(sm_ + MO_XL + r2 * XP + cb) = pack_bf2(l0, l1);
        }
    __syncwarp();

    float dB[2][12][4];
    #pragma unroll
    for (int m = 0; m < 2; m++)
        #pragma unroll
        for (int n = 0; n < 12; n++)
            #pragma unroll
            for (int c = 0; c < 4; c++) dB[m][n][c] = 0.f;
    {
        uint32_t Ahf[2][3][4], Alf[2][3][4];
        #pragma unroll
        for (int m = 0; m < 2; m++)
            #pragma unroll
            for (int k = 0; k < 3; k++) {
                LDSM4(Ahf[m][k], AADDR(MO_XH, row0 + 16 * m, 32 * k, XP));
                LDSM4(Alf[m][k], AADDR(MO_XL, row0 + 16 * m, 32 * k, XP));
            }
        #pragma unroll
        for (int n = 0; n < 12; n++) {
            uint32_t bh[3][2], bl2[3][2];
            #pragma unroll
            for (int k = 0; k < 3; k++) {
                LDSM2(bh[k],  BADDR(PW_BH, n * 8, 32 * k, WP));
                LDSM2(bl2[k], BADDR(PW_BL, n * 8, 32 * k, WP));
            }
            #pragma unroll
            for (int m = 0; m < 2; m++)
                #pragma unroll
                for (int k = 0; k < 3; k++) {
                    MMA16816(dB[m][n], Ahf[m][k], bh[k]);
                    MMA16816(dB[m][n], Ahf[m][k], bl2[k]);
                    MMA16816(dB[m][n], Alf[m][k], bh[k]);
                }
        }
    }
    #pragma unroll
    for (int m = 0; m < 2; m++)
        #pragma unroll
        for (int n = 0; n < 12; n++) {
            float2 bias = *(float2*)(s_bb + n * 8 + 2 * tig);
            float v0 = fmaxf(dB[m][n][0] + bias.x, 0.f);
            float v1 = fmaxf(dB[m][n][1] + bias.y, 0.f);
            float v2 = fmaxf(dB[m][n][2] + bias.x, 0.f);
            float v3 = fmaxf(dB[m][n][3] + bias.y, 0.f);
            int r1 = row0 + 16 * m + gid, r2 = r1 + 8;
            int cb = (n * 8 + 2 * tig) * 2;
            __nv_bfloat16 h0, l0, h1, l1;
            split_bf(v0, h0, l0); split_bf(v1, h1, l1);
            *(uint32_t*)(sm_ + MO_XH + r1 * XP + cb) = pack_bf2(h0, h1);
            *(uint32_t*)(sm_ + MO_XL + r1 * XP + cb) = pack_bf2(l0, l1);
            split_bf(v2, h0, l0); split_bf(v3, h1, l1);
            *(uint32_t*)(sm_ + MO_XH + r2 * XP + cb) = pack_bf2(h0, h1);
            *(uint32_t*)(sm_ + MO_XL + r2 * XP + cb) = pack_bf2(l0, l1);
        }
    __syncwarp();

    float dC[2][2][4];
    #pragma unroll
    for (int m = 0; m < 2; m++)
        #pragma unroll
        for (int n = 0; n < 2; n++)
            #pragma unroll
            for (int c = 0; c < 4; c++) dC[m][n][c] = 0.f;
    {
        uint32_t Ahf[2][6][4], Alf[2][6][4];
        #pragma unroll
        for (int m = 0; m < 2; m++)
            #pragma unroll
            for (int k = 0; k < 6; k++) {
                LDSM4(Ahf[m][k], AADDR(MO_XH, row0 + 16 * m, 32 * k, XP));
                LDSM4(Alf[m][k], AADDR(MO_XL, row0 + 16 * m, 32 * k, XP));
            }
        #pragma unroll
        for (int n = 0; n < 2; n++) {
            #pragma unroll
            for (int k = 0; k < 6; k++) {
                uint32_t bh[2], bl2[2];
                LDSM2(bh,  BADDR(PW_CH, n * 8, 32 * k, CP));
                LDSM2(bl2, BADDR(PW_CL, n * 8, 32 * k, CP));
                #pragma unroll
                for (int m = 0; m < 2; m++) {
                    MMA16816(dC[m][n], Ahf[m][k], bh);
                    MMA16816(dC[m][n], Ahf[m][k], bl2);
                    MMA16816(dC[m][n], Alf[m][k], bh);
                }
            }
        }
    }

    #pragma unroll
    for (int m = 0; m < 2; m++)
        #pragma unroll
        for (int n = 0; n < 2; n++) {
            int r1 = row0 + 16 * m + gid, r2 = r1 + 8;
            int cc = n * 8 + 2 * tig;
            s_ex[r1 * 18 + cc]     = dC[m][n][0];
            s_ex[r1 * 18 + cc + 1] = dC[m][n][1];
            s_ex[r2 * 18 + cc]     = dC[m][n][2];
            s_ex[r2 * 18 + cc + 1] = dC[m][n][3];
        }
    __syncwarp();

    float o9[9];
    #pragma unroll
    for (int o = 0; o < 9; o++) o9[o] = s_ex[tid * 18 + o] + s_bc[o];

    float xv = x[v];
    float mx = fmaxf(o9[6], fmaxf(o9[7], o9[8]));
    float e0 = expf(o9[6] - mx), e1 = expf(o9[7] - mx), e2 = expf(o9[8] - mx);
    float inv = 1.f / (e0 + e1 + e2);
    float wsm[3] = {e0 * inv, e1 * inv, e2 * inv};

    float p3 = 0.f;
    #pragma unroll
    for (int k = 0; k < 3; k++) {
        float mu = o9[k];
        float scv = o9[3 + k];
        if (scv == 0.f) scv = 1e-9f;
        scv = fabsf(scv);
        float invs = 1.f / scv;
        float l = fabsf(normcdff((xv + 0.5f - mu) * invs)
                      - normcdff((xv - 0.5f - mu) * invs));
        p3 = fmaf(wsm[k], l, p3);
    }

    out[v] = p3;
    #pragma unroll
    for (int o = 0; o < 9; o++)
        out[(size_t)VOX + (size_t)o * VOX + v] = o9[o];
    #undef AADDR
    #undef BADDR
}

extern "C" void kernel_launch(void* const* d_in, const int* in_sizes, int n_in,
                              void* d_out, int out_size) {
    const float* x     = (const float*)d_in[0];
    const float* hyper = (const float*)d_in[1];
    const float* W3    = (const float*)d_in[2];
    const float* b3    = (const float*)d_in[3];
    const float* W1    = (const float*)d_in[4];
    const float* b1    = (const float*)d_in[5];
    const float* Wa    = (const float*)d_in[6];
    const float* ba    = (const float*)d_in[7];
    const float* Wb    = (const float*)d_in[8];
    const float* bb    = (const float*)d_in[9];
    const float* Wc    = (const float*)d_in[10];
    const float* bc    = (const float*)d_in[11];
    float* out = (float*)d_out;

    cudaFuncSetAttribute(conv3d_mma_kernel,
                         cudaFuncAttributeMaxDynamicSharedMemorySize, C_SMEM);
    cudaFuncSetAttribute(conv2d_mma_kernel,
                         cudaFuncAttributeMaxDynamicSharedMemorySize, G_SMEM);
    cudaFuncSetAttribute(mlp_mma_kernel,
                         cudaFuncAttributeMaxDynamicSharedMemorySize, MO_SMEM);

    pack_kernel<<<256, 256>>>(W3, W1, Wa, ba, Wb, bb, Wc, bc);
    im2col_kernel<<<4096, 256>>>(hyper);
    conv2d_mma_kernel<<<36 * KSPLIT, 256, G_SMEM>>>();
    conv3d_mma_kernel<<<192 * 8, 384, C_SMEM>>>(x, b1);
    mlp_mma_kernel<<<VOX / 256, 256, MO_SMEM>>>(x, b3, out);
}

// round 13
// speedup vs baseline: 2.3149x; 1.0208x over previous
#include <cuda_runtime.h>
#include <cuda_bf16.h>
#include <cmath>
#include <cstring>
#include <cstdint>

namespace {
constexpr int D = 192, H = 48, W = 48, PLANE = 2304, VOX = 442368;
constexpr int KK = 3456;
constexpr int KSPLIT = 4, KSEG = 864;

// ---- pack buffer (float offsets) : conv3d weight image ----
constexpr int PK_WT = 663552;
constexpr int WT_U32_HALF = 9504;

// ---- conv3d mma smem (bytes) ----
constexpr int C_XW = 0;
constexpr int C_AH = 24576;
constexpr int C_AL = 79872;
constexpr int C_WH = 135168;
constexpr int C_WL = 173184;
constexpr int C_SMEM = 211200;

// ---- conv2d mma smem (bytes): kc=96, pitch 208B ----
constexpr int G_AH = 0;            // 64 x 208
constexpr int G_AL = 13312;
constexpr int G_BH = 26624;        // 192 x 208
constexpr int G_BL = 66560;
constexpr int G_SMEM = 106496;

// ---- mlp: pre-packed weight image (byte offsets, gmem AND smem-identical) ----
constexpr int PW_AH = 0;        // 48 x 112
constexpr int PW_AL = 5376;
constexpr int PW_BH = 10752;    // 96 x 112
constexpr int PW_BL = 21504;
constexpr int PW_CH = 32256;    // 16 x 208
constexpr int PW_CL = 35584;
constexpr int PW_BA = 38912;
constexpr int PW_BB = 39104;
constexpr int PW_BC = 39488;
constexpr int PW_BYTES = 39552;

// ---- mlp smem ----
constexpr int XP = 208;
constexpr int WP = 112;
constexpr int CP = 208;
constexpr int MO_XH = 39552;    // 256 x 208
constexpr int MO_XL = 92800;
constexpr int MO_EX = 146048;   // 256 x 18 f32
constexpr int MO_SMEM = 164480;
}

__device__ __align__(16) float g_pack[689680];
__device__ float g_x1[(size_t)24 * VOX];
__device__ __align__(16) __nv_bfloat16 g_imH[(size_t)PLANE * KK];
__device__ __align__(16) __nv_bfloat16 g_imL[(size_t)PLANE * KK];
__device__ __align__(16) __nv_bfloat16 g_w3H[(size_t)D * KK];
__device__ __align__(16) __nv_bfloat16 g_w3L[(size_t)D * KK];
__device__ float g_part[(size_t)KSPLIT * VOX];
__device__ __align__(16) uint32_t g_mlpw[PW_BYTES / 4];

// ---- mma.sync helpers (validated) ----
__device__ __forceinline__ uint32_t smem_u32(const void* p) {
    uint32_t a;
    asm("{ .reg .u64 t; cvta.to.shared.u64 t, %1; cvt.u32.u64 %0, t; }"
        : "=r"(a) : "l"(p));
    return a;
}
#define LDSM4(r, addr) \
    asm volatile("ldmatrix.sync.aligned.m8n8.x4.shared.b16 {%0,%1,%2,%3}, [%4];" \
        : "=r"((r)[0]), "=r"((r)[1]), "=r"((r)[2]), "=r"((r)[3]) : "r"(addr))
#define LDSM2(r, addr) \
    asm volatile("ldmatrix.sync.aligned.m8n8.x2.shared.b16 {%0,%1}, [%2];" \
        : "=r"((r)[0]), "=r"((r)[1]) : "r"(addr))
#define MMA16816(d, a, b) \
    asm volatile("mma.sync.aligned.m16n8k16.row.col.f32.bf16.bf16.f32 " \
        "{%0,%1,%2,%3}, {%4,%5,%6,%7}, {%8,%9}, {%0,%1,%2,%3};" \
        : "+f"((d)[0]), "+f"((d)[1]), "+f"((d)[2]), "+f"((d)[3]) \
        : "r"((a)[0]), "r"((a)[1]), "r"((a)[2]), "r"((a)[3]), \
          "r"((b)[0]), "r"((b)[1]))

__device__ __forceinline__ void split_bf(float v, __nv_bfloat16& h, __nv_bfloat16& l) {
    h = __float2bfloat16(v);
    l = __float2bfloat16(v - __bfloat162float(h));
}
__device__ __forceinline__ uint32_t pack_bf2(__nv_bfloat16 a, __nv_bfloat16 b) {
    __nv_bfloat162 t; t.x = a; t.y = b;
    uint32_t u; memcpy(&u, &t, 4); return u;
}

// =============== K0a: pack conv weights + MLP weight image ===============
__global__ void pack_kernel(const float* __restrict__ W3, const float* __restrict__ W1,
                            const float* __restrict__ Wa, const float* __restrict__ ba,
                            const float* __restrict__ Wb, const float* __restrict__ bb,
                            const float* __restrict__ Wc, const float* __restrict__ bc) {
    int nt = gridDim.x * blockDim.x, tid = blockIdx.x * blockDim.x + threadIdx.x;
    uint32_t* wt = (uint32_t*)(g_pack + PK_WT);
    for (int j = tid; j < 2 * WT_U32_HALF; j += nt) {
        int half = j / WT_U32_HALF, jj = j % WT_U32_HALF;
        int row = jj / 36, col = jj % 36;
        int kw = row / 24, c = row % 24;
        float v[2];
        #pragma unroll
        for (int s = 0; s < 2; s++) {
            int k = col * 2 + s;
            float val = 0.f;
            if (k <= 60) {
                int kd = k / 11, kh = k % 11;
                int flat = kd * 121 + kh * 11 + kw;
                if (flat < 665) val = W1[c * 1331 + flat];
            }
            v[s] = val;
        }
        __nv_bfloat16 h0, l0, h1, l1;
        split_bf(v[0], h0, l0); split_bf(v[1], h1, l1);
        wt[j] = half ? pack_bf2(l0, l1) : pack_bf2(h0, h1);
    }
    for (int i = tid; i < D * KK; i += nt) {
        int kk = i % KK, d = i / KK;
        int ic = kk / 9, t = kk % 9;
        float v = W3[((size_t)d * 384 + ic) * 9 + t];
        __nv_bfloat16 hv, lv; split_bf(v, hv, lv);
        g_w3H[i] = hv; g_w3L[i] = lv;
    }
    for (int i = tid; i < 48 * 16; i += nt) {
        int u = i / 16, k2 = i % 16;
        int c0 = 2 * k2, c1 = c0 + 1;
        float v0 = (c0 < 25) ? Wa[u * 25 + c0] : 0.f;
        float v1 = (c1 < 25) ? Wa[u * 25 + c1] : 0.f;
        __nv_bfloat16 h0, l0, h1, l1;
        split_bf(v0, h0, l0); split_bf(v1, h1, l1);
        g_mlpw[PW_AH / 4 + u * 28 + k2] = pack_bf2(h0, h1);
        g_mlpw[PW_AL / 4 + u * 28 + k2] = pack_bf2(l0, l1);
    }
    for (int i = tid; i < 96 * 24; i += nt) {
        int u = i / 24, k2 = i % 24;
        float v0 = Wb[u * 48 + 2 * k2], v1 = Wb[u * 48 + 2 * k2 + 1];
        __nv_bfloat16 h0, l0, h1, l1;
        split_bf(v0, h0, l0); split_bf(v1, h1, l1);
        g_mlpw[PW_BH / 4 + u * 28 + k2] = pack_bf2(h0, h1);
        g_mlpw[PW_BL / 4 + u * 28 + k2] = pack_bf2(l0, l1);
    }
    for (int i = tid; i < 16 * 48; i += nt) {
        int u = i / 48, k2 = i % 48;
        float v0 = (u < 9) ? Wc[u * 96 + 2 * k2] : 0.f;
        float v1 = (u < 9) ? Wc[u * 96 + 2 * k2 + 1] : 0.f;
        __nv_bfloat16 h0, l0, h1, l1;
        split_bf(v0, h0, l0); split_bf(v1, h1, l1);
        g_mlpw[PW_CH / 4 + u * 52 + k2] = pack_bf2(h0, h1);
        g_mlpw[PW_CL / 4 + u * 52 + k2] = pack_bf2(l0, l1);
    }
    float* fw = (float*)g_mlpw;
    for (int i = tid; i < 48; i += nt) fw[PW_BA / 4 + i] = ba[i];
    for (int i = tid; i < 96; i += nt) fw[PW_BB / 4 + i] = bb[i];
    for (int i = tid; i < 16; i += nt) fw[PW_BC / 4 + i] = (i < 9) ? bc[i] : 0.f;
    for (int i = tid; i < 48 * 12; i += nt) {
        int u = i / 12, k2 = 16 + i % 12;
        g_mlpw[PW_AH / 4 + u * 28 + k2] = 0;
        g_mlpw[PW_AL / 4 + u * 28 + k2] = 0;
    }
    for (int i = tid; i < 96 * 4; i += nt) {
        int u = i / 4, k2 = 24 + i % 4;
        g_mlpw[PW_BH / 4 + u * 28 + k2] = 0;
        g_mlpw[PW_BL / 4 + u * 28 + k2] = 0;
    }
    for (int i = tid; i < 16 * 4; i += nt) {
        int u = i / 4, k2 = 48 + i % 4;
        g_mlpw[PW_CH / 4 + u * 52 + k2] = 0;
        g_mlpw[PW_CL / 4 + u * 52 + k2] = 0;
    }
}

// =============== K0b: im2col v2 — 32-bit indexing, 4 px per block ===============
__global__ __launch_bounds__(256)
void im2col_kernel(const float* __restrict__ hyper) {
    int kk = blockIdx.x * 256 + threadIdx.x;
    if (kk >= KK) return;
    int ic = kk / 9;
    int t = kk - ic * 9;
    int ky = t / 3 - 1, kx = t - (t / 3) * 3 - 1;
    const float* hp = hyper + (size_t)ic * PLANE;
    int px0 = blockIdx.y * 4;
    #pragma unroll
    for (int j = 0; j < 4; j++) {
        int px = px0 + j;
        int h = px / 48, w = px - h * 48;
        int gh = h + ky, gw = w + kx;
        float v = 0.f;
        if (gh >= 0 && gh < 48 && gw >= 0 && gw < 48)
            v = hp[gh * 48 + gw];
        __nv_bfloat16 hv, lv; split_bf(v, hv, lv);
        size_t o = (size_t)px * KK + kk;
        g_imH[o] = hv; g_imL[o] = lv;
    }
}

// =============== K1: conv2d GEMM, kc=96 chunks ===============
__global__ __launch_bounds__(256)
void conv2d_mma_kernel() {
    extern __shared__ char s[];
    const uint32_t sb = smem_u32(s);
    const int tid = threadIdx.x;
    const int lane = tid & 31, warp = tid >> 5;
    const int wm = warp >> 2, wn = warp & 3;
    const int gid = lane >> 2, tig = lane & 3;
    const int amat = lane >> 3, arow = lane & 7;
    const int brow = lane & 7, bk = (lane >> 3) & 1, bn8 = (lane >> 4) & 1;

    const int mblk = blockIdx.x % 36, ksp = blockIdx.x / 36;
    const int px0 = mblk * 64;
    const int k0 = ksp * KSEG;

    float acc[2][6][4];
    #pragma unroll
    for (int mt = 0; mt < 2; mt++)
        #pragma unroll
        for (int n = 0; n < 6; n++)
            #pragma unroll
            for (int c = 0; c < 4; c++) acc[mt][n][c] = 0.f;

    #pragma unroll 1
    for (int ch = 0; ch < 9; ch++) {
        const int koff = k0 + ch * 96;
        // stage: 256 rows (64 A + 192 B) x 2 halves x 12 uint4 (192B)
        for (int id = tid; id < 6144; id += 256) {
            int row = id / 24, r2 = id % 24;
            int half = r2 / 12, q = r2 % 12;
            const uint4* src;
            uint4* dst;
            if (row < 64) {
                size_t base = ((size_t)(px0 + row) * KK + koff);
                src = (const uint4*)((half ? g_imL : g_imH) + base) + q;
                dst = (uint4*)(s + (half ? G_AL : G_AH) + row * 208) + q;
            } else {
                int dch = row - 64;
                size_t base = ((size_t)dch * KK + koff);
                src = (const uint4*)((half ? g_w3L : g_w3H) + base) + q;
                dst = (uint4*)(s + (half ? G_BL : G_BH) + dch * 208) + q;
            }
            *dst = *src;
        }
        __syncthreads();
        #pragma unroll
        for (int j = 0; j < 6; j++) {
            uint32_t Ah[2][4], Al[2][4];
            #pragma unroll
            for (int mt = 0; mt < 2; mt++) {
                uint32_t aoff = (uint32_t)((wm * 32 + mt * 16 + arow + (amat & 1) * 8) * 208
                                           + j * 32 + (amat >> 1) * 16);
                LDSM4(Ah[mt], sb + G_AH + aoff);
                LDSM4(Al[mt], sb + G_AL + aoff);
            }
            uint32_t Bh[3][4], Bl[3][4];
            #pragma unroll
            for (int nb = 0; nb < 3; nb++) {
                uint32_t boff = (uint32_t)((wn * 48 + nb * 16 + brow + bn8 * 8) * 208
                                           + j * 32 + bk * 16);
                LDSM4(Bh[nb], sb + G_BH + boff);
                LDSM4(Bl[nb], sb + G_BL + boff);
            }
            #pragma unroll
            for (int mt = 0; mt < 2; mt++)
                #pragma unroll
                for (int nb = 0; nb < 3; nb++) {
                    MMA16816(acc[mt][nb * 2],     Ah[mt], Bh[nb]);
                    MMA16816(acc[mt][nb * 2],     Ah[mt], Bl[nb]);
                    MMA16816(acc[mt][nb * 2],     Al[mt], Bh[nb]);
                    MMA16816(acc[mt][nb * 2 + 1], Ah[mt], Bh[nb] + 2);
                    MMA16816(acc[mt][nb * 2 + 1], Ah[mt], Bl[nb] + 2);
                    MMA16816(acc[mt][nb * 2 + 1], Al[mt], Bh[nb] + 2);
                }
        }
        __syncthreads();
    }

    float* op = g_part + (size_t)ksp * VOX;
    #pragma unroll
    for (int mt = 0; mt < 2; mt++) {
        int px = px0 + wm * 32 + mt * 16 + gid;
        #pragma unroll
        for (int n = 0; n < 6; n++) {
            int d0 = wn * 48 + n * 8 + 2 * tig;
            op[(size_t)d0 * PLANE + px]           = acc[mt][n][0];
            op[(size_t)(d0 + 1) * PLANE + px]     = acc[mt][n][1];
            op[(size_t)d0 * PLANE + px + 8]       = acc[mt][n][2];
            op[(size_t)(d0 + 1) * PLANE + px + 8] = acc[mt][n][3];
        }
    }
}

// =============== K2: masked conv3d, kw-split across 12 warps (R11-validated) ===============
__global__ __launch_bounds__(384)
void conv3d_mma_kernel(const float* __restrict__ x, const float* __restrict__ b1) {
    extern __shared__ char cs[];
    const uint32_t sb = smem_u32(cs);
    const int tid = threadIdx.x;
    const int lane = tid & 31, wrp = tid >> 5;
    const int hrow = (wrp < 6) ? wrp : wrp - 6;
    const int khalf = (wrp < 6) ? 0 : 1;
    const int gid = lane >> 2, tig = lane & 3;
    const int amat = lane >> 3, arow = lane & 7;
    const int brow = (lane & 15) & 7, bhf = (lane & 15) >> 3;

    const int d = blockIdx.x >> 3, hb = blockIdx.x & 7;
    const int h0 = hb * 6;

    float* s_xw = (float*)(cs + C_XW);
    for (int i = tid; i < 6 * 16 * 64; i += 384) {
        int s = i >> 10, rem = i & 1023;
        int r = rem >> 6, wxx = rem & 63;
        int sd = d - 5 + s, gh = h0 - 5 + r, gw = wxx - 5;
        float v = 0.f;
        if (sd >= 0 && gh >= 0 && gh < 48 && gw >= 0 && gw < 48)
            v = x[(size_t)sd * PLANE + gh * 48 + gw];
        s_xw[i] = v;
    }
    {
        float4* wdst = (float4*)(cs + C_WH);
        const float4* wsrc = (const float4*)(g_pack + PK_WT);
        for (int i = tid; i < (2 * WT_U32_HALF) / 4; i += 384) wdst[i] = wsrc[i];
    }
    __syncthreads();

    {
        int r = tid;
        int hr = r >> 6, wx = r & 63;
        #pragma unroll
        for (int i = 0; i < 32; i++) {
            const int k0 = 2 * i, k1 = 2 * i + 1;
            float v0 = 0.f, v1 = 0.f;
            if (k0 <= 60) v0 = s_xw[((k0 / 11) * 16 + hr + (k0 % 11)) * 64 + wx];
            if (k1 <= 60) v1 = s_xw[((k1 / 11) * 16 + hr + (k1 % 11)) * 64 + wx];
            __nv_bfloat16 h0b, l0b, h1b, l1b;
            split_bf(v0, h0b, l0b); split_bf(v1, h1b, l1b);
            *(uint32_t*)(cs + C_AH + r * 144 + i * 4) = pack_bf2(h0b, h1b);
            *(uint32_t*)(cs + C_AL + r * 144 + i * 4) = pack_bf2(l0b, l1b);
        }
    }
    __syncthreads();

    float acc[3][3][4];
    #pragma unroll
    for (int mt = 0; mt < 3; mt++)
        #pragma unroll
        for (int n = 0; n < 3; n++)
            #pragma unroll
            for (int c = 0; c < 4; c++) acc[mt][n][c] = 0.f;

    const int kw_lo = khalf * 6, kw_hi = khalf ? 11 : 6;
    #pragma unroll 1
    for (int kw = kw_lo; kw < kw_hi; kw++) {
        #pragma unroll
        for (int k16 = 0; k16 < 4; k16++) {
            uint32_t bh[3][2], bl[3][2];
            #pragma unroll
            for (int n = 0; n < 3; n++) {
                uint32_t boff = (uint32_t)((kw * 24 + n * 8 + brow) * 144 + k16 * 32 + bhf * 16);
                LDSM2(bh[n], sb + C_WH + boff);
                LDSM2(bl[n], sb + C_WL + boff);
            }
            #pragma unroll
            for (int mt = 0; mt < 3; mt++) {
                int rowbase = hrow * 64 + mt * 16 + kw;
                uint32_t aoff = (uint32_t)((rowbase + arow + (amat & 1) * 8) * 144
                                           + k16 * 32 + (amat >> 1) * 16);
                uint32_t Ah[4], Al[4];
                LDSM4(Ah, sb + C_AH + aoff);
                LDSM4(Al, sb + C_AL + aoff);
                #pragma unroll
                for (int n = 0; n < 3; n++) {
                    MMA16816(acc[mt][n], Ah, bh[n]);
                    MMA16816(acc[mt][n], Ah, bl[n]);
                    MMA16816(acc[mt][n], Al, bh[n]);
                }
            }
        }
    }

    __syncthreads();
    float* exch = (float*)(cs + C_AL);
    if (khalf == 1) {
        float* e = exch + ((wrp - 6) * 32 + lane) * 37;
        #pragma unroll
        for (int mt = 0; mt < 3; mt++)
            #pragma unroll
            for (int n = 0; n < 3; n++)
                #pragma unroll
                for (int c = 0; c < 4; c++)
                    e[(mt * 3 + n) * 4 + c] = acc[mt][n][c];
    }
    __syncthreads();
    if (khalf == 0) {
        const float* e = exch + (wrp * 32 + lane) * 37;
        float bb1[3][2];
        #pragma unroll
        for (int n = 0; n < 3; n++) {
            int c0 = n * 8 + 2 * tig;
            bb1[n][0] = b1[c0]; bb1[n][1] = b1[c0 + 1];
        }
        const int h_glob = h0 + hrow;
        #pragma unroll
        for (int mt = 0; mt < 3; mt++) {
            int px0 = mt * 16 + gid, px1 = px0 + 8;
            #pragma unroll
            for (int n = 0; n < 3; n++) {
                int c0 = n * 8 + 2 * tig;
                const float* ep = e + (mt * 3 + n) * 4;
                float* o0 = g_x1 + ((size_t)d * 24 + c0) * PLANE + h_glob * 48;
                float* o1 = g_x1 + ((size_t)d * 24 + c0 + 1) * PLANE + h_glob * 48;
                o0[px0] = acc[mt][n][0] + ep[0] + bb1[n][0];
                o1[px0] = acc[mt][n][1] + ep[1] + bb1[n][1];
                o0[px1] = acc[mt][n][2] + ep[2] + bb1[n][0];
                o1[px1] = acc[mt][n][3] + ep[3] + bb1[n][1];
            }
        }
    }
}

// =============== K3: MLP, 256 voxels/CTA (R12-validated) ===============
__global__ __launch_bounds__(256)
void mlp_mma_kernel(const float* __restrict__ x, const float* __restrict__ b3,
                    float* __restrict__ out)
{
    extern __shared__ char sm_[];
    const uint32_t sb = smem_u32(sm_);
    const int tid = threadIdx.x;
    const int lane = tid & 31, w = tid >> 5;
    const int gid = lane >> 2, tig = lane & 3;

    for (int i = tid; i < PW_BYTES / 16; i += 256)
        ((uint4*)sm_)[i] = ((const uint4*)g_mlpw)[i];

    float* s_ba = (float*)(sm_ + PW_BA);
    float* s_bb = (float*)(sm_ + PW_BB);
    float* s_bc = (float*)(sm_ + PW_BC);
    float* s_ex = (float*)(sm_ + MO_EX);

    const int v = blockIdx.x * 256 + tid;
    const int dd = v / PLANE, p = v % PLANE;
    {
        const float* xb = g_x1 + (size_t)dd * 24 * PLANE + p;
        float t[26];
        #pragma unroll
        for (int c = 0; c < 24; c++) t[c] = xb[(size_t)c * PLANE];
        t[24] = g_part[v] + g_part[VOX + v] + g_part[2 * (size_t)VOX + v]
              + g_part[3 * (size_t)VOX + v] + b3[dd];
        t[25] = 0.f;
        #pragma unroll
        for (int i = 0; i < 16; i++) {
            float v0 = (2 * i < 26) ? t[2 * i] : 0.f;
            float v1 = (2 * i + 1 < 26) ? t[2 * i + 1] : 0.f;
            __nv_bfloat16 h0, l0, h1, l1;
            split_bf(v0, h0, l0); split_bf(v1, h1, l1);
            *(uint32_t*)(sm_ + MO_XH + tid * XP + 4 * i) = pack_bf2(h0, h1);
            *(uint32_t*)(sm_ + MO_XL + tid * XP + 4 * i) = pack_bf2(l0, l1);
        }
    }
    __syncthreads();

    const int amat = lane >> 3, arow = lane & 7;
    const int bl15 = lane & 15, brow = bl15 & 7, bhf = bl15 >> 3;
    #define AADDR(off, row0, kb, P) \
        (sb + (off) + (uint32_t)(((row0) + arow + (amat & 1) * 8) * (P) + (kb) + (amat >> 1) * 16))
    #define BADDR(off, n0, kb, P) \
        (sb + (off) + (uint32_t)(((n0) + brow) * (P) + (kb) + bhf * 16))

    const int row0 = w * 32;

    float dA[2][6][4];
    #pragma unroll
    for (int m = 0; m < 2; m++)
        #pragma unroll
        for (int n = 0; n < 6; n++)
            #pragma unroll
            for (int c = 0; c < 4; c++) dA[m][n][c] = 0.f;
    {
        uint32_t Ahf[2][2][4], Alf[2][2][4];
        #pragma unroll
        for (int m = 0; m < 2; m++)
            #pragma unroll
            for (int k = 0; k < 2; k++) {
                LDSM4(Ahf[m][k], AADDR(MO_XH, row0 + 16 * m, 32 * k, XP));
                LDSM4(Alf[m][k], AADDR(MO_XL, row0 + 16 * m, 32 * k, XP));
            }
        #pragma unroll
        for (int n = 0; n < 6; n++) {
            uint32_t bh[2][2], bl2[2][2];
            #pragma unroll
            for (int k = 0; k < 2; k++) {
                LDSM2(bh[k],  BADDR(PW_AH, n * 8, 32 * k, WP));
                LDSM2(bl2[k], BADDR(PW_AL, n * 8, 32 * k, WP));
            }
            #pragma unroll
            for (int m = 0; m < 2; m++)
                #pragma unroll
                for (int k = 0; k < 2; k++) {
                    MMA16816(dA[m][n], Ahf[m][k], bh[k]);
                    MMA16816(dA[m][n], Ahf[m][k], bl2[k]);
                    MMA16816(dA[m][n], Alf[m][k], bh[k]);
                }
        }
    }
    #pragma unroll
    for (int m = 0; m < 2; m++)
        #pragma unroll
        for (int n = 0; n < 6; n++) {
            float2 bias = *(float2*)(s_ba + n * 8 + 2 * tig);
            float v0 = fmaxf(dA[m][n][0] + bias.x, 0.f);
            float v1 = fmaxf(dA[m][n][1] + bias.y, 0.f);
            float v2 = fmaxf(dA[m][n][2] + bias.x, 0.f);
            float v3 = fmaxf(dA[m][n][3] + bias.y, 0.f);
            int r1 = row0 + 16 * m + gid, r2 = r1 + 8;
            int cb = (n * 8 + 2 * tig) * 2;
            __nv_bfloat16 h0, l0, h1, l1;
            split_bf(v0, h0, l0); split_bf(v1, h1, l1);
            *(uint32_t*)(sm_ + MO_XH + r1 * XP + cb) = pack_bf2(h0, h1);
            *(uint32_t*)(sm_ + MO_XL + r1 * XP + cb) = pack_bf2(l0, l1);
            split_bf(v2, h0, l0); split_bf(v3, h1, l1);
            *(uint32_t*)(sm_ + MO_XH + r2 * XP + cb) = pack_bf2(h0, h1);
            *(uint32_t*)(sm_ + MO_XL + r2 * XP + cb) = pack_bf2(l0, l1);
        }
    __syncwarp();

    float dB[2][12][4];
    #pragma unroll
    for (int m = 0; m < 2; m++)
        #pragma unroll
        for (int n = 0; n < 12; n++)
            #pragma unroll
            for (int c = 0; c < 4; c++) dB[m][n][c] = 0.f;
    {
        uint32_t Ahf[2][3][4], Alf[2][3][4];
        #pragma unroll
        for (int m = 0; m < 2; m++)
            #pragma unroll
            for (int k = 0; k < 3; k++) {
                LDSM4(Ahf[m][k], AADDR(MO_XH, row0 + 16 * m, 32 * k, XP));
                LDSM4(Alf[m][k], AADDR(MO_XL, row0 + 16 * m, 32 * k, XP));
            }
        #pragma unroll
        for (int n = 0; n < 12; n++) {
            uint32_t bh[3][2], bl2[3][2];
            #pragma unroll
            for (int k = 0; k < 3; k++) {
                LDSM2(bh[k],  BADDR(PW_BH, n * 8, 32 * k, WP));
                LDSM2(bl2[k], BADDR(PW_BL, n * 8, 32 * k, WP));
            }
            #pragma unroll
            for (int m = 0; m < 2; m++)
                #pragma unroll
                for (int k = 0; k < 3; k++) {
                    MMA16816(dB[m][n], Ahf[m][k], bh[k]);
                    MMA16816(dB[m][n], Ahf[m][k], bl2[k]);
                    MMA16816(dB[m][n], Alf[m][k], bh[k]);
                }
        }
    }
    #pragma unroll
    for (int m = 0; m < 2; m++)
        #pragma unroll
        for (int n = 0; n < 12; n++) {
            float2 bias = *(float2*)(s_bb + n * 8 + 2 * tig);
            float v0 = fmaxf(dB[m][n][0] + bias.x, 0.f);
            float v1 = fmaxf(dB[m][n][1] + bias.y, 0.f);
            float v2 = fmaxf(dB[m][n][2] + bias.x, 0.f);
            float v3 = fmaxf(dB[m][n][3] + bias.y, 0.f);
            int r1 = row0 + 16 * m + gid, r2 = r1 + 8;
            int cb = (n * 8 + 2 * tig) * 2;
            __nv_bfloat16 h0, l0, h1, l1;
            split_bf(v0, h0, l0); split_bf(v1, h1, l1);
            *(uint32_t*)(sm_ + MO_XH + r1 * XP + cb) = pack_bf2(h0, h1);
            *(uint32_t*)(sm_ + MO_XL + r1 * XP + cb) = pack_bf2(l0, l1);
            split_bf(v2, h0, l0); split_bf(v3, h1, l1);
            *(uint32_t*)(sm_ + MO_XH + r2 * XP + cb) = pack_bf2(h0, h1);
            *(uint32_t*)(sm_ + MO_XL + r2 * XP + cb) = pack_bf2(l0, l1);
        }
    __syncwarp();

    float dC[2][2][4];
    #pragma unroll
    for (int m = 0; m < 2; m++)
        #pragma unroll
        for (int n = 0; n < 2; n++)
            #pragma unroll
            for (int c = 0; c < 4; c++) dC[m][n][c] = 0.f;
    {
        uint32_t Ahf[2][6][4], Alf[2][6][4];
        #pragma unroll
        for (int m = 0; m < 2; m++)
            #pragma unroll
            for (int k = 0; k < 6; k++) {
                LDSM4(Ahf[m][k], AADDR(MO_XH, row0 + 16 * m, 32 * k, XP));
                LDSM4(Alf[m][k], AADDR(MO_XL, row0 + 16 * m, 32 * k, XP));
            }
        #pragma unroll
        for (int n = 0; n < 2; n++) {
            #pragma unroll
            for (int k = 0; k < 6; k++) {
                uint32_t bh[2], bl2[2];
                LDSM2(bh,  BADDR(PW_CH, n * 8, 32 * k, CP));
                LDSM2(bl2, BADDR(PW_CL, n * 8, 32 * k, CP));
                #pragma unroll
                for (int m = 0; m < 2; m++) {
                    MMA16816(dC[m][n], Ahf[m][k], bh);
                    MMA16816(dC[m][n], Ahf[m][k], bl2);
                    MMA16816(dC[m][n], Alf[m][k], bh);
                }
            }
        }
    }

    #pragma unroll
    for (int m = 0; m < 2; m++)
        #pragma unroll
        for (int n = 0; n < 2; n++) {
            int r1 = row0 + 16 * m + gid, r2 = r1 + 8;
            int cc = n * 8 + 2 * tig;
            s_ex[r1 * 18 + cc]     = dC[m][n][0];
            s_ex[r1 * 18 + cc + 1] = dC[m][n][1];
            s_ex[r2 * 18 + cc]     = dC[m][n][2];
            s_ex[r2 * 18 + cc + 1] = dC[m][n][3];
        }
    __syncwarp();

    float o9[9];
    #pragma unroll
    for (int o = 0; o < 9; o++) o9[o] = s_ex[tid * 18 + o] + s_bc[o];

    float xv = x[v];
    float mx = fmaxf(o9[6], fmaxf(o9[7], o9[8]));
    float e0 = expf(o9[6] - mx), e1 = expf(o9[7] - mx), e2 = expf(o9[8] - mx);
    float inv = 1.f / (e0 + e1 + e2);
    float wsm[3] = {e0 * inv, e1 * inv, e2 * inv};

    float p3 = 0.f;
    #pragma unroll
    for (int k = 0; k < 3; k++) {
        float mu = o9[k];
        float scv = o9[3 + k];
        if (scv == 0.f) scv = 1e-9f;
        scv = fabsf(scv);
        float invs = 1.f / scv;
        float l = fabsf(normcdff((xv + 0.5f - mu) * invs)
                      - normcdff((xv - 0.5f - mu) * invs));
        p3 = fmaf(wsm[k], l, p3);
    }

    out[v] = p3;
    #pragma unroll
    for (int o = 0; o < 9; o++)
        out[(size_t)VOX + (size_t)o * VOX + v] = o9[o];
    #undef AADDR
    #undef BADDR
}

extern "C" void kernel_launch(void* const* d_in, const int* in_sizes, int n_in,
                              void* d_out, int out_size) {
    const float* x     = (const float*)d_in[0];
    const float* hyper = (const float*)d_in[1];
    const float* W3    = (const float*)d_in[2];
    const float* b3    = (const float*)d_in[3];
    const float* W1    = (const float*)d_in[4];
    const float* b1    = (const float*)d_in[5];
    const float* Wa    = (const float*)d_in[6];
    const float* ba    = (const float*)d_in[7];
    const float* Wb    = (const float*)d_in[8];
    const float* bb    = (const float*)d_in[9];
    const float* Wc    = (const float*)d_in[10];
    const float* bc    = (const float*)d_in[11];
    float* out = (float*)d_out;

    cudaFuncSetAttribute(conv3d_mma_kernel,
                         cudaFuncAttributeMaxDynamicSharedMemorySize, C_SMEM);
    cudaFuncSetAttribute(conv2d_mma_kernel,
                         cudaFuncAttributeMaxDynamicSharedMemorySize, G_SMEM);
    cudaFuncSetAttribute(mlp_mma_kernel,
                         cudaFuncAttributeMaxDynamicSharedMemorySize, MO_SMEM);

    pack_kernel<<<256, 256>>>(W3, W1, Wa, ba, Wb, bb, Wc, bc);
    im2col_kernel<<<dim3((KK + 255) / 256, PLANE / 4), 256>>>(hyper);
    conv2d_mma_kernel<<<36 * KSPLIT, 256, G_SMEM>>>();
    conv3d_mma_kernel<<<192 * 8, 384, C_SMEM>>>(x, b1);
    mlp_mma_kernel<<<VOX / 256, 256, MO_SMEM>>>(x, b3, out);
}

// round 14
// speedup vs baseline: 2.6486x; 1.1441x over previous
#include <cuda_runtime.h>
#include <cuda_bf16.h>
#include <cmath>
#include <cstring>
#include <cstdint>

namespace {
constexpr int D = 192, H = 48, W = 48, PLANE = 2304, VOX = 442368;
constexpr int KK = 3456;
constexpr int KSPLIT = 4, KSEG = 864;

// ---- pack buffer (float offsets) : conv3d weight image ----
constexpr int PK_WT = 663552;
constexpr int WT_U32_HALF = 9504;

// ---- conv3d mma smem (bytes) ----
constexpr int C_XW = 0;
constexpr int C_AH = 24576;
constexpr int C_AL = 79872;
constexpr int C_WH = 135168;
constexpr int C_WL = 173184;
constexpr int C_SMEM = 211200;

// ---- conv2d mma smem: double-buffered kc=48, pitch 112B ----
constexpr int G_AH = 0;            // 64 x 112
constexpr int G_AL = 7168;
constexpr int G_BH = 14336;        // 192 x 112
constexpr int G_BL = 35840;
constexpr int GB   = 57344;        // one buffer
constexpr int G_SMEM = 2 * GB;     // 114688

// ---- mlp: pre-packed weight image ----
constexpr int PW_AH = 0;
constexpr int PW_AL = 5376;
constexpr int PW_BH = 10752;
constexpr int PW_BL = 21504;
constexpr int PW_CH = 32256;
constexpr int PW_CL = 35584;
constexpr int PW_BA = 38912;
constexpr int PW_BB = 39104;
constexpr int PW_BC = 39488;
constexpr int PW_BYTES = 39552;

// ---- mlp smem ----
constexpr int XP = 208;
constexpr int WP = 112;
constexpr int CP = 208;
constexpr int MO_XH = 39552;
constexpr int MO_XL = 92800;
constexpr int MO_EX = 146048;
constexpr int MO_SMEM = 164480;
}

__device__ __align__(16) float g_pack[689680];
__device__ float g_x1[(size_t)24 * VOX];
__device__ __align__(16) __nv_bfloat16 g_imH[(size_t)PLANE * KK];
__device__ __align__(16) __nv_bfloat16 g_imL[(size_t)PLANE * KK];
__device__ __align__(16) __nv_bfloat16 g_w3H[(size_t)D * KK];
__device__ __align__(16) __nv_bfloat16 g_w3L[(size_t)D * KK];
__device__ float g_part[(size_t)KSPLIT * VOX];
__device__ __align__(16) uint32_t g_mlpw[PW_BYTES / 4];

// ---- mma.sync helpers (validated) ----
__device__ __forceinline__ uint32_t smem_u32(const void* p) {
    uint32_t a;
    asm("{ .reg .u64 t; cvta.to.shared.u64 t, %1; cvt.u32.u64 %0, t; }"
        : "=r"(a) : "l"(p));
    return a;
}
#define LDSM4(r, addr) \
    asm volatile("ldmatrix.sync.aligned.m8n8.x4.shared.b16 {%0,%1,%2,%3}, [%4];" \
        : "=r"((r)[0]), "=r"((r)[1]), "=r"((r)[2]), "=r"((r)[3]) : "r"(addr))
#define LDSM2(r, addr) \
    asm volatile("ldmatrix.sync.aligned.m8n8.x2.shared.b16 {%0,%1}, [%2];" \
        : "=r"((r)[0]), "=r"((r)[1]) : "r"(addr))
#define MMA16816(d, a, b) \
    asm volatile("mma.sync.aligned.m16n8k16.row.col.f32.bf16.bf16.f32 " \
        "{%0,%1,%2,%3}, {%4,%5,%6,%7}, {%8,%9}, {%0,%1,%2,%3};" \
        : "+f"((d)[0]), "+f"((d)[1]), "+f"((d)[2]), "+f"((d)[3]) \
        : "r"((a)[0]), "r"((a)[1]), "r"((a)[2]), "r"((a)[3]), \
          "r"((b)[0]), "r"((b)[1]))

__device__ __forceinline__ void split_bf(float v, __nv_bfloat16& h, __nv_bfloat16& l) {
    h = __float2bfloat16(v);
    l = __float2bfloat16(v - __bfloat162float(h));
}
__device__ __forceinline__ uint32_t pack_bf2(__nv_bfloat16 a, __nv_bfloat16 b) {
    __nv_bfloat162 t; t.x = a; t.y = b;
    uint32_t u; memcpy(&u, &t, 4); return u;
}
// Fast truncation split: hi = top 16 bits (exact), lo = rn-bf16 of residual.
// {lo16 of result} = value0, {hi16} = value1 — matches pack_bf2 ordering.
__device__ __forceinline__ void fsplit2(float v0, float v1,
                                        uint32_t& hi, uint32_t& lo) {
    uint32_t u0 = __float_as_uint(v0), u1 = __float_as_uint(v1);
    asm("prmt.b32 %0, %1, %2, 0x7632;" : "=r"(hi) : "r"(u0), "r"(u1));
    float l0 = v0 - __uint_as_float(u0 & 0xFFFF0000u);
    float l1 = v1 - __uint_as_float(u1 & 0xFFFF0000u);
    asm("cvt.rn.bf16x2.f32 %0, %1, %2;" : "=r"(lo) : "f"(l1), "f"(l0));
}

// =============== K0a: pack conv weights + MLP weight image ===============
__global__ void pack_kernel(const float* __restrict__ W3, const float* __restrict__ W1,
                            const float* __restrict__ Wa, const float* __restrict__ ba,
                            const float* __restrict__ Wb, const float* __restrict__ bb,
                            const float* __restrict__ Wc, const float* __restrict__ bc) {
    int nt = gridDim.x * blockDim.x, tid = blockIdx.x * blockDim.x + threadIdx.x;
    uint32_t* wt = (uint32_t*)(g_pack + PK_WT);
    for (int j = tid; j < 2 * WT_U32_HALF; j += nt) {
        int half = j / WT_U32_HALF, jj = j % WT_U32_HALF;
        int row = jj / 36, col = jj % 36;
        int kw = row / 24, c = row % 24;
        float v[2];
        #pragma unroll
        for (int s = 0; s < 2; s++) {
            int k = col * 2 + s;
            float val = 0.f;
            if (k <= 60) {
                int kd = k / 11, kh = k % 11;
                int flat = kd * 121 + kh * 11 + kw;
                if (flat < 665) val = W1[c * 1331 + flat];
            }
            v[s] = val;
        }
        __nv_bfloat16 h0, l0, h1, l1;
        split_bf(v[0], h0, l0); split_bf(v[1], h1, l1);
        wt[j] = half ? pack_bf2(l0, l1) : pack_bf2(h0, h1);
    }
    for (int i = tid; i < D * KK; i += nt) {
        int kk = i % KK, d = i / KK;
        int ic = kk / 9, t = kk % 9;
        float v = W3[((size_t)d * 384 + ic) * 9 + t];
        __nv_bfloat16 hv, lv; split_bf(v, hv, lv);
        g_w3H[i] = hv; g_w3L[i] = lv;
    }
    for (int i = tid; i < 48 * 16; i += nt) {
        int u = i / 16, k2 = i % 16;
        int c0 = 2 * k2, c1 = c0 + 1;
        float v0 = (c0 < 25) ? Wa[u * 25 + c0] : 0.f;
        float v1 = (c1 < 25) ? Wa[u * 25 + c1] : 0.f;
        __nv_bfloat16 h0, l0, h1, l1;
        split_bf(v0, h0, l0); split_bf(v1, h1, l1);
        g_mlpw[PW_AH / 4 + u * 28 + k2] = pack_bf2(h0, h1);
        g_mlpw[PW_AL / 4 + u * 28 + k2] = pack_bf2(l0, l1);
    }
    for (int i = tid; i < 96 * 24; i += nt) {
        int u = i / 24, k2 = i % 24;
        float v0 = Wb[u * 48 + 2 * k2], v1 = Wb[u * 48 + 2 * k2 + 1];
        __nv_bfloat16 h0, l0, h1, l1;
        split_bf(v0, h0, l0); split_bf(v1, h1, l1);
        g_mlpw[PW_BH / 4 + u * 28 + k2] = pack_bf2(h0, h1);
        g_mlpw[PW_BL / 4 + u * 28 + k2] = pack_bf2(l0, l1);
    }
    for (int i = tid; i < 16 * 48; i += nt) {
        int u = i / 48, k2 = i % 48;
        float v0 = (u < 9) ? Wc[u * 96 + 2 * k2] : 0.f;
        float v1 = (u < 9) ? Wc[u * 96 + 2 * k2 + 1] : 0.f;
        __nv_bfloat16 h0, l0, h1, l1;
        split_bf(v0, h0, l0); split_bf(v1, h1, l1);
        g_mlpw[PW_CH / 4 + u * 52 + k2] = pack_bf2(h0, h1);
        g_mlpw[PW_CL / 4 + u * 52 + k2] = pack_bf2(l0, l1);
    }
    float* fw = (float*)g_mlpw;
    for (int i = tid; i < 48; i += nt) fw[PW_BA / 4 + i] = ba[i];
    for (int i = tid; i < 96; i += nt) fw[PW_BB / 4 + i] = bb[i];
    for (int i = tid; i < 16; i += nt) fw[PW_BC / 4 + i] = (i < 9) ? bc[i] : 0.f;
    for (int i = tid; i < 48 * 12; i += nt) {
        int u = i / 12, k2 = 16 + i % 12;
        g_mlpw[PW_AH / 4 + u * 28 + k2] = 0;
        g_mlpw[PW_AL / 4 + u * 28 + k2] = 0;
    }
    for (int i = tid; i < 96 * 4; i += nt) {
        int u = i / 4, k2 = 24 + i % 4;
        g_mlpw[PW_BH / 4 + u * 28 + k2] = 0;
        g_mlpw[PW_BL / 4 + u * 28 + k2] = 0;
    }
    for (int i = tid; i < 16 * 4; i += nt) {
        int u = i / 4, k2 = 48 + i % 4;
        g_mlpw[PW_CH / 4 + u * 52 + k2] = 0;
        g_mlpw[PW_CL / 4 + u * 52 + k2] = 0;
    }
}

// =============== K0b: im2col v2 (R13-validated) ===============
__global__ __launch_bounds__(256)
void im2col_kernel(const float* __restrict__ hyper) {
    int kk = blockIdx.x * 256 + threadIdx.x;
    if (kk >= KK) return;
    int ic = kk / 9;
    int t = kk - ic * 9;
    int ky = t / 3 - 1, kx = t - (t / 3) * 3 - 1;
    const float* hp = hyper + (size_t)ic * PLANE;
    int px0 = blockIdx.y * 4;
    #pragma unroll
    for (int j = 0; j < 4; j++) {
        int px = px0 + j;
        int h = px / 48, w = px - h * 48;
        int gh = h + ky, gw = w + kx;
        float v = 0.f;
        if (gh >= 0 && gh < 48 && gw >= 0 && gw < 48)
            v = hp[gh * 48 + gw];
        __nv_bfloat16 hv, lv; split_bf(v, hv, lv);
        size_t o = (size_t)px * KK + kk;
        g_imH[o] = hv; g_imL[o] = lv;
    }
}

// =============== K1: conv2d GEMM, cp.async double-buffered kc=48 ===============
__global__ __launch_bounds__(256)
void conv2d_mma_kernel() {
    extern __shared__ char s[];
    const uint32_t sb = smem_u32(s);
    const int tid = threadIdx.x;
    const int lane = tid & 31, warp = tid >> 5;
    const int wm = warp >> 2, wn = warp & 3;
    const int gid = lane >> 2, tig = lane & 3;
    const int amat = lane >> 3, arow = lane & 7;
    const int brow = lane & 7, bk = (lane >> 3) & 1, bn8 = (lane >> 4) & 1;

    const int mblk = blockIdx.x % 36, ksp = blockIdx.x / 36;
    const int px0 = mblk * 64;
    const int k0 = ksp * KSEG;

    auto stage = [&](int buf, int koff) {
        char* base = s + buf * GB;
        for (int id = tid; id < 3072; id += 256) {
            int row = id / 12, r2 = id % 12;
            int half = r2 / 6, q = r2 % 6;
            const __nv_bfloat16* src;
            char* dst;
            if (row < 64) {
                src = (half ? g_imL : g_imH) + ((size_t)(px0 + row) * KK + koff);
                dst = base + (half ? G_AL : G_AH) + row * 112;
            } else {
                int dch = row - 64;
                src = (half ? g_w3L : g_w3H) + ((size_t)dch * KK + koff);
                dst = base + (half ? G_BL : G_BH) + dch * 112;
            }
            uint32_t ds = smem_u32(dst + q * 16);
            asm volatile("cp.async.cg.shared.global [%0], [%1], 16;"
                         :: "r"(ds), "l"((const char*)src + q * 16));
        }
        asm volatile("cp.async.commit_group;" ::: "memory");
    };

    float acc[2][6][4];
    #pragma unroll
    for (int mt = 0; mt < 2; mt++)
        #pragma unroll
        for (int n = 0; n < 6; n++)
            #pragma unroll
            for (int c = 0; c < 4; c++) acc[mt][n][c] = 0.f;

    stage(0, k0);
    #pragma unroll 1
    for (int ch = 0; ch < 18; ch++) {
        if (ch + 1 < 18) {
            stage((ch + 1) & 1, k0 + (ch + 1) * 48);
            asm volatile("cp.async.wait_group 1;" ::: "memory");
        } else {
            asm volatile("cp.async.wait_group 0;" ::: "memory");
        }
        __syncthreads();
        const uint32_t bbase = sb + (uint32_t)((ch & 1) * GB);
        #pragma unroll
        for (int j = 0; j < 3; j++) {
            uint32_t Ah[2][4], Al[2][4];
            #pragma unroll
            for (int mt = 0; mt < 2; mt++) {
                uint32_t aoff = (uint32_t)((wm * 32 + mt * 16 + arow + (amat & 1) * 8) * 112
                                           + j * 32 + (amat >> 1) * 16);
                LDSM4(Ah[mt], bbase + G_AH + aoff);
                LDSM4(Al[mt], bbase + G_AL + aoff);
            }
            uint32_t Bh[3][4], Bl[3][4];
            #pragma unroll
            for (int nb = 0; nb < 3; nb++) {
                uint32_t boff = (uint32_t)((wn * 48 + nb * 16 + brow + bn8 * 8) * 112
                                           + j * 32 + bk * 16);
                LDSM4(Bh[nb], bbase + G_BH + boff);
                LDSM4(Bl[nb], bbase + G_BL + boff);
            }
            #pragma unroll
            for (int mt = 0; mt < 2; mt++)
                #pragma unroll
                for (int nb = 0; nb < 3; nb++) {
                    MMA16816(acc[mt][nb * 2],     Ah[mt], Bh[nb]);
                    MMA16816(acc[mt][nb * 2],     Ah[mt], Bl[nb]);
                    MMA16816(acc[mt][nb * 2],     Al[mt], Bh[nb]);
                    MMA16816(acc[mt][nb * 2 + 1], Ah[mt], Bh[nb] + 2);
                    MMA16816(acc[mt][nb * 2 + 1], Ah[mt], Bl[nb] + 2);
                    MMA16816(acc[mt][nb * 2 + 1], Al[mt], Bh[nb] + 2);
                }
        }
        __syncthreads();
    }

    float* op = g_part + (size_t)ksp * VOX;
    #pragma unroll
    for (int mt = 0; mt < 2; mt++) {
        int px = px0 + wm * 32 + mt * 16 + gid;
        #pragma unroll
        for (int n = 0; n < 6; n++) {
            int d0 = wn * 48 + n * 8 + 2 * tig;
            op[(size_t)d0 * PLANE + px]           = acc[mt][n][0];
            op[(size_t)(d0 + 1) * PLANE + px]     = acc[mt][n][1];
            op[(size_t)d0 * PLANE + px + 8]       = acc[mt][n][2];
            op[(size_t)(d0 + 1) * PLANE + px + 8] = acc[mt][n][3];
        }
    }
}

// =============== K2: masked conv3d, kw-split across 12 warps (R11-validated) ===============
__global__ __launch_bounds__(384)
void conv3d_mma_kernel(const float* __restrict__ x, const float* __restrict__ b1) {
    extern __shared__ char cs[];
    const uint32_t sb = smem_u32(cs);
    const int tid = threadIdx.x;
    const int lane = tid & 31, wrp = tid >> 5;
    const int hrow = (wrp < 6) ? wrp : wrp - 6;
    const int khalf = (wrp < 6) ? 0 : 1;
    const int gid = lane >> 2, tig = lane & 3;
    const int amat = lane >> 3, arow = lane & 7;
    const int brow = (lane & 15) & 7, bhf = (lane & 15) >> 3;

    const int d = blockIdx.x >> 3, hb = blockIdx.x & 7;
    const int h0 = hb * 6;

    float* s_xw = (float*)(cs + C_XW);
    for (int i = tid; i < 6 * 16 * 64; i += 384) {
        int s = i >> 10, rem = i & 1023;
        int r = rem >> 6, wxx = rem & 63;
        int sd = d - 5 + s, gh = h0 - 5 + r, gw = wxx - 5;
        float v = 0.f;
        if (sd >= 0 && gh >= 0 && gh < 48 && gw >= 0 && gw < 48)
            v = x[(size_t)sd * PLANE + gh * 48 + gw];
        s_xw[i] = v;
    }
    {
        float4* wdst = (float4*)(cs + C_WH);
        const float4* wsrc = (const float4*)(g_pack + PK_WT);
        for (int i = tid; i < (2 * WT_U32_HALF) / 4; i += 384) wdst[i] = wsrc[i];
    }
    __syncthreads();

    {
        int r = tid;
        int hr = r >> 6, wx = r & 63;
        #pragma unroll
        for (int i = 0; i < 32; i++) {
            const int k0 = 2 * i, k1 = 2 * i + 1;
            float v0 = 0.f, v1 = 0.f;
            if (k0 <= 60) v0 = s_xw[((k0 / 11) * 16 + hr + (k0 % 11)) * 64 + wx];
            if (k1 <= 60) v1 = s_xw[((k1 / 11) * 16 + hr + (k1 % 11)) * 64 + wx];
            uint32_t hv, lv;
            fsplit2(v0, v1, hv, lv);
            *(uint32_t*)(cs + C_AH + r * 144 + i * 4) = hv;
            *(uint32_t*)(cs + C_AL + r * 144 + i * 4) = lv;
        }
    }
    __syncthreads();

    float acc[3][3][4];
    #pragma unroll
    for (int mt = 0; mt < 3; mt++)
        #pragma unroll
        for (int n = 0; n < 3; n++)
            #pragma unroll
            for (int c = 0; c < 4; c++) acc[mt][n][c] = 0.f;

    const int kw_lo = khalf * 6, kw_hi = khalf ? 11 : 6;
    #pragma unroll 1
    for (int kw = kw_lo; kw < kw_hi; kw++) {
        #pragma unroll
        for (int k16 = 0; k16 < 4; k16++) {
            uint32_t bh[3][2], bl[3][2];
            #pragma unroll
            for (int n = 0; n < 3; n++) {
                uint32_t boff = (uint32_t)((kw * 24 + n * 8 + brow) * 144 + k16 * 32 + bhf * 16);
                LDSM2(bh[n], sb + C_WH + boff);
                LDSM2(bl[n], sb + C_WL + boff);
            }
            #pragma unroll
            for (int mt = 0; mt < 3; mt++) {
                int rowbase = hrow * 64 + mt * 16 + kw;
                uint32_t aoff = (uint32_t)((rowbase + arow + (amat & 1) * 8) * 144
                                           + k16 * 32 + (amat >> 1) * 16);
                uint32_t Ah[4], Al[4];
                LDSM4(Ah, sb + C_AH + aoff);
                LDSM4(Al, sb + C_AL + aoff);
                #pragma unroll
                for (int n = 0; n < 3; n++) {
                    MMA16816(acc[mt][n], Ah, bh[n]);
                    MMA16816(acc[mt][n], Ah, bl[n]);
                    MMA16816(acc[mt][n], Al, bh[n]);
                }
            }
        }
    }

    __syncthreads();
    float* exch = (float*)(cs + C_AL);
    if (khalf == 1) {
        float* e = exch + ((wrp - 6) * 32 + lane) * 37;
        #pragma unroll
        for (int mt = 0; mt < 3; mt++)
            #pragma unroll
            for (int n = 0; n < 3; n++)
                #pragma unroll
                for (int c = 0; c < 4; c++)
                    e[(mt * 3 + n) * 4 + c] = acc[mt][n][c];
    }
    __syncthreads();
    if (khalf == 0) {
        const float* e = exch + (wrp * 32 + lane) * 37;
        float bb1[3][2];
        #pragma unroll
        for (int n = 0; n < 3; n++) {
            int c0 = n * 8 + 2 * tig;
            bb1[n][0] = b1[c0]; bb1[n][1] = b1[c0 + 1];
        }
        const int h_glob = h0 + hrow;
        #pragma unroll
        for (int mt = 0; mt < 3; mt++) {
            int px0 = mt * 16 + gid, px1 = px0 + 8;
            #pragma unroll
            for (int n = 0; n < 3; n++) {
                int c0 = n * 8 + 2 * tig;
                const float* ep = e + (mt * 3 + n) * 4;
                float* o0 = g_x1 + ((size_t)d * 24 + c0) * PLANE + h_glob * 48;
                float* o1 = g_x1 + ((size_t)d * 24 + c0 + 1) * PLANE + h_glob * 48;
                o0[px0] = acc[mt][n][0] + ep[0] + bb1[n][0];
                o1[px0] = acc[mt][n][1] + ep[1] + bb1[n][1];
                o0[px1] = acc[mt][n][2] + ep[2] + bb1[n][0];
                o1[px1] = acc[mt][n][3] + ep[3] + bb1[n][1];
            }
        }
    }
}

// =============== K3: MLP, 256 voxels/CTA, fast splits ===============
__global__ __launch_bounds__(256)
void mlp_mma_kernel(const float* __restrict__ x, const float* __restrict__ b3,
                    float* __restrict__ out)
{
    extern __shared__ char sm_[];
    const uint32_t sb = smem_u32(sm_);
    const int tid = threadIdx.x;
    const int lane = tid & 31, w = tid >> 5;
    const int gid = lane >> 2, tig = lane & 3;

    for (int i = tid; i < PW_BYTES / 16; i += 256)
        ((uint4*)sm_)[i] = ((const uint4*)g_mlpw)[i];

    float* s_ba = (float*)(sm_ + PW_BA);
    float* s_bb = (float*)(sm_ + PW_BB);
    float* s_bc = (float*)(sm_ + PW_BC);
    float* s_ex = (float*)(sm_ + MO_EX);

    const int v = blockIdx.x * 256 + tid;
    const int dd = v / PLANE, p = v % PLANE;
    {
        const float* xb = g_x1 + (size_t)dd * 24 * PLANE + p;
        float t[26];
        #pragma unroll
        for (int c = 0; c < 24; c++) t[c] = xb[(size_t)c * PLANE];
        t[24] = g_part[v] + g_part[VOX + v] + g_part[2 * (size_t)VOX + v]
              + g_part[3 * (size_t)VOX + v] + b3[dd];
        t[25] = 0.f;
        #pragma unroll
        for (int i = 0; i < 13; i++) {
            uint32_t hv, lv;
            fsplit2(t[2 * i], t[2 * i + 1], hv, lv);
            *(uint32_t*)(sm_ + MO_XH + tid * XP + 4 * i) = hv;
            *(uint32_t*)(sm_ + MO_XL + tid * XP + 4 * i) = lv;
        }
        #pragma unroll
        for (int i = 13; i < 16; i++) {
            *(uint32_t*)(sm_ + MO_XH + tid * XP + 4 * i) = 0;
            *(uint32_t*)(sm_ + MO_XL + tid * XP + 4 * i) = 0;
        }
    }
    __syncthreads();

    const int amat = lane >> 3, arow = lane & 7;
    const int bl15 = lane & 15, brow = bl15 & 7, bhf = bl15 >> 3;
    #define AADDR(off, row0, kb, P) \
        (sb + (off) + (uint32_t)(((row0) + arow + (amat & 1) * 8) * (P) + (kb) + (amat >> 1) * 16))
    #define BADDR(off, n0, kb, P) \
        (sb + (off) + (uint32_t)(((n0) + brow) * (P) + (kb) + bhf * 16))

    const int row0 = w * 32;

    float dA[2][6][4];
    #pragma unroll
    for (int m = 0; m < 2; m++)
        #pragma unroll
        for (int n = 0; n < 6; n++)
            #pragma unroll
            for (int c = 0; c < 4; c++) dA[m][n][c] = 0.f;
    {
        uint32_t Ahf[2][2][4], Alf[2][2][4];
        #pragma unroll
        for (int m = 0; m < 2; m++)
            #pragma unroll
            for (int k = 0; k < 2; k++) {
                LDSM4(Ahf[m][k], AADDR(MO_XH, row0 + 16 * m, 32 * k, XP));
                LDSM4(Alf[m][k], AADDR(MO_XL, row0 + 16 * m, 32 * k, XP));
            }
        #pragma unroll
        for (int n = 0; n < 6; n++) {
            uint32_t bh[2][2], bl2[2][2];
            #pragma unroll
            for (int k = 0; k < 2; k++) {
                LDSM2(bh[k],  BADDR(PW_AH, n * 8, 32 * k, WP));
                LDSM2(bl2[k], BADDR(PW_AL, n * 8, 32 * k, WP));
            }
            #pragma unroll
            for (int m = 0; m < 2; m++)
                #pragma unroll
                for (int k = 0; k < 2; k++) {
                    MMA16816(dA[m][n], Ahf[m][k], bh[k]);
                    MMA16816(dA[m][n], Ahf[m][k], bl2[k]);
                    MMA16816(dA[m][n], Alf[m][k], bh[k]);
                }
        }
    }
    #pragma unroll
    for (int m = 0; m < 2; m++)
        #pragma unroll
        for (int n = 0; n < 6; n++) {
            float2 bias = *(float2*)(s_ba + n * 8 + 2 * tig);
            float v0 = fmaxf(dA[m][n][0] + bias.x, 0.f);
            float v1 = fmaxf(dA[m][n][1] + bias.y, 0.f);
            float v2 = fmaxf(dA[m][n][2] + bias.x, 0.f);
            float v3 = fmaxf(dA[m][n][3] + bias.y, 0.f);
            int r1 = row0 + 16 * m + gid, r2 = r1 + 8;
            int cb = (n * 8 + 2 * tig) * 2;
            uint32_t hv, lv;
            fsplit2(v0, v1, hv, lv);
            *(uint32_t*)(sm_ + MO_XH + r1 * XP + cb) = hv;
            *(uint32_t*)(sm_ + MO_XL + r1 * XP + cb) = lv;
            fsplit2(v2, v3, hv, lv);
            *(uint32_t*)(sm_ + MO_XH + r2 * XP + cb) = hv;
            *(uint32_t*)(sm_ + MO_XL + r2 * XP + cb) = lv;
        }
    __syncwarp();

    float dB[2][12][4];
    #pragma unroll
    for (int m = 0; m < 2; m++)
        #pragma unroll
        for (int n = 0; n < 12; n++)
            #pragma unroll
            for (int c = 0; c < 4; c++) dB[m][n][c] = 0.f;
    {
        uint32_t Ahf[2][3][4], Alf[2][3][4];
        #pragma unroll
        for (int m = 0; m < 2; m++)
            #pragma unroll
            for (int k = 0; k < 3; k++) {
                LDSM4(Ahf[m][k], AADDR(MO_XH, row0 + 16 * m, 32 * k, XP));
                LDSM4(Alf[m][k], AADDR(MO_XL, row0 + 16 * m, 32 * k, XP));
            }
        #pragma unroll
        for (int n = 0; n < 12; n++) {
            uint32_t bh[3][2], bl2[3][2];
            #pragma unroll
            for (int k = 0; k < 3; k++) {
                LDSM2(bh[k],  BADDR(PW_BH, n * 8, 32 * k, WP));
                LDSM2(bl2[k], BADDR(PW_BL, n * 8, 32 * k, WP));
            }
            #pragma unroll
            for (int m = 0; m < 2; m++)
                #pragma unroll
                for (int k = 0; k < 3; k++) {
                    MMA16816(dB[m][n], Ahf[m][k], bh[k]);
                    MMA16816(dB[m][n], Ahf[m][k], bl2[k]);
                    MMA16816(dB[m][n], Alf[m][k], bh[k]);
                }
        }
    }
    #pragma unroll
    for (int m = 0; m < 2; m++)
        #pragma unroll
        for (int n = 0; n < 12; n++) {
            float2 bias = *(float2*)(s_bb + n * 8 + 2 * tig);
            float v0 = fmaxf(dB[m][n][0] + bias.x, 0.f);
            float v1 = fmaxf(dB[m][n][1] + bias.y, 0.f);
            float v2 = fmaxf(dB[m][n][2] + bias.x, 0.f);
            float v3 = fmaxf(dB[m][n][3] + bias.y, 0.f);
            int r1 = row0 + 16 * m + gid, r2 = r1 + 8;
            int cb = (n * 8 + 2 * tig) * 2;
            uint32_t hv, lv;
            fsplit2(v0, v1, hv, lv);
            *(uint32_t*)(sm_ + MO_XH + r1 * XP + cb) = hv;
            *(uint32_t*)(sm_ + MO_XL + r1 * XP + cb) = lv;
            fsplit2(v2, v3, hv, lv);
            *(uint32_t*)(sm_ + MO_XH + r2 * XP + cb) = hv;
            *(uint32_t*)(sm_ + MO_XL + r2 * XP + cb) = lv;
        }
    __syncwarp();

    float dC[2][2][4];
    #pragma unroll
    for (int m = 0; m < 2; m++)
        #pragma unroll
        for (int n = 0; n < 2; n++)
            #pragma unroll
            for (int c = 0; c < 4; c++) dC[m][n][c] = 0.f;
    {
        uint32_t Ahf[2][6][4], Alf[2][6][4];
        #pragma unroll
        for (int m = 0; m < 2; m++)
            #pragma unroll
            for (int k = 0; k < 6; k++) {
                LDSM4(Ahf[m][k], AADDR(MO_XH, row0 + 16 * m, 32 * k, XP));
                LDSM4(Alf[m][k], AADDR(MO_XL, row0 + 16 * m, 32 * k, XP));
            }
        #pragma unroll
        for (int n = 0; n < 2; n++) {
            #pragma unroll
            for (int k = 0; k < 6; k++) {
                uint32_t bh[2], bl2[2];
                LDSM2(bh,  BADDR(PW_CH, n * 8, 32 * k, CP));
                LDSM2(bl2, BADDR(PW_CL, n * 8, 32 * k, CP));
                #pragma unroll
                for (int m = 0; m < 2; m++) {
                    MMA16816(dC[m][n], Ahf[m][k], bh);
                    MMA16816(dC[m][n], Ahf[m][k], bl2);
                    MMA16816(dC[m][n], Alf[m][k], bh);
                }
            }
        }
    }

    #pragma unroll
    for (int m = 0; m < 2; m++)
        #pragma unroll
        for (int n = 0; n < 2; n++) {
            int r1 = row0 + 16 * m + gid, r2 = r1 + 8;
            int cc = n * 8 + 2 * tig;
            s_ex[r1 * 18 + cc]     = dC[m][n][0];
            s_ex[r1 * 18 + cc + 1] = dC[m][n][1];
            s_ex[r2 * 18 + cc]     = dC[m][n][2];
            s_ex[r2 * 18 + cc + 1] = dC[m][n][3];
        }
    __syncwarp();

    float o9[9];
    #pragma unroll
    for (int o = 0; o < 9; o++) o9[o] = s_ex[tid * 18 + o] + s_bc[o];

    float xv = x[v];
    float mx = fmaxf(o9[6], fmaxf(o9[7], o9[8]));
    float e0 = expf(o9[6] - mx), e1 = expf(o9[7] - mx), e2 = expf(o9[8] - mx);
    float inv = 1.f / (e0 + e1 + e2);
    float wsm[3] = {e0 * inv, e1 * inv, e2 * inv};

    float p3 = 0.f;
    #pragma unroll
    for (int k = 0; k < 3; k++) {
        float mu = o9[k];
        float scv = o9[3 + k];
        if (scv == 0.f) scv = 1e-9f;
        scv = fabsf(scv);
        float invs = 1.f / scv;
        float l = fabsf(normcdff((xv + 0.5f - mu) * invs)
                      - normcdff((xv - 0.5f - mu) * invs));
        p3 = fmaf(wsm[k], l, p3);
    }

    out[v] = p3;
    #pragma unroll
    for (int o = 0; o < 9; o++)
        out[(size_t)VOX + (size_t)o * VOX + v] = o9[o];
    #undef AADDR
    #undef BADDR
}

extern "C" void kernel_launch(void* const* d_in, const int* in_sizes, int n_in,
                              void* d_out, int out_size) {
    const float* x     = (const float*)d_in[0];
    const float* hyper = (const float*)d_in[1];
    const float* W3    = (const float*)d_in[2];
    const float* b3    = (const float*)d_in[3];
    const float* W1    = (const float*)d_in[4];
    const float* b1    = (const float*)d_in[5];
    const float* Wa    = (const float*)d_in[6];
    const float* ba    = (const float*)d_in[7];
    const float* Wb    = (const float*)d_in[8];
    const float* bb    = (const float*)d_in[9];
    const float* Wc    = (const float*)d_in[10];
    const float* bc    = (const float*)d_in[11];
    float* out = (float*)d_out;

    cudaFuncSetAttribute(conv3d_mma_kernel,
                         cudaFuncAttributeMaxDynamicSharedMemorySize, C_SMEM);
    cudaFuncSetAttribute(conv2d_mma_kernel,
                         cudaFuncAttributeMaxDynamicSharedMemorySize, G_SMEM);
    cudaFuncSetAttribute(mlp_mma_kernel,
                         cudaFuncAttributeMaxDynamicSharedMemorySize, MO_SMEM);

    pack_kernel<<<256, 256>>>(W3, W1, Wa, ba, Wb, bb, Wc, bc);
    im2col_kernel<<<dim3((KK + 255) / 256, PLANE / 4), 256>>>(hyper);
    conv2d_mma_kernel<<<36 * KSPLIT, 256, G_SMEM>>>();
    conv3d_mma_kernel<<<192 * 8, 384, C_SMEM>>>(x, b1);
    mlp_mma_kernel<<<VOX / 256, 256, MO_SMEM>>>(x, b3, out);
}